// round 6
// baseline (speedup 1.0000x reference)
#include <cuda_runtime.h>
#include <cuda_bf16.h>
#include <math.h>
#include <stdint.h>

// ---------------------------------------------------------------------------
// Problem constants (B=1)
// ---------------------------------------------------------------------------
#define ZD 8
#define HD_ 60
#define WD 120
#define CDIM 192
#define NHEADS 6
#define WS0 2
#define WS1 6
#define WS2 12
#define NTOK 57600
#define NWIN 400
#define NLOC 144
#define NZ 4
#define NH 10
#define NL 10

// ---------------------------------------------------------------------------
// Scratch — plain bf16 GEMM operands (1-term).
// B' stored transposed: rows = N, K-major.
// ---------------------------------------------------------------------------
__device__ __nv_bfloat16 g_A1[NTOK * 192];      // ln1/ln2 out (K=192)
__device__ float         g_qkv[NTOK * 576];     // qkv fp32
__device__ __nv_bfloat16 g_Aattn[NTOK * 192];   // attn out (K=192)
__device__ float         g_y[NTOK * 192];       // post-MSA residual
__device__ __nv_bfloat16 g_A2[NTOK * 768];      // fc1 out (K=768)
__device__ __nv_bfloat16 g_Bqkv[576 * 192];
__device__ __nv_bfloat16 g_Bproj[192 * 192];
__device__ __nv_bfloat16 g_Bfc1[768 * 192];
__device__ __nv_bfloat16 g_Bfc2[192 * 768];

// ---------------------------------------------------------------------------
// Helpers
// ---------------------------------------------------------------------------
__device__ __forceinline__ float warpsum(float v) {
#pragma unroll
    for (int o = 16; o > 0; o >>= 1) v += __shfl_xor_sync(0xffffffffu, v, o);
    return v;
}

__device__ __forceinline__ int win_to_orig(int w, int n) {
    int ih = (w / NL) % NH, iz = w / (NL * NH);
    int il = w % NL;
    int z = n / (WS1 * WS2), hh = (n / WS2) % WS1, l = n % WS2;
    int gz = iz * WS0 + z, gh = ih * WS1 + hh, gl = il * WS2 + l;
    int oz = (gz + 1) & 7;
    int oh = gh + 3; if (oh >= HD_) oh -= HD_;
    int ol = gl + 6; if (ol >= WD) ol -= WD;
    return (oz * HD_ + oh) * WD + ol;
}

__device__ __forceinline__ uint32_t cvta_smem(const void* p) {
    return (uint32_t)__cvta_generic_to_shared(p);
}

__device__ __forceinline__ void cp16(uint32_t saddr, const void* g) {
    asm volatile("cp.async.cg.shared.global [%0], [%1], 16;"
                 :: "r"(saddr), "l"(g));
}

// ---------------------------------------------------------------------------
// Weight prep: W[K,N] fp32 -> B'[N, K] bf16
// ---------------------------------------------------------------------------
__global__ void k_wprep(const float* __restrict__ W, __nv_bfloat16* __restrict__ Bp,
                        int K, int N) {
    int i = blockIdx.x * 256 + threadIdx.x;
    if (i >= K * N) return;
    int k = i / N, n = i - k * N;
    Bp[(size_t)n * K + k] = __float2bfloat16(W[i]);
}

// ---------------------------------------------------------------------------
// K1: LN1 + modulate + roll + window gather -> bf16 A
// ---------------------------------------------------------------------------
__global__ __launch_bounds__(256) void k_ln1(const float* __restrict__ x,
                                             const float* __restrict__ cond,
                                             const float* __restrict__ g,
                                             const float* __restrict__ b) {
    int t = blockIdx.x * 8 + (threadIdx.x >> 5);
    int lane = threadIdx.x & 31;
    int w = t / NLOC, n = t - w * NLOC;
    int src = win_to_orig(w, n);
    const float* xr = x + (size_t)src * CDIM;
    float v[6]; float s = 0.f;
#pragma unroll
    for (int i = 0; i < 6; i++) { v[i] = xr[lane + 32 * i]; s += v[i]; }
    s = warpsum(s);
    float mu = s * (1.f / 192.f);
    float vs = 0.f;
#pragma unroll
    for (int i = 0; i < 6; i++) { float d = v[i] - mu; vs += d * d; }
    vs = warpsum(vs);
    float rstd = rsqrtf(vs * (1.f / 192.f) + 1e-5f);
#pragma unroll
    for (int i = 0; i < 6; i++) {
        int c = lane + 32 * i;
        float val = (v[i] - mu) * rstd * g[c] + b[c];
        val = val * (1.f + cond[192 + c]) + cond[c];
        g_A1[(size_t)t * 192 + c] = __float2bfloat16(val);
    }
}

// ---------------------------------------------------------------------------
// K5: LN2 + modulate -> bf16 A
// ---------------------------------------------------------------------------
__global__ __launch_bounds__(256) void k_ln2(const float* __restrict__ cond,
                                             const float* __restrict__ g,
                                             const float* __restrict__ b) {
    int t = blockIdx.x * 8 + (threadIdx.x >> 5);
    int lane = threadIdx.x & 31;
    const float* xr = g_y + (size_t)t * CDIM;
    float v[6]; float s = 0.f;
#pragma unroll
    for (int i = 0; i < 6; i++) { v[i] = xr[lane + 32 * i]; s += v[i]; }
    s = warpsum(s);
    float mu = s * (1.f / 192.f);
    float vs = 0.f;
#pragma unroll
    for (int i = 0; i < 6; i++) { float d = v[i] - mu; vs += d * d; }
    vs = warpsum(vs);
    float rstd = rsqrtf(vs * (1.f / 192.f) + 1e-5f);
#pragma unroll
    for (int i = 0; i < 6; i++) {
        int c = lane + 32 * i;
        float val = (v[i] - mu) * rstd * g[c] + b[c];
        val = val * (1.f + cond[768 + c]) + cond[576 + c];
        g_A1[(size_t)t * 192 + c] = __float2bfloat16(val);
    }
}

// ---------------------------------------------------------------------------
// Tensor-core GEMM, cp.async 2-stage pipeline.
// Block tile 128x192, 8 warps (2x4), warp tile 64x48, K chunks of 64 bf16.
// Dynamic smem: 2 stages x (A 16KB + B 24KB) = 80KB.
// ---------------------------------------------------------------------------
#define STAGE_BYTES 40960
template <int MODE>
__global__ __launch_bounds__(256, 1) void k_tc_gemm(
    const __nv_bfloat16* __restrict__ A, const __nv_bfloat16* __restrict__ Bw,
    const float* __restrict__ bias, int Keff,
    float* __restrict__ fout, __nv_bfloat16* __restrict__ sout,
    const float* __restrict__ res, const float* __restrict__ cond) {
    extern __shared__ __align__(1024) unsigned char smem_dyn[];

    const int tid = threadIdx.x;
    const int lane = tid & 31;
    const int wid = tid >> 5;
    const int warp_m = (wid & 1) * 64;
    const int warp_n = (wid >> 1) * 48;

    const int rowbase = blockIdx.y * 128;
    const int colbase = blockIdx.x * 192;
    const int nchunks = Keff >> 6;

    const __nv_bfloat16* Arow = A + (size_t)rowbase * Keff;
    const __nv_bfloat16* Brow = Bw + (size_t)colbase * Keff;

    float acc[4][6][4];
#pragma unroll
    for (int mt = 0; mt < 4; mt++)
#pragma unroll
        for (int nt = 0; nt < 6; nt++)
#pragma unroll
            for (int i = 0; i < 4; i++) acc[mt][nt][i] = 0.f;

    int ar[4], as_[4], br[6], bs_[6];
#pragma unroll
    for (int i = 0; i < 4; i++) {
        int idx = tid + i * 256;
        ar[i] = idx >> 3; as_[i] = idx & 7;
    }
#pragma unroll
    for (int i = 0; i < 6; i++) {
        int idx = tid + i * 256;
        br[i] = idx >> 3; bs_[i] = idx & 7;
    }

    const uint32_t smem_u = cvta_smem(smem_dyn);

    auto issue = [&](int ch) {
        uint32_t sa = smem_u + (ch & 1) * STAGE_BYTES;
        uint32_t sb = sa + 16384;
        const __nv_bfloat16* Ach = Arow + ch * 64;
        const __nv_bfloat16* Bch = Brow + ch * 64;
#pragma unroll
        for (int i = 0; i < 4; i++)
            cp16(sa + (uint32_t)(ar[i] * 128 + ((as_[i] ^ (ar[i] & 7)) << 4)),
                 Ach + (size_t)ar[i] * Keff + as_[i] * 8);
#pragma unroll
        for (int i = 0; i < 6; i++)
            cp16(sb + (uint32_t)(br[i] * 128 + ((bs_[i] ^ (br[i] & 7)) << 4)),
                 Bch + (size_t)br[i] * Keff + bs_[i] * 8);
        asm volatile("cp.async.commit_group;");
    };

    issue(0);

    for (int ch = 0; ch < nchunks; ch++) {
        if (ch + 1 < nchunks) {
            issue(ch + 1);
            asm volatile("cp.async.wait_group 1;");
        } else {
            asm volatile("cp.async.wait_group 0;");
        }
        __syncthreads();

        uint32_t sa = smem_u + (ch & 1) * STAGE_BYTES;
        uint32_t sb = sa + 16384;

#pragma unroll
        for (int kk = 0; kk < 4; kk++) {
            uint32_t af[4][4];
#pragma unroll
            for (int mt = 0; mt < 4; mt++) {
                int r = warp_m + mt * 16 + (lane & 15);
                int seg = kk * 2 + (lane >> 4);
                uint32_t addr = sa + r * 128 + (((seg ^ (r & 7)) & 7) << 4);
                asm volatile(
                    "ldmatrix.sync.aligned.m8n8.x4.shared.b16 {%0,%1,%2,%3}, [%4];"
                    : "=r"(af[mt][0]), "=r"(af[mt][1]), "=r"(af[mt][2]), "=r"(af[mt][3])
                    : "r"(addr));
            }
            uint32_t bf[6][2];
#pragma unroll
            for (int nt = 0; nt < 6; nt++) {
                int r = warp_n + nt * 8 + (lane & 7);
                int seg = kk * 2 + ((lane >> 3) & 1);
                uint32_t addr = sb + r * 128 + (((seg ^ (r & 7)) & 7) << 4);
                asm volatile(
                    "ldmatrix.sync.aligned.m8n8.x2.shared.b16 {%0,%1}, [%2];"
                    : "=r"(bf[nt][0]), "=r"(bf[nt][1])
                    : "r"(addr));
            }
#pragma unroll
            for (int mt = 0; mt < 4; mt++)
#pragma unroll
                for (int nt = 0; nt < 6; nt++) {
                    asm volatile(
                        "mma.sync.aligned.m16n8k16.row.col.f32.bf16.bf16.f32 "
                        "{%0,%1,%2,%3}, {%4,%5,%6,%7}, {%8,%9}, {%0,%1,%2,%3};"
                        : "+f"(acc[mt][nt][0]), "+f"(acc[mt][nt][1]),
                          "+f"(acc[mt][nt][2]), "+f"(acc[mt][nt][3])
                        : "r"(af[mt][0]), "r"(af[mt][1]), "r"(af[mt][2]), "r"(af[mt][3]),
                          "r"(bf[nt][0]), "r"(bf[nt][1]));
                }
        }
        __syncthreads();
    }

    // -------------------- epilogue --------------------
#pragma unroll
    for (int mt = 0; mt < 4; mt++) {
#pragma unroll
        for (int half = 0; half < 2; half++) {
            int row = rowbase + warp_m + mt * 16 + (lane >> 2) + half * 8;
            int orow = 0;
            if (MODE == 1) orow = win_to_orig(row / NLOC, row % NLOC);
#pragma unroll
            for (int nt = 0; nt < 6; nt++) {
#pragma unroll
                for (int e = 0; e < 2; e++) {
                    float v = acc[mt][nt][half * 2 + e];
                    int c = colbase + warp_n + nt * 8 + (lane & 3) * 2 + e;
                    if (MODE == 0) {
                        fout[(size_t)row * 576 + c] = v + bias[c];
                    } else if (MODE == 1) {
                        float val = v + bias[c];
                        fout[(size_t)orow * 192 + c] =
                            res[(size_t)orow * 192 + c] + cond[384 + c] * val;
                    } else if (MODE == 2) {
                        float xg = v + bias[c];
                        float gl = 0.5f * xg * (1.f + erff(xg * 0.70710678118654752f));
                        sout[(size_t)row * 768 + c] = __float2bfloat16(gl);
                    } else {
                        float val = v + bias[c];
                        fout[(size_t)row * 192 + c] =
                            res[(size_t)row * 192 + c] + cond[960 + c] * val;
                    }
                }
            }
        }
    }
}

// ---------------------------------------------------------------------------
// K3: fused window attention (fp32; writes bf16 for proj GEMM)
// ---------------------------------------------------------------------------
__global__ __launch_bounds__(160) void k_attn(const float* __restrict__ qkv,
                                              const float* __restrict__ bias_table) {
    int w = blockIdx.x / NHEADS;
    int head = blockIdx.x - w * NHEADS;
    __shared__ float ks[NLOC][32];
    __shared__ float vs[NLOC][32];
    __shared__ float qs[NLOC][33];
    __shared__ int cmi[NLOC];
    __shared__ int lblm[NLOC];

    int tid = threadIdx.x;
    const float* base = qkv + (size_t)w * NLOC * 576;

    for (int idx = tid; idx < NLOC * 8; idx += 160) {
        int row = idx >> 3, f = idx & 7;
        const float* rb = base + (size_t)row * 576 + head * 32 + f * 4;
        float4 qv = *(const float4*)(rb);
        float4 kv = *(const float4*)(rb + 192);
        float4 vv = *(const float4*)(rb + 384);
        qs[row][f * 4 + 0] = qv.x; qs[row][f * 4 + 1] = qv.y;
        qs[row][f * 4 + 2] = qv.z; qs[row][f * 4 + 3] = qv.w;
        *(float4*)&ks[row][f * 4] = kv;
        *(float4*)&vs[row][f * 4] = vv;
    }
    int ih = (w / NL) % NH, iz = w / (NL * NH);
    if (tid < NLOC) {
        int z = tid / 72, hh = (tid / 12) % 6, l = tid % 12;
        cmi[tid] = 1656 * z + 138 * hh - l;
        int gz = iz * WS0 + z, gh = ih * WS1 + hh;
        int zseg = gz < 6 ? 0 : (gz < 7 ? 1 : 2);
        int hseg = gh < 54 ? 0 : (gh < 57 ? 1 : 2);
        lblm[tid] = zseg * 3 + hseg;
    }
    __syncthreads();

    if (tid < NLOC) {
        float q[32];
#pragma unroll
        for (int d = 0; d < 32; d++) q[d] = qs[tid][d] * 0.17677669529663687f;
        int z1 = tid / 72, h1 = (tid / 12) % 6, l1 = tid % 12;
        int cn = 828 * z1 + 23 * h1 + l1 + 11;
        int mylbl = lblm[tid];
        int typ = iz * NH + ih;
        const float* bt = bias_table + typ * NHEADS + head;

        float acc[32];
#pragma unroll
        for (int d = 0; d < 32; d++) acc[d] = 0.f;
        float mrun = -1e30f, lrun = 0.f;

        for (int m = 0; m < NLOC; m++) {
            float s = 0.f;
#pragma unroll
            for (int f = 0; f < 8; f++) {
                float4 kk = *(const float4*)&ks[m][f * 4];
                s = fmaf(q[f * 4 + 0], kk.x, s);
                s = fmaf(q[f * 4 + 1], kk.y, s);
                s = fmaf(q[f * 4 + 2], kk.z, s);
                s = fmaf(q[f * 4 + 3], kk.w, s);
            }
            int pidx = cn + cmi[m];
            s += __ldg(bt + (size_t)pidx * 240);
            if (lblm[m] != mylbl) s -= 100.f;

            if (s > mrun) {
                float corr = __expf(mrun - s);
                lrun = lrun * corr + 1.f;
#pragma unroll
                for (int d = 0; d < 32; d++)
                    acc[d] = fmaf(acc[d], corr, vs[m][d]);
                mrun = s;
            } else {
                float p = __expf(s - mrun);
                lrun += p;
#pragma unroll
                for (int d = 0; d < 32; d++)
                    acc[d] = fmaf(p, vs[m][d], acc[d]);
            }
        }
        float inv = 1.f / lrun;
        size_t row = (size_t)(w * NLOC + tid);
        int c0 = head * 32;
#pragma unroll
        for (int d = 0; d < 32; d++) {
            g_Aattn[row * 192 + c0 + d] = __float2bfloat16(acc[d] * inv);
        }
    }
}

// ---------------------------------------------------------------------------
// Launch
// ---------------------------------------------------------------------------
extern "C" void kernel_launch(void* const* d_in, const int* in_sizes, int n_in,
                              void* d_out, int out_size) {
    const float* x          = (const float*)d_in[0];
    const float* cond       = (const float*)d_in[1];
    const float* g1         = (const float*)d_in[2];
    const float* bt1        = (const float*)d_in[3];
    const float* w_qkv      = (const float*)d_in[4];
    const float* b_qkv      = (const float*)d_in[5];
    const float* bias_table = (const float*)d_in[6];
    const float* w_proj     = (const float*)d_in[7];
    const float* b_proj     = (const float*)d_in[8];
    const float* g2         = (const float*)d_in[9];
    const float* bt2        = (const float*)d_in[10];
    const float* w_fc1      = (const float*)d_in[11];
    const float* b_fc1      = (const float*)d_in[12];
    const float* w_fc2      = (const float*)d_in[13];
    const float* b_fc2      = (const float*)d_in[14];
    float* out = (float*)d_out;

    __nv_bfloat16 *a1, *aat, *a2, *bq, *bp, *bf1, *bf2;
    float *qkvb, *yb;
    cudaGetSymbolAddress((void**)&a1, g_A1);
    cudaGetSymbolAddress((void**)&qkvb, g_qkv);
    cudaGetSymbolAddress((void**)&aat, g_Aattn);
    cudaGetSymbolAddress((void**)&yb, g_y);
    cudaGetSymbolAddress((void**)&a2, g_A2);
    cudaGetSymbolAddress((void**)&bq, g_Bqkv);
    cudaGetSymbolAddress((void**)&bp, g_Bproj);
    cudaGetSymbolAddress((void**)&bf1, g_Bfc1);
    cudaGetSymbolAddress((void**)&bf2, g_Bfc2);

    static bool attr_done = false;
    if (!attr_done) {
        cudaFuncSetAttribute(k_tc_gemm<0>,
                             cudaFuncAttributeMaxDynamicSharedMemorySize, 2 * STAGE_BYTES);
        cudaFuncSetAttribute(k_tc_gemm<1>,
                             cudaFuncAttributeMaxDynamicSharedMemorySize, 2 * STAGE_BYTES);
        cudaFuncSetAttribute(k_tc_gemm<2>,
                             cudaFuncAttributeMaxDynamicSharedMemorySize, 2 * STAGE_BYTES);
        cudaFuncSetAttribute(k_tc_gemm<3>,
                             cudaFuncAttributeMaxDynamicSharedMemorySize, 2 * STAGE_BYTES);
        attr_done = true;
    }

    // Weight transpose to bf16
    k_wprep<<<(192 * 576 + 255) / 256, 256>>>(w_qkv, bq, 192, 576);
    k_wprep<<<(192 * 192 + 255) / 256, 256>>>(w_proj, bp, 192, 192);
    k_wprep<<<(192 * 768 + 255) / 256, 256>>>(w_fc1, bf1, 192, 768);
    k_wprep<<<(768 * 192 + 255) / 256, 256>>>(w_fc2, bf2, 768, 192);

    // 1. LN1 + modulate + window gather
    k_ln1<<<NTOK / 8, 256>>>(x, cond, g1, bt1);

    // 2. QKV GEMM: (57600,192) @ (192,576)
    k_tc_gemm<0><<<dim3(3, NTOK / 128), 256, 2 * STAGE_BYTES>>>(
        a1, bq, b_qkv, 192, qkvb, nullptr, nullptr, nullptr);

    // 3. Window attention
    k_attn<<<NWIN * NHEADS, 160>>>(qkvb, bias_table);

    // 4. Proj GEMM + scatter + gated residual -> y
    k_tc_gemm<1><<<dim3(1, NTOK / 128), 256, 2 * STAGE_BYTES>>>(
        aat, bp, b_proj, 192, yb, nullptr, x, cond);

    // 5. LN2 + modulate
    k_ln2<<<NTOK / 8, 256>>>(cond, g2, bt2);

    // 6. FC1 GEMM + GeLU
    k_tc_gemm<2><<<dim3(4, NTOK / 128), 256, 2 * STAGE_BYTES>>>(
        a1, bf1, b_fc1, 192, nullptr, a2, nullptr, nullptr);

    // 7. FC2 GEMM + gated residual -> out
    k_tc_gemm<3><<<dim3(1, NTOK / 128), 256, 2 * STAGE_BYTES>>>(
        a2, bf2, b_fc2, 768, out, nullptr, yb, cond);
}

// round 7
// speedup vs baseline: 1.7751x; 1.7751x over previous
#include <cuda_runtime.h>
#include <cuda_bf16.h>
#include <math.h>
#include <stdint.h>

// ---------------------------------------------------------------------------
// Problem constants (B=1)
// ---------------------------------------------------------------------------
#define ZD 8
#define HD_ 60
#define WD 120
#define CDIM 192
#define NHEADS 6
#define WS0 2
#define WS1 6
#define WS2 12
#define NTOK 57600
#define NWIN 400
#define NLOC 144
#define NZ 4
#define NH 10
#define NL 10

// ---------------------------------------------------------------------------
// Scratch. 2-term split-K: A' = [hi | lo], B' = [hi | hi] (rows=N, K-major)
// ---------------------------------------------------------------------------
__device__ __nv_bfloat16 g_A1[NTOK * 384];      // ln1/ln2 out, split (K=192)
__device__ __nv_bfloat16 g_Aattn[NTOK * 384];   // attn out, split (K=192)
__device__ float         g_y[NTOK * 192];       // post-MSA residual
__device__ __nv_bfloat16 g_A2[NTOK * 1536];     // fc1 out, split (K=768)
__device__ __nv_bfloat16 g_Bqkv[576 * 384];
__device__ __nv_bfloat16 g_Bproj[192 * 384];
__device__ __nv_bfloat16 g_Bfc1[768 * 384];
__device__ __nv_bfloat16 g_Bfc2[192 * 1536];
// attention operands, per (window,head) contiguous
__device__ __nv_bfloat16 g_q[NTOK * 192];       // [w][h][n][d], q pre-scaled
__device__ __nv_bfloat16 g_k[NTOK * 192];       // [w][h][n][d]
__device__ __nv_bfloat16 g_vT[NTOK * 192];      // [w][h][d][n]
// combined bias+mask in mma-fragment order: [type*6+head][cn][mt][nt8][lane][4]
__device__ float g_comb[240 * 20736];

// ---------------------------------------------------------------------------
// Helpers
// ---------------------------------------------------------------------------
__device__ __forceinline__ float warpsum(float v) {
#pragma unroll
    for (int o = 16; o > 0; o >>= 1) v += __shfl_xor_sync(0xffffffffu, v, o);
    return v;
}

__device__ __forceinline__ int win_to_orig(int w, int n) {
    int ih = (w / NL) % NH, iz = w / (NL * NH);
    int il = w % NL;
    int z = n / (WS1 * WS2), hh = (n / WS2) % WS1, l = n % WS2;
    int gz = iz * WS0 + z, gh = ih * WS1 + hh, gl = il * WS2 + l;
    int oz = (gz + 1) & 7;
    int oh = gh + 3; if (oh >= HD_) oh -= HD_;
    int ol = gl + 6; if (ol >= WD) ol -= WD;
    return (oz * HD_ + oh) * WD + ol;
}

__device__ __forceinline__ uint32_t cvta_smem(const void* p) {
    return (uint32_t)__cvta_generic_to_shared(p);
}

__device__ __forceinline__ void split_store(__nv_bfloat16* base, size_t stride2,
                                            size_t row, int K, int c, float v) {
    __nv_bfloat16 hi = __float2bfloat16(v);
    __nv_bfloat16 lo = __float2bfloat16(v - __bfloat162float(hi));
    size_t rb = row * stride2;
    base[rb + c] = hi;
    base[rb + K + c] = lo;
}

__device__ __forceinline__ void cp16(uint32_t saddr, const void* g) {
    asm volatile("cp.async.cg.shared.global [%0], [%1], 16;"
                 :: "r"(saddr), "l"(g));
}

__device__ __forceinline__ void mma16816(float* c, const uint32_t* a, const uint32_t* b) {
    asm volatile(
        "mma.sync.aligned.m16n8k16.row.col.f32.bf16.bf16.f32 "
        "{%0,%1,%2,%3}, {%4,%5,%6,%7}, {%8,%9}, {%0,%1,%2,%3};"
        : "+f"(c[0]), "+f"(c[1]), "+f"(c[2]), "+f"(c[3])
        : "r"(a[0]), "r"(a[1]), "r"(a[2]), "r"(a[3]), "r"(b[0]), "r"(b[1]));
}

// ---------------------------------------------------------------------------
// Weight prep: W[K,N] fp32 -> B'[N, 2K] bf16 (hi, hi)
// ---------------------------------------------------------------------------
__global__ void k_wprep(const float* __restrict__ W, __nv_bfloat16* __restrict__ Bp,
                        int K, int N) {
    int i = blockIdx.x * 256 + threadIdx.x;
    if (i >= K * N) return;
    int k = i / N, n = i - k * N;
    __nv_bfloat16 hi = __float2bfloat16(W[i]);
    size_t base = (size_t)n * 2 * K;
    Bp[base + k] = hi;
    Bp[base + K + k] = hi;
}

// ---------------------------------------------------------------------------
// Bias+mask precompute into mma fragment order.
// linear idx = cn*2304 + mt*256 + nt8*128 + lane*4 + he
// ---------------------------------------------------------------------------
__global__ void k_bias(const float* __restrict__ bt) {
    int th = blockIdx.x;               // 0..239
    int typ = th / 6, head = th - typ * 6;
    int iz = typ / 10, ih = typ - iz * 10;
    float* dst = g_comb + (size_t)th * 20736;
    for (int idx = threadIdx.x; idx < 20736; idx += 256) {
        int cn_ = idx / 2304, r1 = idx - cn_ * 2304;
        int mt = r1 / 256, r2 = r1 - mt * 256;
        int nt8 = r2 >> 7, r3 = r2 & 127;
        int lane = r3 >> 2, he = r3 & 3;
        int h = he >> 1, e = he & 1;
        int m = mt * 16 + (lane >> 2) + h * 8;
        int n = cn_ * 16 + nt8 * 8 + (lane & 3) * 2 + e;
        int z1 = m / 72, h1 = (m / 12) % 6, l1 = m % 12;
        int z2 = n / 72, h2 = (n / 12) % 6, l2 = n % 12;
        int pidx = 828 * z1 + 23 * h1 + l1 + 11 + 1656 * z2 + 138 * h2 - l2;
        float v = bt[(size_t)pidx * 240 + typ * 6 + head];
        int gz1 = iz * 2 + z1, gh1 = ih * 6 + h1;
        int gz2 = iz * 2 + z2, gh2 = ih * 6 + h2;
        int lq = (gz1 < 6 ? 0 : (gz1 < 7 ? 1 : 2)) * 3 + (gh1 < 54 ? 0 : (gh1 < 57 ? 1 : 2));
        int lk = (gz2 < 6 ? 0 : (gz2 < 7 ? 1 : 2)) * 3 + (gh2 < 54 ? 0 : (gh2 < 57 ? 1 : 2));
        if (lq != lk) v -= 100.f;
        dst[idx] = v;
    }
}

// ---------------------------------------------------------------------------
// K1: LN1 + modulate + roll + window gather -> split A'
// ---------------------------------------------------------------------------
__global__ __launch_bounds__(256) void k_ln1(const float* __restrict__ x,
                                             const float* __restrict__ cond,
                                             const float* __restrict__ g,
                                             const float* __restrict__ b) {
    int t = blockIdx.x * 8 + (threadIdx.x >> 5);
    int lane = threadIdx.x & 31;
    int w = t / NLOC, n = t - w * NLOC;
    int src = win_to_orig(w, n);
    const float* xr = x + (size_t)src * CDIM;
    float v[6]; float s = 0.f;
#pragma unroll
    for (int i = 0; i < 6; i++) { v[i] = xr[lane + 32 * i]; s += v[i]; }
    s = warpsum(s);
    float mu = s * (1.f / 192.f);
    float vs = 0.f;
#pragma unroll
    for (int i = 0; i < 6; i++) { float d = v[i] - mu; vs += d * d; }
    vs = warpsum(vs);
    float rstd = rsqrtf(vs * (1.f / 192.f) + 1e-5f);
#pragma unroll
    for (int i = 0; i < 6; i++) {
        int c = lane + 32 * i;
        float val = (v[i] - mu) * rstd * g[c] + b[c];
        val = val * (1.f + cond[192 + c]) + cond[c];
        split_store(g_A1, 384, (size_t)t, 192, c, val);
    }
}

// ---------------------------------------------------------------------------
// K5: LN2 + modulate -> split A'
// ---------------------------------------------------------------------------
__global__ __launch_bounds__(256) void k_ln2(const float* __restrict__ cond,
                                             const float* __restrict__ g,
                                             const float* __restrict__ b) {
    int t = blockIdx.x * 8 + (threadIdx.x >> 5);
    int lane = threadIdx.x & 31;
    const float* xr = g_y + (size_t)t * CDIM;
    float v[6]; float s = 0.f;
#pragma unroll
    for (int i = 0; i < 6; i++) { v[i] = xr[lane + 32 * i]; s += v[i]; }
    s = warpsum(s);
    float mu = s * (1.f / 192.f);
    float vs = 0.f;
#pragma unroll
    for (int i = 0; i < 6; i++) { float d = v[i] - mu; vs += d * d; }
    vs = warpsum(vs);
    float rstd = rsqrtf(vs * (1.f / 192.f) + 1e-5f);
#pragma unroll
    for (int i = 0; i < 6; i++) {
        int c = lane + 32 * i;
        float val = (v[i] - mu) * rstd * g[c] + b[c];
        val = val * (1.f + cond[768 + c]) + cond[576 + c];
        split_store(g_A1, 384, (size_t)t, 192, c, val);
    }
}

// ---------------------------------------------------------------------------
// Tensor-core GEMM, cp.async 2-stage pipeline (as R4).
// MODE 0: qkv -> q/k/vT bf16 per-(window,head) layouts (q pre-scaled)
// MODE 1: proj: scatter + gated residual -> g_y
// MODE 2: fc1: GeLU -> split bf16 (K=768 layout)
// MODE 3: fc2: gated residual -> out
// ---------------------------------------------------------------------------
#define STAGE_BYTES 40960
template <int MODE>
__global__ __launch_bounds__(256, 1) void k_tc_gemm(
    const __nv_bfloat16* __restrict__ A, const __nv_bfloat16* __restrict__ Bw,
    const float* __restrict__ bias, int Keff,
    float* __restrict__ fout, __nv_bfloat16* __restrict__ sout,
    const float* __restrict__ res, const float* __restrict__ cond) {
    extern __shared__ __align__(1024) unsigned char smem_dyn[];

    const int tid = threadIdx.x;
    const int lane = tid & 31;
    const int wid = tid >> 5;
    const int warp_m = (wid & 1) * 64;
    const int warp_n = (wid >> 1) * 48;

    const int rowbase = blockIdx.y * 128;
    const int colbase = blockIdx.x * 192;
    const int nchunks = Keff >> 6;

    const __nv_bfloat16* Arow = A + (size_t)rowbase * Keff;
    const __nv_bfloat16* Brow = Bw + (size_t)colbase * Keff;

    float acc[4][6][4];
#pragma unroll
    for (int mt = 0; mt < 4; mt++)
#pragma unroll
        for (int nt = 0; nt < 6; nt++)
#pragma unroll
            for (int i = 0; i < 4; i++) acc[mt][nt][i] = 0.f;

    int ar[4], as_[4], br[6], bs_[6];
#pragma unroll
    for (int i = 0; i < 4; i++) {
        int idx = tid + i * 256;
        ar[i] = idx >> 3; as_[i] = idx & 7;
    }
#pragma unroll
    for (int i = 0; i < 6; i++) {
        int idx = tid + i * 256;
        br[i] = idx >> 3; bs_[i] = idx & 7;
    }

    const uint32_t smem_u = cvta_smem(smem_dyn);

    auto issue = [&](int ch) {
        uint32_t sa = smem_u + (ch & 1) * STAGE_BYTES;
        uint32_t sb = sa + 16384;
        const __nv_bfloat16* Ach = Arow + ch * 64;
        const __nv_bfloat16* Bch = Brow + ch * 64;
#pragma unroll
        for (int i = 0; i < 4; i++)
            cp16(sa + (uint32_t)(ar[i] * 128 + ((as_[i] ^ (ar[i] & 7)) << 4)),
                 Ach + (size_t)ar[i] * Keff + as_[i] * 8);
#pragma unroll
        for (int i = 0; i < 6; i++)
            cp16(sb + (uint32_t)(br[i] * 128 + ((bs_[i] ^ (br[i] & 7)) << 4)),
                 Bch + (size_t)br[i] * Keff + bs_[i] * 8);
        asm volatile("cp.async.commit_group;");
    };

    issue(0);

    for (int ch = 0; ch < nchunks; ch++) {
        if (ch + 1 < nchunks) {
            issue(ch + 1);
            asm volatile("cp.async.wait_group 1;");
        } else {
            asm volatile("cp.async.wait_group 0;");
        }
        __syncthreads();

        uint32_t sa = smem_u + (ch & 1) * STAGE_BYTES;
        uint32_t sb = sa + 16384;

#pragma unroll
        for (int kk = 0; kk < 4; kk++) {
            uint32_t af[4][4];
#pragma unroll
            for (int mt = 0; mt < 4; mt++) {
                int r = warp_m + mt * 16 + (lane & 15);
                int seg = kk * 2 + (lane >> 4);
                uint32_t addr = sa + r * 128 + (((seg ^ (r & 7)) & 7) << 4);
                asm volatile(
                    "ldmatrix.sync.aligned.m8n8.x4.shared.b16 {%0,%1,%2,%3}, [%4];"
                    : "=r"(af[mt][0]), "=r"(af[mt][1]), "=r"(af[mt][2]), "=r"(af[mt][3])
                    : "r"(addr));
            }
            uint32_t bf[6][2];
#pragma unroll
            for (int nt = 0; nt < 6; nt++) {
                int r = warp_n + nt * 8 + (lane & 7);
                int seg = kk * 2 + ((lane >> 3) & 1);
                uint32_t addr = sb + r * 128 + (((seg ^ (r & 7)) & 7) << 4);
                asm volatile(
                    "ldmatrix.sync.aligned.m8n8.x2.shared.b16 {%0,%1}, [%2];"
                    : "=r"(bf[nt][0]), "=r"(bf[nt][1])
                    : "r"(addr));
            }
#pragma unroll
            for (int mt = 0; mt < 4; mt++)
#pragma unroll
                for (int nt = 0; nt < 6; nt++)
                    mma16816(acc[mt][nt], af[mt], bf[nt]);
        }
        __syncthreads();
    }

    // -------------------- epilogue --------------------
    const int kind = blockIdx.x;  // used by MODE 0
#pragma unroll
    for (int mt = 0; mt < 4; mt++) {
#pragma unroll
        for (int half = 0; half < 2; half++) {
            int row = rowbase + warp_m + mt * 16 + (lane >> 2) + half * 8;
            int orow = 0, wwin = 0, nn = 0;
            if (MODE == 1) orow = win_to_orig(row / NLOC, row % NLOC);
            if (MODE == 0) { wwin = row / NLOC; nn = row - wwin * NLOC; }
#pragma unroll
            for (int nt = 0; nt < 6; nt++) {
#pragma unroll
                for (int e = 0; e < 2; e++) {
                    float v = acc[mt][nt][half * 2 + e];
                    int c = colbase + warp_n + nt * 8 + (lane & 3) * 2 + e;
                    if (MODE == 0) {
                        int cc = c - colbase;
                        int hd = cc >> 5, d = cc & 31;
                        float val = v + bias[c];
                        size_t w6h = (size_t)(wwin * 6 + hd);
                        if (kind == 0)
                            g_q[(w6h * 144 + nn) * 32 + d] =
                                __float2bfloat16(val * 0.17677669529663687f);
                        else if (kind == 1)
                            g_k[(w6h * 144 + nn) * 32 + d] = __float2bfloat16(val);
                        else
                            g_vT[(w6h * 32 + d) * 144 + nn] = __float2bfloat16(val);
                    } else if (MODE == 1) {
                        float val = v + bias[c];
                        fout[(size_t)orow * 192 + c] =
                            res[(size_t)orow * 192 + c] + cond[384 + c] * val;
                    } else if (MODE == 2) {
                        float xg = v + bias[c];
                        float gl = 0.5f * xg * (1.f + erff(xg * 0.70710678118654752f));
                        split_store(sout, 1536, (size_t)row, 768, c, gl);
                    } else {
                        float val = v + bias[c];
                        fout[(size_t)row * 192 + c] =
                            res[(size_t)row * 192 + c] + cond[960 + c] * val;
                    }
                }
            }
        }
    }
}

// ---------------------------------------------------------------------------
// K3: tensor-core flash attention. Block = (window, head), 3 warps x 48 rows.
// Q/K smem rows 80B (bank-disjoint), vT rows 304B (bank-disjoint).
// ---------------------------------------------------------------------------
__global__ __launch_bounds__(96) void k_attn() {
    __shared__ __align__(16) __nv_bfloat16 sq[144 * 40];
    __shared__ __align__(16) __nv_bfloat16 sk[144 * 40];
    __shared__ __align__(16) __nv_bfloat16 sv[32 * 152];

    int w = blockIdx.x / 6, head = blockIdx.x - w * 6;
    int tid = threadIdx.x, lane = tid & 31, wp = tid >> 5;
    size_t w6h = (size_t)(w * 6 + head);
    const __nv_bfloat16* qgb = g_q + w6h * 4608;
    const __nv_bfloat16* kgb = g_k + w6h * 4608;
    const __nv_bfloat16* vgb = g_vT + w6h * 4608;
    uint32_t squ = cvta_smem(sq), sku = cvta_smem(sk), svu = cvta_smem(sv);

    for (int i = tid; i < 576; i += 96) {
        int r = i >> 2, s = i & 3;
        cp16(squ + r * 80 + s * 16, qgb + r * 32 + s * 8);
        cp16(sku + r * 80 + s * 16, kgb + r * 32 + s * 8);
    }
    for (int i = tid; i < 576; i += 96) {
        int r = i / 18, s = i - r * 18;
        cp16(svu + r * 304 + s * 16, vgb + r * 144 + s * 8);
    }
    asm volatile("cp.async.commit_group;");
    asm volatile("cp.async.wait_group 0;");
    __syncthreads();

    int iz = w / 100, ih = (w / 10) % 10;
    const float* comb = g_comb + (size_t)(((iz * 10 + ih) * 6 + head)) * 20736;

    // preload Q fragments (fixed for whole kernel)
    uint32_t qf[3][2][4];
#pragma unroll
    for (int mtl = 0; mtl < 3; mtl++)
#pragma unroll
        for (int ks = 0; ks < 2; ks++) {
            int r = wp * 48 + mtl * 16 + (lane & 15);
            int seg = ks * 2 + (lane >> 4);
            uint32_t addr = squ + r * 80 + seg * 16;
            asm volatile(
                "ldmatrix.sync.aligned.m8n8.x4.shared.b16 {%0,%1,%2,%3}, [%4];"
                : "=r"(qf[mtl][ks][0]), "=r"(qf[mtl][ks][1]),
                  "=r"(qf[mtl][ks][2]), "=r"(qf[mtl][ks][3])
                : "r"(addr));
        }

    float O[3][4][4];
#pragma unroll
    for (int a = 0; a < 3; a++)
#pragma unroll
        for (int b = 0; b < 4; b++)
#pragma unroll
            for (int c = 0; c < 4; c++) O[a][b][c] = 0.f;
    float mrun[3][2], lrun[3][2];
#pragma unroll
    for (int a = 0; a < 3; a++) { mrun[a][0] = mrun[a][1] = -1e30f; lrun[a][0] = lrun[a][1] = 0.f; }

#pragma unroll 1
    for (int cn_ = 0; cn_ < 9; cn_++) {
        uint32_t kf[2][2][2];
#pragma unroll
        for (int nt8 = 0; nt8 < 2; nt8++)
#pragma unroll
            for (int ks = 0; ks < 2; ks++) {
                int r = cn_ * 16 + nt8 * 8 + (lane & 7);
                int seg = ks * 2 + ((lane >> 3) & 1);
                uint32_t addr = sku + r * 80 + seg * 16;
                asm volatile(
                    "ldmatrix.sync.aligned.m8n8.x2.shared.b16 {%0,%1}, [%2];"
                    : "=r"(kf[nt8][ks][0]), "=r"(kf[nt8][ks][1]) : "r"(addr));
            }
        uint32_t vf[4][2];
#pragma unroll
        for (int dt = 0; dt < 4; dt++) {
            int r = dt * 8 + (lane & 7);
            int seg = cn_ * 2 + ((lane >> 3) & 1);
            uint32_t addr = svu + r * 304 + seg * 16;
            asm volatile(
                "ldmatrix.sync.aligned.m8n8.x2.shared.b16 {%0,%1}, [%2];"
                : "=r"(vf[dt][0]), "=r"(vf[dt][1]) : "r"(addr));
        }

#pragma unroll
        for (int mtl = 0; mtl < 3; mtl++) {
            float s_[2][4];
#pragma unroll
            for (int nt8 = 0; nt8 < 2; nt8++) {
#pragma unroll
                for (int i = 0; i < 4; i++) s_[nt8][i] = 0.f;
#pragma unroll
                for (int ks = 0; ks < 2; ks++)
                    mma16816(s_[nt8], qf[mtl][ks], kf[nt8][ks]);
                const float4 b4 = *(const float4*)(comb +
                    (size_t)(((cn_ * 9 + wp * 3 + mtl) * 2 + nt8) * 128 + lane * 4));
                s_[nt8][0] += b4.x; s_[nt8][1] += b4.y;
                s_[nt8][2] += b4.z; s_[nt8][3] += b4.w;
            }
            // row max over chunk (rows h=0: idx 0,1; h=1: idx 2,3)
            float rm0 = fmaxf(fmaxf(s_[0][0], s_[0][1]), fmaxf(s_[1][0], s_[1][1]));
            float rm1 = fmaxf(fmaxf(s_[0][2], s_[0][3]), fmaxf(s_[1][2], s_[1][3]));
            rm0 = fmaxf(rm0, __shfl_xor_sync(0xffffffffu, rm0, 1));
            rm0 = fmaxf(rm0, __shfl_xor_sync(0xffffffffu, rm0, 2));
            rm1 = fmaxf(rm1, __shfl_xor_sync(0xffffffffu, rm1, 1));
            rm1 = fmaxf(rm1, __shfl_xor_sync(0xffffffffu, rm1, 2));
            float nm0 = fmaxf(mrun[mtl][0], rm0);
            float nm1 = fmaxf(mrun[mtl][1], rm1);
            float cr0 = __expf(mrun[mtl][0] - nm0);
            float cr1 = __expf(mrun[mtl][1] - nm1);
            mrun[mtl][0] = nm0; mrun[mtl][1] = nm1;
            float p[2][4];
#pragma unroll
            for (int nt8 = 0; nt8 < 2; nt8++) {
                p[nt8][0] = __expf(s_[nt8][0] - nm0);
                p[nt8][1] = __expf(s_[nt8][1] - nm0);
                p[nt8][2] = __expf(s_[nt8][2] - nm1);
                p[nt8][3] = __expf(s_[nt8][3] - nm1);
            }
            float ps0 = p[0][0] + p[0][1] + p[1][0] + p[1][1];
            float ps1 = p[0][2] + p[0][3] + p[1][2] + p[1][3];
            ps0 += __shfl_xor_sync(0xffffffffu, ps0, 1);
            ps0 += __shfl_xor_sync(0xffffffffu, ps0, 2);
            ps1 += __shfl_xor_sync(0xffffffffu, ps1, 1);
            ps1 += __shfl_xor_sync(0xffffffffu, ps1, 2);
            lrun[mtl][0] = lrun[mtl][0] * cr0 + ps0;
            lrun[mtl][1] = lrun[mtl][1] * cr1 + ps1;
#pragma unroll
            for (int dt = 0; dt < 4; dt++) {
                O[mtl][dt][0] *= cr0; O[mtl][dt][1] *= cr0;
                O[mtl][dt][2] *= cr1; O[mtl][dt][3] *= cr1;
            }
            // pack P as A fragment
            uint32_t pa[4];
            __nv_bfloat162 t0 = __floats2bfloat162_rn(p[0][0], p[0][1]);
            __nv_bfloat162 t1 = __floats2bfloat162_rn(p[0][2], p[0][3]);
            __nv_bfloat162 t2 = __floats2bfloat162_rn(p[1][0], p[1][1]);
            __nv_bfloat162 t3 = __floats2bfloat162_rn(p[1][2], p[1][3]);
            pa[0] = *(uint32_t*)&t0; pa[1] = *(uint32_t*)&t1;
            pa[2] = *(uint32_t*)&t2; pa[3] = *(uint32_t*)&t3;
#pragma unroll
            for (int dt = 0; dt < 4; dt++)
                mma16816(O[mtl][dt], pa, vf[dt]);
        }
    }

    // epilogue: normalize + 2-term split store
#pragma unroll
    for (int mtl = 0; mtl < 3; mtl++) {
        float inv0 = 1.f / lrun[mtl][0];
        float inv1 = 1.f / lrun[mtl][1];
        int t0 = w * 144 + wp * 48 + mtl * 16 + (lane >> 2);
        int c0 = head * 32 + (lane & 3) * 2;
#pragma unroll
        for (int dt = 0; dt < 4; dt++) {
            int c = c0 + dt * 8;
            float v0 = O[mtl][dt][0] * inv0, v1 = O[mtl][dt][1] * inv0;
            float v2 = O[mtl][dt][2] * inv1, v3 = O[mtl][dt][3] * inv1;
            __nv_bfloat16 h0 = __float2bfloat16(v0), h1 = __float2bfloat16(v1);
            __nv_bfloat16 h2 = __float2bfloat16(v2), h3 = __float2bfloat16(v3);
            *(__nv_bfloat162*)&g_Aattn[(size_t)t0 * 384 + c] =
                __nv_bfloat162(h0, h1);
            *(__nv_bfloat162*)&g_Aattn[(size_t)t0 * 384 + 192 + c] =
                __nv_bfloat162(__float2bfloat16(v0 - __bfloat162float(h0)),
                               __float2bfloat16(v1 - __bfloat162float(h1)));
            *(__nv_bfloat162*)&g_Aattn[(size_t)(t0 + 8) * 384 + c] =
                __nv_bfloat162(h2, h3);
            *(__nv_bfloat162*)&g_Aattn[(size_t)(t0 + 8) * 384 + 192 + c] =
                __nv_bfloat162(__float2bfloat16(v2 - __bfloat162float(h2)),
                               __float2bfloat16(v3 - __bfloat162float(h3)));
        }
    }
}

// ---------------------------------------------------------------------------
// Launch
// ---------------------------------------------------------------------------
extern "C" void kernel_launch(void* const* d_in, const int* in_sizes, int n_in,
                              void* d_out, int out_size) {
    const float* x          = (const float*)d_in[0];
    const float* cond       = (const float*)d_in[1];
    const float* g1         = (const float*)d_in[2];
    const float* bt1        = (const float*)d_in[3];
    const float* w_qkv      = (const float*)d_in[4];
    const float* b_qkv      = (const float*)d_in[5];
    const float* bias_table = (const float*)d_in[6];
    const float* w_proj     = (const float*)d_in[7];
    const float* b_proj     = (const float*)d_in[8];
    const float* g2         = (const float*)d_in[9];
    const float* bt2        = (const float*)d_in[10];
    const float* w_fc1      = (const float*)d_in[11];
    const float* b_fc1      = (const float*)d_in[12];
    const float* w_fc2      = (const float*)d_in[13];
    const float* b_fc2      = (const float*)d_in[14];
    float* out = (float*)d_out;

    __nv_bfloat16 *a1, *aat, *a2, *bq, *bp, *bf1, *bf2;
    float *yb;
    cudaGetSymbolAddress((void**)&a1, g_A1);
    cudaGetSymbolAddress((void**)&aat, g_Aattn);
    cudaGetSymbolAddress((void**)&yb, g_y);
    cudaGetSymbolAddress((void**)&a2, g_A2);
    cudaGetSymbolAddress((void**)&bq, g_Bqkv);
    cudaGetSymbolAddress((void**)&bp, g_Bproj);
    cudaGetSymbolAddress((void**)&bf1, g_Bfc1);
    cudaGetSymbolAddress((void**)&bf2, g_Bfc2);

    static bool attr_done = false;
    if (!attr_done) {
        cudaFuncSetAttribute(k_tc_gemm<0>,
                             cudaFuncAttributeMaxDynamicSharedMemorySize, 2 * STAGE_BYTES);
        cudaFuncSetAttribute(k_tc_gemm<1>,
                             cudaFuncAttributeMaxDynamicSharedMemorySize, 2 * STAGE_BYTES);
        cudaFuncSetAttribute(k_tc_gemm<2>,
                             cudaFuncAttributeMaxDynamicSharedMemorySize, 2 * STAGE_BYTES);
        cudaFuncSetAttribute(k_tc_gemm<3>,
                             cudaFuncAttributeMaxDynamicSharedMemorySize, 2 * STAGE_BYTES);
        attr_done = true;
    }

    // Weight split/transpose + bias precompute
    k_wprep<<<(192 * 576 + 255) / 256, 256>>>(w_qkv, bq, 192, 576);
    k_wprep<<<(192 * 192 + 255) / 256, 256>>>(w_proj, bp, 192, 192);
    k_wprep<<<(192 * 768 + 255) / 256, 256>>>(w_fc1, bf1, 192, 768);
    k_wprep<<<(768 * 192 + 255) / 256, 256>>>(w_fc2, bf2, 768, 192);
    k_bias<<<240, 256>>>(bias_table);

    // 1. LN1 + modulate + window gather
    k_ln1<<<NTOK / 8, 256>>>(x, cond, g1, bt1);

    // 2. QKV GEMM -> q/k/vT bf16
    k_tc_gemm<0><<<dim3(3, NTOK / 128), 256, 2 * STAGE_BYTES>>>(
        a1, bq, b_qkv, 384, nullptr, nullptr, nullptr, nullptr);

    // 3. Flash attention (tensor cores)
    k_attn<<<NWIN * NHEADS, 96>>>();

    // 4. Proj GEMM + scatter + gated residual -> y
    k_tc_gemm<1><<<dim3(1, NTOK / 128), 256, 2 * STAGE_BYTES>>>(
        aat, bp, b_proj, 384, yb, nullptr, x, cond);

    // 5. LN2 + modulate
    k_ln2<<<NTOK / 8, 256>>>(cond, g2, bt2);

    // 6. FC1 GEMM + GeLU
    k_tc_gemm<2><<<dim3(4, NTOK / 128), 256, 2 * STAGE_BYTES>>>(
        a1, bf1, b_fc1, 384, nullptr, a2, nullptr, nullptr);

    // 7. FC2 GEMM + gated residual -> out
    k_tc_gemm<3><<<dim3(1, NTOK / 128), 256, 2 * STAGE_BYTES>>>(
        a2, bf2, b_fc2, 1536, out, nullptr, yb, cond);
}

// round 8
// speedup vs baseline: 2.5781x; 1.4524x over previous
#include <cuda_runtime.h>
#include <cuda_bf16.h>
#include <math.h>
#include <stdint.h>

// ---------------------------------------------------------------------------
// Problem constants (B=1)
// ---------------------------------------------------------------------------
#define ZD 8
#define HD_ 60
#define WD 120
#define CDIM 192
#define NHEADS 6
#define WS0 2
#define WS1 6
#define WS2 12
#define NTOK 57600
#define NWIN 400
#define NLOC 144
#define NZ 4
#define NH 10
#define NL 10

// ---------------------------------------------------------------------------
// Scratch — plain 1-term bf16 GEMM operands. B' rows = N, K-major.
// ---------------------------------------------------------------------------
__device__ __nv_bfloat16 g_A1[NTOK * 192];      // ln1/ln2 out (K=192)
__device__ __nv_bfloat16 g_Aattn[NTOK * 192];   // attn out (K=192)
__device__ float         g_y[NTOK * 192];       // post-MSA residual
__device__ __nv_bfloat16 g_A2[NTOK * 768];      // fc1 out (K=768)
__device__ __nv_bfloat16 g_Bqkv[576 * 192];
__device__ __nv_bfloat16 g_Bproj[192 * 192];
__device__ __nv_bfloat16 g_Bfc1[768 * 192];
__device__ __nv_bfloat16 g_Bfc2[192 * 768];
// attention operands, per (window,head) contiguous
__device__ __nv_bfloat16 g_q[NTOK * 192];       // [w][h][n][d], q pre-scaled
__device__ __nv_bfloat16 g_k[NTOK * 192];       // [w][h][n][d]
__device__ __nv_bfloat16 g_vT[NTOK * 192];      // [w][h][d][n]
// combined bias+mask in mma-fragment order: [type*6+head][cn][mt][nt8][lane][4]
__device__ float g_comb[240 * 20736];

// ---------------------------------------------------------------------------
// Helpers
// ---------------------------------------------------------------------------
__device__ __forceinline__ float warpsum(float v) {
#pragma unroll
    for (int o = 16; o > 0; o >>= 1) v += __shfl_xor_sync(0xffffffffu, v, o);
    return v;
}

__device__ __forceinline__ int win_to_orig(int w, int n) {
    int ih = (w / NL) % NH, iz = w / (NL * NH);
    int il = w % NL;
    int z = n / (WS1 * WS2), hh = (n / WS2) % WS1, l = n % WS2;
    int gz = iz * WS0 + z, gh = ih * WS1 + hh, gl = il * WS2 + l;
    int oz = (gz + 1) & 7;
    int oh = gh + 3; if (oh >= HD_) oh -= HD_;
    int ol = gl + 6; if (ol >= WD) ol -= WD;
    return (oz * HD_ + oh) * WD + ol;
}

__device__ __forceinline__ uint32_t cvta_smem(const void* p) {
    return (uint32_t)__cvta_generic_to_shared(p);
}

__device__ __forceinline__ void cp16(uint32_t saddr, const void* g) {
    asm volatile("cp.async.cg.shared.global [%0], [%1], 16;"
                 :: "r"(saddr), "l"(g));
}

__device__ __forceinline__ void mma16816(float* c, const uint32_t* a, const uint32_t* b) {
    asm volatile(
        "mma.sync.aligned.m16n8k16.row.col.f32.bf16.bf16.f32 "
        "{%0,%1,%2,%3}, {%4,%5,%6,%7}, {%8,%9}, {%0,%1,%2,%3};"
        : "+f"(c[0]), "+f"(c[1]), "+f"(c[2]), "+f"(c[3])
        : "r"(a[0]), "r"(a[1]), "r"(a[2]), "r"(a[3]), "r"(b[0]), "r"(b[1]));
}

// ---------------------------------------------------------------------------
// Fused prep: 4 weight transposes + bias/mask precompute, one launch.
// Blocks [0,432): qkv  [432,576): proj  [576,1152): fc1  [1152,1728): fc2
// Blocks [1728,1968): bias+mask
// ---------------------------------------------------------------------------
__device__ __forceinline__ void wprep_body(const float* __restrict__ W,
                                           __nv_bfloat16* __restrict__ Bp,
                                           int K, int N, int blk) {
    int i = blk * 256 + threadIdx.x;
    if (i >= K * N) return;
    int k = i / N, n = i - k * N;
    Bp[(size_t)n * K + k] = __float2bfloat16(W[i]);
}

__global__ void k_prep(const float* __restrict__ wq, const float* __restrict__ wp,
                       const float* __restrict__ w1, const float* __restrict__ w2,
                       const float* __restrict__ bt) {
    int b = blockIdx.x;
    if (b < 432)       { wprep_body(wq, g_Bqkv, 192, 576, b); return; }
    if (b < 576)       { wprep_body(wp, g_Bproj, 192, 192, b - 432); return; }
    if (b < 1152)      { wprep_body(w1, g_Bfc1, 192, 768, b - 576); return; }
    if (b < 1728)      { wprep_body(w2, g_Bfc2, 768, 192, b - 1152); return; }
    int th = b - 1728;                 // 0..239
    int typ = th / 6, head = th - typ * 6;
    int iz = typ / 10, ih = typ - iz * 10;
    float* dst = g_comb + (size_t)th * 20736;
    for (int idx = threadIdx.x; idx < 20736; idx += 256) {
        int cn_ = idx / 2304, r1 = idx - cn_ * 2304;
        int mt = r1 / 256, r2 = r1 - mt * 256;
        int nt8 = r2 >> 7, r3 = r2 & 127;
        int lane = r3 >> 2, he = r3 & 3;
        int h = he >> 1, e = he & 1;
        int m = mt * 16 + (lane >> 2) + h * 8;
        int n = cn_ * 16 + nt8 * 8 + (lane & 3) * 2 + e;
        int z1 = m / 72, h1 = (m / 12) % 6, l1 = m % 12;
        int z2 = n / 72, h2 = (n / 12) % 6, l2 = n % 12;
        int pidx = 828 * z1 + 23 * h1 + l1 + 11 + 1656 * z2 + 138 * h2 - l2;
        float v = bt[(size_t)pidx * 240 + typ * 6 + head];
        int gz1 = iz * 2 + z1, gh1 = ih * 6 + h1;
        int gz2 = iz * 2 + z2, gh2 = ih * 6 + h2;
        int lq = (gz1 < 6 ? 0 : (gz1 < 7 ? 1 : 2)) * 3 + (gh1 < 54 ? 0 : (gh1 < 57 ? 1 : 2));
        int lk = (gz2 < 6 ? 0 : (gz2 < 7 ? 1 : 2)) * 3 + (gh2 < 54 ? 0 : (gh2 < 57 ? 1 : 2));
        if (lq != lk) v -= 100.f;
        dst[idx] = v;
    }
}

// ---------------------------------------------------------------------------
// K1: LN1 + modulate + roll + window gather -> bf16 A
// ---------------------------------------------------------------------------
__global__ __launch_bounds__(256) void k_ln1(const float* __restrict__ x,
                                             const float* __restrict__ cond,
                                             const float* __restrict__ g,
                                             const float* __restrict__ b) {
    int t = blockIdx.x * 8 + (threadIdx.x >> 5);
    int lane = threadIdx.x & 31;
    int w = t / NLOC, n = t - w * NLOC;
    int src = win_to_orig(w, n);
    const float* xr = x + (size_t)src * CDIM;
    float v[6]; float s = 0.f;
#pragma unroll
    for (int i = 0; i < 6; i++) { v[i] = xr[lane + 32 * i]; s += v[i]; }
    s = warpsum(s);
    float mu = s * (1.f / 192.f);
    float vs = 0.f;
#pragma unroll
    for (int i = 0; i < 6; i++) { float d = v[i] - mu; vs += d * d; }
    vs = warpsum(vs);
    float rstd = rsqrtf(vs * (1.f / 192.f) + 1e-5f);
#pragma unroll
    for (int i = 0; i < 6; i++) {
        int c = lane + 32 * i;
        float val = (v[i] - mu) * rstd * g[c] + b[c];
        val = val * (1.f + cond[192 + c]) + cond[c];
        g_A1[(size_t)t * 192 + c] = __float2bfloat16(val);
    }
}

// ---------------------------------------------------------------------------
// K5: LN2 + modulate -> bf16 A
// ---------------------------------------------------------------------------
__global__ __launch_bounds__(256) void k_ln2(const float* __restrict__ cond,
                                             const float* __restrict__ g,
                                             const float* __restrict__ b) {
    int t = blockIdx.x * 8 + (threadIdx.x >> 5);
    int lane = threadIdx.x & 31;
    const float* xr = g_y + (size_t)t * CDIM;
    float v[6]; float s = 0.f;
#pragma unroll
    for (int i = 0; i < 6; i++) { v[i] = xr[lane + 32 * i]; s += v[i]; }
    s = warpsum(s);
    float mu = s * (1.f / 192.f);
    float vs = 0.f;
#pragma unroll
    for (int i = 0; i < 6; i++) { float d = v[i] - mu; vs += d * d; }
    vs = warpsum(vs);
    float rstd = rsqrtf(vs * (1.f / 192.f) + 1e-5f);
#pragma unroll
    for (int i = 0; i < 6; i++) {
        int c = lane + 32 * i;
        float val = (v[i] - mu) * rstd * g[c] + b[c];
        val = val * (1.f + cond[768 + c]) + cond[576 + c];
        g_A1[(size_t)t * 192 + c] = __float2bfloat16(val);
    }
}

// ---------------------------------------------------------------------------
// Tensor-core GEMM, cp.async 2-stage pipeline.
// Block tile 128x192, 8 warps (2x4), warp tile 64x48, K chunks of 64 bf16.
// MODE 0: qkv -> q/k/vT bf16 per-(window,head) layouts (q pre-scaled)
// MODE 1: proj: scatter + gated residual -> g_y
// MODE 2: fc1: GeLU -> bf16 (K=768 layout)
// MODE 3: fc2: gated residual -> out
// ---------------------------------------------------------------------------
#define STAGE_BYTES 40960
template <int MODE>
__global__ __launch_bounds__(256, 1) void k_tc_gemm(
    const __nv_bfloat16* __restrict__ A, const __nv_bfloat16* __restrict__ Bw,
    const float* __restrict__ bias, int Keff,
    float* __restrict__ fout, __nv_bfloat16* __restrict__ sout,
    const float* __restrict__ res, const float* __restrict__ cond) {
    extern __shared__ __align__(1024) unsigned char smem_dyn[];

    const int tid = threadIdx.x;
    const int lane = tid & 31;
    const int wid = tid >> 5;
    const int warp_m = (wid & 1) * 64;
    const int warp_n = (wid >> 1) * 48;

    const int rowbase = blockIdx.y * 128;
    const int colbase = blockIdx.x * 192;
    const int nchunks = Keff >> 6;

    const __nv_bfloat16* Arow = A + (size_t)rowbase * Keff;
    const __nv_bfloat16* Brow = Bw + (size_t)colbase * Keff;

    float acc[4][6][4];
#pragma unroll
    for (int mt = 0; mt < 4; mt++)
#pragma unroll
        for (int nt = 0; nt < 6; nt++)
#pragma unroll
            for (int i = 0; i < 4; i++) acc[mt][nt][i] = 0.f;

    int ar[4], as_[4], br[6], bs_[6];
#pragma unroll
    for (int i = 0; i < 4; i++) {
        int idx = tid + i * 256;
        ar[i] = idx >> 3; as_[i] = idx & 7;
    }
#pragma unroll
    for (int i = 0; i < 6; i++) {
        int idx = tid + i * 256;
        br[i] = idx >> 3; bs_[i] = idx & 7;
    }

    const uint32_t smem_u = cvta_smem(smem_dyn);

    auto issue = [&](int ch) {
        uint32_t sa = smem_u + (ch & 1) * STAGE_BYTES;
        uint32_t sb = sa + 16384;
        const __nv_bfloat16* Ach = Arow + ch * 64;
        const __nv_bfloat16* Bch = Brow + ch * 64;
#pragma unroll
        for (int i = 0; i < 4; i++)
            cp16(sa + (uint32_t)(ar[i] * 128 + ((as_[i] ^ (ar[i] & 7)) << 4)),
                 Ach + (size_t)ar[i] * Keff + as_[i] * 8);
#pragma unroll
        for (int i = 0; i < 6; i++)
            cp16(sb + (uint32_t)(br[i] * 128 + ((bs_[i] ^ (br[i] & 7)) << 4)),
                 Bch + (size_t)br[i] * Keff + bs_[i] * 8);
        asm volatile("cp.async.commit_group;");
    };

    issue(0);

    for (int ch = 0; ch < nchunks; ch++) {
        if (ch + 1 < nchunks) {
            issue(ch + 1);
            asm volatile("cp.async.wait_group 1;");
        } else {
            asm volatile("cp.async.wait_group 0;");
        }
        __syncthreads();

        uint32_t sa = smem_u + (ch & 1) * STAGE_BYTES;
        uint32_t sb = sa + 16384;

#pragma unroll
        for (int kk = 0; kk < 4; kk++) {
            uint32_t af[4][4];
#pragma unroll
            for (int mt = 0; mt < 4; mt++) {
                int r = warp_m + mt * 16 + (lane & 15);
                int seg = kk * 2 + (lane >> 4);
                uint32_t addr = sa + r * 128 + (((seg ^ (r & 7)) & 7) << 4);
                asm volatile(
                    "ldmatrix.sync.aligned.m8n8.x4.shared.b16 {%0,%1,%2,%3}, [%4];"
                    : "=r"(af[mt][0]), "=r"(af[mt][1]), "=r"(af[mt][2]), "=r"(af[mt][3])
                    : "r"(addr));
            }
            uint32_t bf[6][2];
#pragma unroll
            for (int nt = 0; nt < 6; nt++) {
                int r = warp_n + nt * 8 + (lane & 7);
                int seg = kk * 2 + ((lane >> 3) & 1);
                uint32_t addr = sb + r * 128 + (((seg ^ (r & 7)) & 7) << 4);
                asm volatile(
                    "ldmatrix.sync.aligned.m8n8.x2.shared.b16 {%0,%1}, [%2];"
                    : "=r"(bf[nt][0]), "=r"(bf[nt][1])
                    : "r"(addr));
            }
#pragma unroll
            for (int mt = 0; mt < 4; mt++)
#pragma unroll
                for (int nt = 0; nt < 6; nt++)
                    mma16816(acc[mt][nt], af[mt], bf[nt]);
        }
        __syncthreads();
    }

    // -------------------- epilogue --------------------
    const int kind = blockIdx.x;  // used by MODE 0
#pragma unroll
    for (int mt = 0; mt < 4; mt++) {
#pragma unroll
        for (int half = 0; half < 2; half++) {
            int row = rowbase + warp_m + mt * 16 + (lane >> 2) + half * 8;
            int orow = 0, wwin = 0, nn = 0;
            if (MODE == 1) orow = win_to_orig(row / NLOC, row % NLOC);
            if (MODE == 0) { wwin = row / NLOC; nn = row - wwin * NLOC; }
#pragma unroll
            for (int nt = 0; nt < 6; nt++) {
#pragma unroll
                for (int e = 0; e < 2; e++) {
                    float v = acc[mt][nt][half * 2 + e];
                    int c = colbase + warp_n + nt * 8 + (lane & 3) * 2 + e;
                    if (MODE == 0) {
                        int cc = c - colbase;
                        int hd = cc >> 5, d = cc & 31;
                        float val = v + bias[c];
                        size_t w6h = (size_t)(wwin * 6 + hd);
                        if (kind == 0)
                            g_q[(w6h * 144 + nn) * 32 + d] =
                                __float2bfloat16(val * 0.17677669529663687f);
                        else if (kind == 1)
                            g_k[(w6h * 144 + nn) * 32 + d] = __float2bfloat16(val);
                        else
                            g_vT[(w6h * 32 + d) * 144 + nn] = __float2bfloat16(val);
                    } else if (MODE == 1) {
                        float val = v + bias[c];
                        fout[(size_t)orow * 192 + c] =
                            res[(size_t)orow * 192 + c] + cond[384 + c] * val;
                    } else if (MODE == 2) {
                        float xg = v + bias[c];
                        float gl = 0.5f * xg * (1.f + erff(xg * 0.70710678118654752f));
                        sout[(size_t)row * 768 + c] = __float2bfloat16(gl);
                    } else {
                        float val = v + bias[c];
                        fout[(size_t)row * 192 + c] =
                            res[(size_t)row * 192 + c] + cond[960 + c] * val;
                    }
                }
            }
        }
    }
}

// ---------------------------------------------------------------------------
// K3: tensor-core flash attention. Block = (window, head), 3 warps x 48 rows.
// ---------------------------------------------------------------------------
__global__ __launch_bounds__(96) void k_attn() {
    __shared__ __align__(16) __nv_bfloat16 sq[144 * 40];
    __shared__ __align__(16) __nv_bfloat16 sk[144 * 40];
    __shared__ __align__(16) __nv_bfloat16 sv[32 * 152];

    int w = blockIdx.x / 6, head = blockIdx.x - w * 6;
    int tid = threadIdx.x, lane = tid & 31, wp = tid >> 5;
    size_t w6h = (size_t)(w * 6 + head);
    const __nv_bfloat16* qgb = g_q + w6h * 4608;
    const __nv_bfloat16* kgb = g_k + w6h * 4608;
    const __nv_bfloat16* vgb = g_vT + w6h * 4608;
    uint32_t squ = cvta_smem(sq), sku = cvta_smem(sk), svu = cvta_smem(sv);

    for (int i = tid; i < 576; i += 96) {
        int r = i >> 2, s = i & 3;
        cp16(squ + r * 80 + s * 16, qgb + r * 32 + s * 8);
        cp16(sku + r * 80 + s * 16, kgb + r * 32 + s * 8);
    }
    for (int i = tid; i < 576; i += 96) {
        int r = i / 18, s = i - r * 18;
        cp16(svu + r * 304 + s * 16, vgb + r * 144 + s * 8);
    }
    asm volatile("cp.async.commit_group;");
    asm volatile("cp.async.wait_group 0;");
    __syncthreads();

    int iz = w / 100, ih = (w / 10) % 10;
    const float* comb = g_comb + (size_t)(((iz * 10 + ih) * 6 + head)) * 20736;

    uint32_t qf[3][2][4];
#pragma unroll
    for (int mtl = 0; mtl < 3; mtl++)
#pragma unroll
        for (int ks = 0; ks < 2; ks++) {
            int r = wp * 48 + mtl * 16 + (lane & 15);
            int seg = ks * 2 + (lane >> 4);
            uint32_t addr = squ + r * 80 + seg * 16;
            asm volatile(
                "ldmatrix.sync.aligned.m8n8.x4.shared.b16 {%0,%1,%2,%3}, [%4];"
                : "=r"(qf[mtl][ks][0]), "=r"(qf[mtl][ks][1]),
                  "=r"(qf[mtl][ks][2]), "=r"(qf[mtl][ks][3])
                : "r"(addr));
        }

    float O[3][4][4];
#pragma unroll
    for (int a = 0; a < 3; a++)
#pragma unroll
        for (int b = 0; b < 4; b++)
#pragma unroll
            for (int c = 0; c < 4; c++) O[a][b][c] = 0.f;
    float mrun[3][2], lrun[3][2];
#pragma unroll
    for (int a = 0; a < 3; a++) { mrun[a][0] = mrun[a][1] = -1e30f; lrun[a][0] = lrun[a][1] = 0.f; }

#pragma unroll 1
    for (int cn_ = 0; cn_ < 9; cn_++) {
        uint32_t kf[2][2][2];
#pragma unroll
        for (int nt8 = 0; nt8 < 2; nt8++)
#pragma unroll
            for (int ks = 0; ks < 2; ks++) {
                int r = cn_ * 16 + nt8 * 8 + (lane & 7);
                int seg = ks * 2 + ((lane >> 3) & 1);
                uint32_t addr = sku + r * 80 + seg * 16;
                asm volatile(
                    "ldmatrix.sync.aligned.m8n8.x2.shared.b16 {%0,%1}, [%2];"
                    : "=r"(kf[nt8][ks][0]), "=r"(kf[nt8][ks][1]) : "r"(addr));
            }
        uint32_t vf[4][2];
#pragma unroll
        for (int dt = 0; dt < 4; dt++) {
            int r = dt * 8 + (lane & 7);
            int seg = cn_ * 2 + ((lane >> 3) & 1);
            uint32_t addr = svu + r * 304 + seg * 16;
            asm volatile(
                "ldmatrix.sync.aligned.m8n8.x2.shared.b16 {%0,%1}, [%2];"
                : "=r"(vf[dt][0]), "=r"(vf[dt][1]) : "r"(addr));
        }

#pragma unroll
        for (int mtl = 0; mtl < 3; mtl++) {
            float s_[2][4];
#pragma unroll
            for (int nt8 = 0; nt8 < 2; nt8++) {
#pragma unroll
                for (int i = 0; i < 4; i++) s_[nt8][i] = 0.f;
#pragma unroll
                for (int ks = 0; ks < 2; ks++)
                    mma16816(s_[nt8], qf[mtl][ks], kf[nt8][ks]);
                const float4 b4 = *(const float4*)(comb +
                    (size_t)(((cn_ * 9 + wp * 3 + mtl) * 2 + nt8) * 128 + lane * 4));
                s_[nt8][0] += b4.x; s_[nt8][1] += b4.y;
                s_[nt8][2] += b4.z; s_[nt8][3] += b4.w;
            }
            float rm0 = fmaxf(fmaxf(s_[0][0], s_[0][1]), fmaxf(s_[1][0], s_[1][1]));
            float rm1 = fmaxf(fmaxf(s_[0][2], s_[0][3]), fmaxf(s_[1][2], s_[1][3]));
            rm0 = fmaxf(rm0, __shfl_xor_sync(0xffffffffu, rm0, 1));
            rm0 = fmaxf(rm0, __shfl_xor_sync(0xffffffffu, rm0, 2));
            rm1 = fmaxf(rm1, __shfl_xor_sync(0xffffffffu, rm1, 1));
            rm1 = fmaxf(rm1, __shfl_xor_sync(0xffffffffu, rm1, 2));
            float nm0 = fmaxf(mrun[mtl][0], rm0);
            float nm1 = fmaxf(mrun[mtl][1], rm1);
            float cr0 = __expf(mrun[mtl][0] - nm0);
            float cr1 = __expf(mrun[mtl][1] - nm1);
            mrun[mtl][0] = nm0; mrun[mtl][1] = nm1;
            float p[2][4];
#pragma unroll
            for (int nt8 = 0; nt8 < 2; nt8++) {
                p[nt8][0] = __expf(s_[nt8][0] - nm0);
                p[nt8][1] = __expf(s_[nt8][1] - nm0);
                p[nt8][2] = __expf(s_[nt8][2] - nm1);
                p[nt8][3] = __expf(s_[nt8][3] - nm1);
            }
            float ps0 = p[0][0] + p[0][1] + p[1][0] + p[1][1];
            float ps1 = p[0][2] + p[0][3] + p[1][2] + p[1][3];
            ps0 += __shfl_xor_sync(0xffffffffu, ps0, 1);
            ps0 += __shfl_xor_sync(0xffffffffu, ps0, 2);
            ps1 += __shfl_xor_sync(0xffffffffu, ps1, 1);
            ps1 += __shfl_xor_sync(0xffffffffu, ps1, 2);
            lrun[mtl][0] = lrun[mtl][0] * cr0 + ps0;
            lrun[mtl][1] = lrun[mtl][1] * cr1 + ps1;
#pragma unroll
            for (int dt = 0; dt < 4; dt++) {
                O[mtl][dt][0] *= cr0; O[mtl][dt][1] *= cr0;
                O[mtl][dt][2] *= cr1; O[mtl][dt][3] *= cr1;
            }
            uint32_t pa[4];
            __nv_bfloat162 t0 = __floats2bfloat162_rn(p[0][0], p[0][1]);
            __nv_bfloat162 t1 = __floats2bfloat162_rn(p[0][2], p[0][3]);
            __nv_bfloat162 t2 = __floats2bfloat162_rn(p[1][0], p[1][1]);
            __nv_bfloat162 t3 = __floats2bfloat162_rn(p[1][2], p[1][3]);
            pa[0] = *(uint32_t*)&t0; pa[1] = *(uint32_t*)&t1;
            pa[2] = *(uint32_t*)&t2; pa[3] = *(uint32_t*)&t3;
#pragma unroll
            for (int dt = 0; dt < 4; dt++)
                mma16816(O[mtl][dt], pa, vf[dt]);
        }
    }

#pragma unroll
    for (int mtl = 0; mtl < 3; mtl++) {
        float inv0 = 1.f / lrun[mtl][0];
        float inv1 = 1.f / lrun[mtl][1];
        int t0 = w * 144 + wp * 48 + mtl * 16 + (lane >> 2);
        int c0 = head * 32 + (lane & 3) * 2;
#pragma unroll
        for (int dt = 0; dt < 4; dt++) {
            int c = c0 + dt * 8;
            float v0 = O[mtl][dt][0] * inv0, v1 = O[mtl][dt][1] * inv0;
            float v2 = O[mtl][dt][2] * inv1, v3 = O[mtl][dt][3] * inv1;
            *(__nv_bfloat162*)&g_Aattn[(size_t)t0 * 192 + c] =
                __floats2bfloat162_rn(v0, v1);
            *(__nv_bfloat162*)&g_Aattn[(size_t)(t0 + 8) * 192 + c] =
                __floats2bfloat162_rn(v2, v3);
        }
    }
}

// ---------------------------------------------------------------------------
// Launch
// ---------------------------------------------------------------------------
extern "C" void kernel_launch(void* const* d_in, const int* in_sizes, int n_in,
                              void* d_out, int out_size) {
    const float* x          = (const float*)d_in[0];
    const float* cond       = (const float*)d_in[1];
    const float* g1         = (const float*)d_in[2];
    const float* bt1        = (const float*)d_in[3];
    const float* w_qkv      = (const float*)d_in[4];
    const float* b_qkv      = (const float*)d_in[5];
    const float* bias_table = (const float*)d_in[6];
    const float* w_proj     = (const float*)d_in[7];
    const float* b_proj     = (const float*)d_in[8];
    const float* g2         = (const float*)d_in[9];
    const float* bt2        = (const float*)d_in[10];
    const float* w_fc1      = (const float*)d_in[11];
    const float* b_fc1      = (const float*)d_in[12];
    const float* w_fc2      = (const float*)d_in[13];
    const float* b_fc2      = (const float*)d_in[14];
    float* out = (float*)d_out;

    __nv_bfloat16 *a1, *aat, *a2, *bq, *bp, *bf1, *bf2;
    float *yb;
    cudaGetSymbolAddress((void**)&a1, g_A1);
    cudaGetSymbolAddress((void**)&aat, g_Aattn);
    cudaGetSymbolAddress((void**)&yb, g_y);
    cudaGetSymbolAddress((void**)&a2, g_A2);
    cudaGetSymbolAddress((void**)&bq, g_Bqkv);
    cudaGetSymbolAddress((void**)&bp, g_Bproj);
    cudaGetSymbolAddress((void**)&bf1, g_Bfc1);
    cudaGetSymbolAddress((void**)&bf2, g_Bfc2);

    static bool attr_done = false;
    if (!attr_done) {
        cudaFuncSetAttribute(k_tc_gemm<0>,
                             cudaFuncAttributeMaxDynamicSharedMemorySize, 2 * STAGE_BYTES);
        cudaFuncSetAttribute(k_tc_gemm<1>,
                             cudaFuncAttributeMaxDynamicSharedMemorySize, 2 * STAGE_BYTES);
        cudaFuncSetAttribute(k_tc_gemm<2>,
                             cudaFuncAttributeMaxDynamicSharedMemorySize, 2 * STAGE_BYTES);
        cudaFuncSetAttribute(k_tc_gemm<3>,
                             cudaFuncAttributeMaxDynamicSharedMemorySize, 2 * STAGE_BYTES);
        attr_done = true;
    }

    // 0. Fused prep: weight transposes + bias/mask precompute
    k_prep<<<1968, 256>>>(w_qkv, w_proj, w_fc1, w_fc2, bias_table);

    // 1. LN1 + modulate + window gather
    k_ln1<<<NTOK / 8, 256>>>(x, cond, g1, bt1);

    // 2. QKV GEMM -> q/k/vT bf16
    k_tc_gemm<0><<<dim3(3, NTOK / 128), 256, 2 * STAGE_BYTES>>>(
        a1, bq, b_qkv, 192, nullptr, nullptr, nullptr, nullptr);

    // 3. Flash attention (tensor cores)
    k_attn<<<NWIN * NHEADS, 96>>>();

    // 4. Proj GEMM + scatter + gated residual -> y
    k_tc_gemm<1><<<dim3(1, NTOK / 128), 256, 2 * STAGE_BYTES>>>(
        aat, bp, b_proj, 192, yb, nullptr, x, cond);

    // 5. LN2 + modulate
    k_ln2<<<NTOK / 8, 256>>>(cond, g2, bt2);

    // 6. FC1 GEMM + GeLU
    k_tc_gemm<2><<<dim3(4, NTOK / 128), 256, 2 * STAGE_BYTES>>>(
        a1, bf1, b_fc1, 192, nullptr, a2, nullptr, nullptr);

    // 7. FC2 GEMM + gated residual -> out
    k_tc_gemm<3><<<dim3(1, NTOK / 128), 256, 2 * STAGE_BYTES>>>(
        a2, bf2, b_fc2, 768, out, nullptr, yb, cond);
}

// round 9
// speedup vs baseline: 2.7345x; 1.0607x over previous
#include <cuda_runtime.h>
#include <cuda_bf16.h>
#include <math.h>
#include <stdint.h>

// ---------------------------------------------------------------------------
// Problem constants (B=1)
// ---------------------------------------------------------------------------
#define ZD 8
#define HD_ 60
#define WD 120
#define CDIM 192
#define NHEADS 6
#define WS0 2
#define WS1 6
#define WS2 12
#define NTOK 57600
#define NWIN 400
#define NLOC 144
#define NZ 4
#define NH 10
#define NL 10

// ---------------------------------------------------------------------------
// Scratch — plain 1-term bf16 GEMM operands. B' rows = N, K-major.
// ---------------------------------------------------------------------------
__device__ __nv_bfloat16 g_A1[NTOK * 192];      // ln1/ln2 out (K=192)
__device__ __nv_bfloat16 g_Aattn[NTOK * 192];   // attn out (K=192)
__device__ float         g_y[NTOK * 192];       // post-MSA residual
__device__ __nv_bfloat16 g_A2[NTOK * 768];      // fc1 out (K=768)
__device__ __nv_bfloat16 g_Bqkv[576 * 192];
__device__ __nv_bfloat16 g_Bproj[192 * 192];
__device__ __nv_bfloat16 g_Bfc1[768 * 192];
__device__ __nv_bfloat16 g_Bfc2[192 * 768];
// attention operands, per (window,head) contiguous — all [w][h][n][d]
__device__ __nv_bfloat16 g_q[NTOK * 192];       // q pre-scaled
__device__ __nv_bfloat16 g_k[NTOK * 192];
__device__ __nv_bfloat16 g_v[NTOK * 192];
// combined bias+mask in mma-fragment order: [type*6+head][cn][mt][nt8][lane][4]
__device__ float g_comb[240 * 20736];

// ---------------------------------------------------------------------------
// Helpers
// ---------------------------------------------------------------------------
__device__ __forceinline__ float warpsum(float v) {
#pragma unroll
    for (int o = 16; o > 0; o >>= 1) v += __shfl_xor_sync(0xffffffffu, v, o);
    return v;
}

__device__ __forceinline__ int win_to_orig(int w, int n) {
    int ih = (w / NL) % NH, iz = w / (NL * NH);
    int il = w % NL;
    int z = n / (WS1 * WS2), hh = (n / WS2) % WS1, l = n % WS2;
    int gz = iz * WS0 + z, gh = ih * WS1 + hh, gl = il * WS2 + l;
    int oz = (gz + 1) & 7;
    int oh = gh + 3; if (oh >= HD_) oh -= HD_;
    int ol = gl + 6; if (ol >= WD) ol -= WD;
    return (oz * HD_ + oh) * WD + ol;
}

__device__ __forceinline__ uint32_t cvta_smem(const void* p) {
    return (uint32_t)__cvta_generic_to_shared(p);
}

__device__ __forceinline__ void cp16(uint32_t saddr, const void* g) {
    asm volatile("cp.async.cg.shared.global [%0], [%1], 16;"
                 :: "r"(saddr), "l"(g));
}

__device__ __forceinline__ void mma16816(float* c, const uint32_t* a, const uint32_t* b) {
    asm volatile(
        "mma.sync.aligned.m16n8k16.row.col.f32.bf16.bf16.f32 "
        "{%0,%1,%2,%3}, {%4,%5,%6,%7}, {%8,%9}, {%0,%1,%2,%3};"
        : "+f"(c[0]), "+f"(c[1]), "+f"(c[2]), "+f"(c[3])
        : "r"(a[0]), "r"(a[1]), "r"(a[2]), "r"(a[3]), "r"(b[0]), "r"(b[1]));
}

// ---------------------------------------------------------------------------
// Fused prep: 4 weight transposes + bias/mask precompute, one launch.
// ---------------------------------------------------------------------------
__device__ __forceinline__ void wprep_body(const float* __restrict__ W,
                                           __nv_bfloat16* __restrict__ Bp,
                                           int K, int N, int blk) {
    int i = blk * 256 + threadIdx.x;
    if (i >= K * N) return;
    int k = i / N, n = i - k * N;
    Bp[(size_t)n * K + k] = __float2bfloat16(W[i]);
}

__global__ void k_prep(const float* __restrict__ wq, const float* __restrict__ wp,
                       const float* __restrict__ w1, const float* __restrict__ w2,
                       const float* __restrict__ bt) {
    int b = blockIdx.x;
    if (b < 432)       { wprep_body(wq, g_Bqkv, 192, 576, b); return; }
    if (b < 576)       { wprep_body(wp, g_Bproj, 192, 192, b - 432); return; }
    if (b < 1152)      { wprep_body(w1, g_Bfc1, 192, 768, b - 576); return; }
    if (b < 1728)      { wprep_body(w2, g_Bfc2, 768, 192, b - 1152); return; }
    int th = b - 1728;                 // 0..239
    int typ = th / 6, head = th - typ * 6;
    int iz = typ / 10, ih = typ - iz * 10;
    float* dst = g_comb + (size_t)th * 20736;
    for (int idx = threadIdx.x; idx < 20736; idx += 256) {
        int cn_ = idx / 2304, r1 = idx - cn_ * 2304;
        int mt = r1 / 256, r2 = r1 - mt * 256;
        int nt8 = r2 >> 7, r3 = r2 & 127;
        int lane = r3 >> 2, he = r3 & 3;
        int h = he >> 1, e = he & 1;
        int m = mt * 16 + (lane >> 2) + h * 8;
        int n = cn_ * 16 + nt8 * 8 + (lane & 3) * 2 + e;
        int z1 = m / 72, h1 = (m / 12) % 6, l1 = m % 12;
        int z2 = n / 72, h2 = (n / 12) % 6, l2 = n % 12;
        int pidx = 828 * z1 + 23 * h1 + l1 + 11 + 1656 * z2 + 138 * h2 - l2;
        float v = bt[(size_t)pidx * 240 + typ * 6 + head];
        int gz1 = iz * 2 + z1, gh1 = ih * 6 + h1;
        int gz2 = iz * 2 + z2, gh2 = ih * 6 + h2;
        int lq = (gz1 < 6 ? 0 : (gz1 < 7 ? 1 : 2)) * 3 + (gh1 < 54 ? 0 : (gh1 < 57 ? 1 : 2));
        int lk = (gz2 < 6 ? 0 : (gz2 < 7 ? 1 : 2)) * 3 + (gh2 < 54 ? 0 : (gh2 < 57 ? 1 : 2));
        if (lq != lk) v -= 100.f;
        dst[idx] = v;
    }
}

// ---------------------------------------------------------------------------
// K1: LN1 + modulate + roll + window gather -> bf16 A
// ---------------------------------------------------------------------------
__global__ __launch_bounds__(256) void k_ln1(const float* __restrict__ x,
                                             const float* __restrict__ cond,
                                             const float* __restrict__ g,
                                             const float* __restrict__ b) {
    int t = blockIdx.x * 8 + (threadIdx.x >> 5);
    int lane = threadIdx.x & 31;
    int w = t / NLOC, n = t - w * NLOC;
    int src = win_to_orig(w, n);
    const float* xr = x + (size_t)src * CDIM;
    float v[6]; float s = 0.f;
#pragma unroll
    for (int i = 0; i < 6; i++) { v[i] = xr[lane + 32 * i]; s += v[i]; }
    s = warpsum(s);
    float mu = s * (1.f / 192.f);
    float vs = 0.f;
#pragma unroll
    for (int i = 0; i < 6; i++) { float d = v[i] - mu; vs += d * d; }
    vs = warpsum(vs);
    float rstd = rsqrtf(vs * (1.f / 192.f) + 1e-5f);
#pragma unroll
    for (int i = 0; i < 6; i++) {
        int c = lane + 32 * i;
        float val = (v[i] - mu) * rstd * g[c] + b[c];
        val = val * (1.f + cond[192 + c]) + cond[c];
        g_A1[(size_t)t * 192 + c] = __float2bfloat16(val);
    }
}

// ---------------------------------------------------------------------------
// K5: LN2 + modulate -> bf16 A
// ---------------------------------------------------------------------------
__global__ __launch_bounds__(256) void k_ln2(const float* __restrict__ cond,
                                             const float* __restrict__ g,
                                             const float* __restrict__ b) {
    int t = blockIdx.x * 8 + (threadIdx.x >> 5);
    int lane = threadIdx.x & 31;
    const float* xr = g_y + (size_t)t * CDIM;
    float v[6]; float s = 0.f;
#pragma unroll
    for (int i = 0; i < 6; i++) { v[i] = xr[lane + 32 * i]; s += v[i]; }
    s = warpsum(s);
    float mu = s * (1.f / 192.f);
    float vs = 0.f;
#pragma unroll
    for (int i = 0; i < 6; i++) { float d = v[i] - mu; vs += d * d; }
    vs = warpsum(vs);
    float rstd = rsqrtf(vs * (1.f / 192.f) + 1e-5f);
#pragma unroll
    for (int i = 0; i < 6; i++) {
        int c = lane + 32 * i;
        float val = (v[i] - mu) * rstd * g[c] + b[c];
        val = val * (1.f + cond[768 + c]) + cond[576 + c];
        g_A1[(size_t)t * 192 + c] = __float2bfloat16(val);
    }
}

// ---------------------------------------------------------------------------
// Tensor-core GEMM, cp.async 2-stage pipeline.
// MODE 0: qkv -> q/k/v bf16 per-(window,head) [n][d] layouts (q pre-scaled)
// MODE 1: proj: scatter + gated residual -> g_y
// MODE 2: fc1: GeLU -> bf16 (K=768 layout)
// MODE 3: fc2: gated residual -> out
// ---------------------------------------------------------------------------
#define STAGE_BYTES 40960
template <int MODE>
__global__ __launch_bounds__(256, 1) void k_tc_gemm(
    const __nv_bfloat16* __restrict__ A, const __nv_bfloat16* __restrict__ Bw,
    const float* __restrict__ bias, int Keff,
    float* __restrict__ fout, __nv_bfloat16* __restrict__ sout,
    const float* __restrict__ res, const float* __restrict__ cond) {
    extern __shared__ __align__(1024) unsigned char smem_dyn[];

    const int tid = threadIdx.x;
    const int lane = tid & 31;
    const int wid = tid >> 5;
    const int warp_m = (wid & 1) * 64;
    const int warp_n = (wid >> 1) * 48;

    const int rowbase = blockIdx.y * 128;
    const int colbase = blockIdx.x * 192;
    const int nchunks = Keff >> 6;

    const __nv_bfloat16* Arow = A + (size_t)rowbase * Keff;
    const __nv_bfloat16* Brow = Bw + (size_t)colbase * Keff;

    float acc[4][6][4];
#pragma unroll
    for (int mt = 0; mt < 4; mt++)
#pragma unroll
        for (int nt = 0; nt < 6; nt++)
#pragma unroll
            for (int i = 0; i < 4; i++) acc[mt][nt][i] = 0.f;

    int ar[4], as_[4], br[6], bs_[6];
#pragma unroll
    for (int i = 0; i < 4; i++) {
        int idx = tid + i * 256;
        ar[i] = idx >> 3; as_[i] = idx & 7;
    }
#pragma unroll
    for (int i = 0; i < 6; i++) {
        int idx = tid + i * 256;
        br[i] = idx >> 3; bs_[i] = idx & 7;
    }

    const uint32_t smem_u = cvta_smem(smem_dyn);

    auto issue = [&](int ch) {
        uint32_t sa = smem_u + (ch & 1) * STAGE_BYTES;
        uint32_t sb = sa + 16384;
        const __nv_bfloat16* Ach = Arow + ch * 64;
        const __nv_bfloat16* Bch = Brow + ch * 64;
#pragma unroll
        for (int i = 0; i < 4; i++)
            cp16(sa + (uint32_t)(ar[i] * 128 + ((as_[i] ^ (ar[i] & 7)) << 4)),
                 Ach + (size_t)ar[i] * Keff + as_[i] * 8);
#pragma unroll
        for (int i = 0; i < 6; i++)
            cp16(sb + (uint32_t)(br[i] * 128 + ((bs_[i] ^ (br[i] & 7)) << 4)),
                 Bch + (size_t)br[i] * Keff + bs_[i] * 8);
        asm volatile("cp.async.commit_group;");
    };

    issue(0);

    for (int ch = 0; ch < nchunks; ch++) {
        if (ch + 1 < nchunks) {
            issue(ch + 1);
            asm volatile("cp.async.wait_group 1;");
        } else {
            asm volatile("cp.async.wait_group 0;");
        }
        __syncthreads();

        uint32_t sa = smem_u + (ch & 1) * STAGE_BYTES;
        uint32_t sb = sa + 16384;

#pragma unroll
        for (int kk = 0; kk < 4; kk++) {
            uint32_t af[4][4];
#pragma unroll
            for (int mt = 0; mt < 4; mt++) {
                int r = warp_m + mt * 16 + (lane & 15);
                int seg = kk * 2 + (lane >> 4);
                uint32_t addr = sa + r * 128 + (((seg ^ (r & 7)) & 7) << 4);
                asm volatile(
                    "ldmatrix.sync.aligned.m8n8.x4.shared.b16 {%0,%1,%2,%3}, [%4];"
                    : "=r"(af[mt][0]), "=r"(af[mt][1]), "=r"(af[mt][2]), "=r"(af[mt][3])
                    : "r"(addr));
            }
            uint32_t bf[6][2];
#pragma unroll
            for (int nt = 0; nt < 6; nt++) {
                int r = warp_n + nt * 8 + (lane & 7);
                int seg = kk * 2 + ((lane >> 3) & 1);
                uint32_t addr = sb + r * 128 + (((seg ^ (r & 7)) & 7) << 4);
                asm volatile(
                    "ldmatrix.sync.aligned.m8n8.x2.shared.b16 {%0,%1}, [%2];"
                    : "=r"(bf[nt][0]), "=r"(bf[nt][1])
                    : "r"(addr));
            }
#pragma unroll
            for (int mt = 0; mt < 4; mt++)
#pragma unroll
                for (int nt = 0; nt < 6; nt++)
                    mma16816(acc[mt][nt], af[mt], bf[nt]);
        }
        __syncthreads();
    }

    // -------------------- epilogue --------------------
    const int kind = blockIdx.x;  // used by MODE 0
#pragma unroll
    for (int mt = 0; mt < 4; mt++) {
#pragma unroll
        for (int half = 0; half < 2; half++) {
            int row = rowbase + warp_m + mt * 16 + (lane >> 2) + half * 8;
            int orow = 0, wwin = 0, nn = 0;
            if (MODE == 1) orow = win_to_orig(row / NLOC, row % NLOC);
            if (MODE == 0) { wwin = row / NLOC; nn = row - wwin * NLOC; }
#pragma unroll
            for (int nt = 0; nt < 6; nt++) {
                int cc = warp_n + nt * 8 + (lane & 3) * 2;
                float v0 = acc[mt][nt][half * 2 + 0];
                float v1 = acc[mt][nt][half * 2 + 1];
                if (MODE == 0) {
                    int hd = cc >> 5, d = cc & 31;
                    float a0 = v0 + bias[colbase + cc];
                    float a1 = v1 + bias[colbase + cc + 1];
                    size_t w6h = (size_t)(wwin * 6 + hd);
                    __nv_bfloat16* dst;
                    if (kind == 0) {
                        a0 *= 0.17677669529663687f;
                        a1 *= 0.17677669529663687f;
                        dst = g_q;
                    } else if (kind == 1) dst = g_k;
                    else dst = g_v;
                    *(__nv_bfloat162*)&dst[(w6h * 144 + nn) * 32 + d] =
                        __floats2bfloat162_rn(a0, a1);
                } else if (MODE == 1) {
#pragma unroll
                    for (int e = 0; e < 2; e++) {
                        int c = cc + e;
                        float val = (e ? v1 : v0) + bias[c];
                        fout[(size_t)orow * 192 + c] =
                            res[(size_t)orow * 192 + c] + cond[384 + c] * val;
                    }
                } else if (MODE == 2) {
#pragma unroll
                    for (int e = 0; e < 2; e++) {
                        int c = colbase + cc + e;
                        float xg = (e ? v1 : v0) + bias[c];
                        float gl = 0.5f * xg * (1.f + erff(xg * 0.70710678118654752f));
                        sout[(size_t)row * 768 + c] = __float2bfloat16(gl);
                    }
                } else {
#pragma unroll
                    for (int e = 0; e < 2; e++) {
                        int c = cc + e;
                        float val = (e ? v1 : v0) + bias[c];
                        fout[(size_t)row * 192 + c] =
                            res[(size_t)row * 192 + c] + cond[960 + c] * val;
                    }
                }
            }
        }
    }
}

// ---------------------------------------------------------------------------
// K3: tensor-core flash attention. Block = (window, head), 3 warps x 48 rows.
// Q/K/V all [n][d] in smem with 80B row stride; V B-fragments via ldmatrix.trans.
// ---------------------------------------------------------------------------
__global__ __launch_bounds__(96) void k_attn() {
    __shared__ __align__(16) __nv_bfloat16 sq[144 * 40];
    __shared__ __align__(16) __nv_bfloat16 sk[144 * 40];
    __shared__ __align__(16) __nv_bfloat16 sv[144 * 40];

    int w = blockIdx.x / 6, head = blockIdx.x - w * 6;
    int tid = threadIdx.x, lane = tid & 31, wp = tid >> 5;
    size_t w6h = (size_t)(w * 6 + head);
    const __nv_bfloat16* qgb = g_q + w6h * 4608;
    const __nv_bfloat16* kgb = g_k + w6h * 4608;
    const __nv_bfloat16* vgb = g_v + w6h * 4608;
    uint32_t squ = cvta_smem(sq), sku = cvta_smem(sk), svu = cvta_smem(sv);

    for (int i = tid; i < 576; i += 96) {
        int r = i >> 2, s = i & 3;
        cp16(squ + r * 80 + s * 16, qgb + r * 32 + s * 8);
        cp16(sku + r * 80 + s * 16, kgb + r * 32 + s * 8);
        cp16(svu + r * 80 + s * 16, vgb + r * 32 + s * 8);
    }
    asm volatile("cp.async.commit_group;");
    asm volatile("cp.async.wait_group 0;");
    __syncthreads();

    int iz = w / 100, ih = (w / 10) % 10;
    const float* comb = g_comb + (size_t)(((iz * 10 + ih) * 6 + head)) * 20736;

    uint32_t qf[3][2][4];
#pragma unroll
    for (int mtl = 0; mtl < 3; mtl++)
#pragma unroll
        for (int ks = 0; ks < 2; ks++) {
            int r = wp * 48 + mtl * 16 + (lane & 15);
            int seg = ks * 2 + (lane >> 4);
            uint32_t addr = squ + r * 80 + seg * 16;
            asm volatile(
                "ldmatrix.sync.aligned.m8n8.x4.shared.b16 {%0,%1,%2,%3}, [%4];"
                : "=r"(qf[mtl][ks][0]), "=r"(qf[mtl][ks][1]),
                  "=r"(qf[mtl][ks][2]), "=r"(qf[mtl][ks][3])
                : "r"(addr));
        }

    float O[3][4][4];
#pragma unroll
    for (int a = 0; a < 3; a++)
#pragma unroll
        for (int b = 0; b < 4; b++)
#pragma unroll
            for (int c = 0; c < 4; c++) O[a][b][c] = 0.f;
    float mrun[3][2], lrun[3][2];
#pragma unroll
    for (int a = 0; a < 3; a++) { mrun[a][0] = mrun[a][1] = -1e30f; lrun[a][0] = lrun[a][1] = 0.f; }

#pragma unroll 1
    for (int cn_ = 0; cn_ < 9; cn_++) {
        uint32_t kf[2][2][2];
#pragma unroll
        for (int nt8 = 0; nt8 < 2; nt8++)
#pragma unroll
            for (int ks = 0; ks < 2; ks++) {
                int r = cn_ * 16 + nt8 * 8 + (lane & 7);
                int seg = ks * 2 + ((lane >> 3) & 1);
                uint32_t addr = sku + r * 80 + seg * 16;
                asm volatile(
                    "ldmatrix.sync.aligned.m8n8.x2.shared.b16 {%0,%1}, [%2];"
                    : "=r"(kf[nt8][ks][0]), "=r"(kf[nt8][ks][1]) : "r"(addr));
            }
        // V fragments: B (K=n chunk of 16, N=d tile of 8) via trans from [n][d]
        uint32_t vf[4][2];
#pragma unroll
        for (int dt = 0; dt < 4; dt++) {
            int r = cn_ * 16 + (lane & 7) + ((lane >> 3) & 1) * 8;
            uint32_t addr = svu + r * 80 + dt * 16;
            asm volatile(
                "ldmatrix.sync.aligned.m8n8.x2.trans.shared.b16 {%0,%1}, [%2];"
                : "=r"(vf[dt][0]), "=r"(vf[dt][1]) : "r"(addr));
        }

#pragma unroll
        for (int mtl = 0; mtl < 3; mtl++) {
            float s_[2][4];
#pragma unroll
            for (int nt8 = 0; nt8 < 2; nt8++) {
#pragma unroll
                for (int i = 0; i < 4; i++) s_[nt8][i] = 0.f;
#pragma unroll
                for (int ks = 0; ks < 2; ks++)
                    mma16816(s_[nt8], qf[mtl][ks], kf[nt8][ks]);
                const float4 b4 = *(const float4*)(comb +
                    (size_t)(((cn_ * 9 + wp * 3 + mtl) * 2 + nt8) * 128 + lane * 4));
                s_[nt8][0] += b4.x; s_[nt8][1] += b4.y;
                s_[nt8][2] += b4.z; s_[nt8][3] += b4.w;
            }
            float rm0 = fmaxf(fmaxf(s_[0][0], s_[0][1]), fmaxf(s_[1][0], s_[1][1]));
            float rm1 = fmaxf(fmaxf(s_[0][2], s_[0][3]), fmaxf(s_[1][2], s_[1][3]));
            rm0 = fmaxf(rm0, __shfl_xor_sync(0xffffffffu, rm0, 1));
            rm0 = fmaxf(rm0, __shfl_xor_sync(0xffffffffu, rm0, 2));
            rm1 = fmaxf(rm1, __shfl_xor_sync(0xffffffffu, rm1, 1));
            rm1 = fmaxf(rm1, __shfl_xor_sync(0xffffffffu, rm1, 2));
            float nm0 = fmaxf(mrun[mtl][0], rm0);
            float nm1 = fmaxf(mrun[mtl][1], rm1);
            float cr0 = __expf(mrun[mtl][0] - nm0);
            float cr1 = __expf(mrun[mtl][1] - nm1);
            mrun[mtl][0] = nm0; mrun[mtl][1] = nm1;
            float p[2][4];
#pragma unroll
            for (int nt8 = 0; nt8 < 2; nt8++) {
                p[nt8][0] = __expf(s_[nt8][0] - nm0);
                p[nt8][1] = __expf(s_[nt8][1] - nm0);
                p[nt8][2] = __expf(s_[nt8][2] - nm1);
                p[nt8][3] = __expf(s_[nt8][3] - nm1);
            }
            float ps0 = p[0][0] + p[0][1] + p[1][0] + p[1][1];
            float ps1 = p[0][2] + p[0][3] + p[1][2] + p[1][3];
            ps0 += __shfl_xor_sync(0xffffffffu, ps0, 1);
            ps0 += __shfl_xor_sync(0xffffffffu, ps0, 2);
            ps1 += __shfl_xor_sync(0xffffffffu, ps1, 1);
            ps1 += __shfl_xor_sync(0xffffffffu, ps1, 2);
            lrun[mtl][0] = lrun[mtl][0] * cr0 + ps0;
            lrun[mtl][1] = lrun[mtl][1] * cr1 + ps1;
#pragma unroll
            for (int dt = 0; dt < 4; dt++) {
                O[mtl][dt][0] *= cr0; O[mtl][dt][1] *= cr0;
                O[mtl][dt][2] *= cr1; O[mtl][dt][3] *= cr1;
            }
            uint32_t pa[4];
            __nv_bfloat162 t0 = __floats2bfloat162_rn(p[0][0], p[0][1]);
            __nv_bfloat162 t1 = __floats2bfloat162_rn(p[0][2], p[0][3]);
            __nv_bfloat162 t2 = __floats2bfloat162_rn(p[1][0], p[1][1]);
            __nv_bfloat162 t3 = __floats2bfloat162_rn(p[1][2], p[1][3]);
            pa[0] = *(uint32_t*)&t0; pa[1] = *(uint32_t*)&t1;
            pa[2] = *(uint32_t*)&t2; pa[3] = *(uint32_t*)&t3;
#pragma unroll
            for (int dt = 0; dt < 4; dt++)
                mma16816(O[mtl][dt], pa, vf[dt]);
        }
    }

#pragma unroll
    for (int mtl = 0; mtl < 3; mtl++) {
        float inv0 = 1.f / lrun[mtl][0];
        float inv1 = 1.f / lrun[mtl][1];
        int t0 = w * 144 + wp * 48 + mtl * 16 + (lane >> 2);
        int c0 = head * 32 + (lane & 3) * 2;
#pragma unroll
        for (int dt = 0; dt < 4; dt++) {
            int c = c0 + dt * 8;
            float v0 = O[mtl][dt][0] * inv0, v1 = O[mtl][dt][1] * inv0;
            float v2 = O[mtl][dt][2] * inv1, v3 = O[mtl][dt][3] * inv1;
            *(__nv_bfloat162*)&g_Aattn[(size_t)t0 * 192 + c] =
                __floats2bfloat162_rn(v0, v1);
            *(__nv_bfloat162*)&g_Aattn[(size_t)(t0 + 8) * 192 + c] =
                __floats2bfloat162_rn(v2, v3);
        }
    }
}

// ---------------------------------------------------------------------------
// Launch
// ---------------------------------------------------------------------------
extern "C" void kernel_launch(void* const* d_in, const int* in_sizes, int n_in,
                              void* d_out, int out_size) {
    const float* x          = (const float*)d_in[0];
    const float* cond       = (const float*)d_in[1];
    const float* g1         = (const float*)d_in[2];
    const float* bt1        = (const float*)d_in[3];
    const float* w_qkv      = (const float*)d_in[4];
    const float* b_qkv      = (const float*)d_in[5];
    const float* bias_table = (const float*)d_in[6];
    const float* w_proj     = (const float*)d_in[7];
    const float* b_proj     = (const float*)d_in[8];
    const float* g2         = (const float*)d_in[9];
    const float* bt2        = (const float*)d_in[10];
    const float* w_fc1      = (const float*)d_in[11];
    const float* b_fc1      = (const float*)d_in[12];
    const float* w_fc2      = (const float*)d_in[13];
    const float* b_fc2      = (const float*)d_in[14];
    float* out = (float*)d_out;

    __nv_bfloat16 *a1, *aat, *a2, *bq, *bp, *bf1, *bf2;
    float *yb;
    cudaGetSymbolAddress((void**)&a1, g_A1);
    cudaGetSymbolAddress((void**)&aat, g_Aattn);
    cudaGetSymbolAddress((void**)&yb, g_y);
    cudaGetSymbolAddress((void**)&a2, g_A2);
    cudaGetSymbolAddress((void**)&bq, g_Bqkv);
    cudaGetSymbolAddress((void**)&bp, g_Bproj);
    cudaGetSymbolAddress((void**)&bf1, g_Bfc1);
    cudaGetSymbolAddress((void**)&bf2, g_Bfc2);

    static bool attr_done = false;
    if (!attr_done) {
        cudaFuncSetAttribute(k_tc_gemm<0>,
                             cudaFuncAttributeMaxDynamicSharedMemorySize, 2 * STAGE_BYTES);
        cudaFuncSetAttribute(k_tc_gemm<1>,
                             cudaFuncAttributeMaxDynamicSharedMemorySize, 2 * STAGE_BYTES);
        cudaFuncSetAttribute(k_tc_gemm<2>,
                             cudaFuncAttributeMaxDynamicSharedMemorySize, 2 * STAGE_BYTES);
        cudaFuncSetAttribute(k_tc_gemm<3>,
                             cudaFuncAttributeMaxDynamicSharedMemorySize, 2 * STAGE_BYTES);
        attr_done = true;
    }

    // 0. Fused prep: weight transposes + bias/mask precompute
    k_prep<<<1968, 256>>>(w_qkv, w_proj, w_fc1, w_fc2, bias_table);

    // 1. LN1 + modulate + window gather
    k_ln1<<<NTOK / 8, 256>>>(x, cond, g1, bt1);

    // 2. QKV GEMM -> q/k/v bf16
    k_tc_gemm<0><<<dim3(3, NTOK / 128), 256, 2 * STAGE_BYTES>>>(
        a1, bq, b_qkv, 192, nullptr, nullptr, nullptr, nullptr);

    // 3. Flash attention (tensor cores)
    k_attn<<<NWIN * NHEADS, 96>>>();

    // 4. Proj GEMM + scatter + gated residual -> y
    k_tc_gemm<1><<<dim3(1, NTOK / 128), 256, 2 * STAGE_BYTES>>>(
        aat, bp, b_proj, 192, yb, nullptr, x, cond);

    // 5. LN2 + modulate
    k_ln2<<<NTOK / 8, 256>>>(cond, g2, bt2);

    // 6. FC1 GEMM + GeLU
    k_tc_gemm<2><<<dim3(4, NTOK / 128), 256, 2 * STAGE_BYTES>>>(
        a1, bf1, b_fc1, 192, nullptr, a2, nullptr, nullptr);

    // 7. FC2 GEMM + gated residual -> out
    k_tc_gemm<3><<<dim3(1, NTOK / 128), 256, 2 * STAGE_BYTES>>>(
        a2, bf2, b_fc2, 768, out, nullptr, yb, cond);
}

// round 10
// speedup vs baseline: 3.2392x; 1.1846x over previous
#include <cuda_runtime.h>
#include <cuda_bf16.h>
#include <math.h>
#include <stdint.h>

// ---------------------------------------------------------------------------
// Problem constants (B=1)
// ---------------------------------------------------------------------------
#define ZD 8
#define HD_ 60
#define WD 120
#define CDIM 192
#define NHEADS 6
#define WS0 2
#define WS1 6
#define WS2 12
#define NTOK 57600
#define NWIN 400
#define NLOC 144
#define NZ 4
#define NH 10
#define NL 10

// ---------------------------------------------------------------------------
// Scratch — plain bf16 GEMM operands. B' rows = N, K-major.
// ---------------------------------------------------------------------------
__device__ __nv_bfloat16 g_A1[NTOK * 192];      // ln1 out / ln2 out (K=192)
__device__ __nv_bfloat16 g_Aattn[NTOK * 192];   // attn out (K=192)
__device__ float         g_y[NTOK * 192];       // post-MSA residual
__device__ __nv_bfloat16 g_A2[NTOK * 768];      // fc1 out (K=768)
__device__ __nv_bfloat16 g_Bqkv[576 * 192];
__device__ __nv_bfloat16 g_Bproj[192 * 192];
__device__ __nv_bfloat16 g_Bfc1[768 * 192];
__device__ __nv_bfloat16 g_Bfc2[192 * 768];
// attention operands, per (window,head) contiguous — all [w][h][n][d]
__device__ __nv_bfloat16 g_q[NTOK * 192];       // q pre-scaled
__device__ __nv_bfloat16 g_k[NTOK * 192];
__device__ __nv_bfloat16 g_v[NTOK * 192];
// combined bias+mask in mma-fragment order
__device__ float g_comb[240 * 20736];

// ---------------------------------------------------------------------------
// Helpers
// ---------------------------------------------------------------------------
__device__ __forceinline__ float warpsum(float v) {
#pragma unroll
    for (int o = 16; o > 0; o >>= 1) v += __shfl_xor_sync(0xffffffffu, v, o);
    return v;
}

__device__ __forceinline__ int win_to_orig(int w, int n) {
    int ih = (w / NL) % NH, iz = w / (NL * NH);
    int il = w % NL;
    int z = n / (WS1 * WS2), hh = (n / WS2) % WS1, l = n % WS2;
    int gz = iz * WS0 + z, gh = ih * WS1 + hh, gl = il * WS2 + l;
    int oz = (gz + 1) & 7;
    int oh = gh + 3; if (oh >= HD_) oh -= HD_;
    int ol = gl + 6; if (ol >= WD) ol -= WD;
    return (oz * HD_ + oh) * WD + ol;
}

__device__ __forceinline__ uint32_t cvta_smem(const void* p) {
    return (uint32_t)__cvta_generic_to_shared(p);
}

__device__ __forceinline__ void cp16(uint32_t saddr, const void* g) {
    asm volatile("cp.async.cg.shared.global [%0], [%1], 16;"
                 :: "r"(saddr), "l"(g));
}

__device__ __forceinline__ void mma16816(float* c, const uint32_t* a, const uint32_t* b) {
    asm volatile(
        "mma.sync.aligned.m16n8k16.row.col.f32.bf16.bf16.f32 "
        "{%0,%1,%2,%3}, {%4,%5,%6,%7}, {%8,%9}, {%0,%1,%2,%3};"
        : "+f"(c[0]), "+f"(c[1]), "+f"(c[2]), "+f"(c[3])
        : "r"(a[0]), "r"(a[1]), "r"(a[2]), "r"(a[3]), "r"(b[0]), "r"(b[1]));
}

// ---------------------------------------------------------------------------
// Fused prep: 4 weight transposes + bias/mask precompute, one launch.
// ---------------------------------------------------------------------------
__device__ __forceinline__ void wprep_body(const float* __restrict__ W,
                                           __nv_bfloat16* __restrict__ Bp,
                                           int K, int N, int blk) {
    int i = blk * 256 + threadIdx.x;
    if (i >= K * N) return;
    int k = i / N, n = i - k * N;
    Bp[(size_t)n * K + k] = __float2bfloat16(W[i]);
}

__global__ void k_prep(const float* __restrict__ wq, const float* __restrict__ wp,
                       const float* __restrict__ w1, const float* __restrict__ w2,
                       const float* __restrict__ bt) {
    int b = blockIdx.x;
    if (b < 432)       { wprep_body(wq, g_Bqkv, 192, 576, b); return; }
    if (b < 576)       { wprep_body(wp, g_Bproj, 192, 192, b - 432); return; }
    if (b < 1152)      { wprep_body(w1, g_Bfc1, 192, 768, b - 576); return; }
    if (b < 1728)      { wprep_body(w2, g_Bfc2, 768, 192, b - 1152); return; }
    int th = b - 1728;                 // 0..239
    int typ = th / 6, head = th - typ * 6;
    int iz = typ / 10, ih = typ - iz * 10;
    float* dst = g_comb + (size_t)th * 20736;
    for (int idx = threadIdx.x; idx < 20736; idx += 256) {
        int cn_ = idx / 2304, r1 = idx - cn_ * 2304;
        int mt = r1 / 256, r2 = r1 - mt * 256;
        int nt8 = r2 >> 7, r3 = r2 & 127;
        int lane = r3 >> 2, he = r3 & 3;
        int h = he >> 1, e = he & 1;
        int m = mt * 16 + (lane >> 2) + h * 8;
        int n = cn_ * 16 + nt8 * 8 + (lane & 3) * 2 + e;
        int z1 = m / 72, h1 = (m / 12) % 6, l1 = m % 12;
        int z2 = n / 72, h2 = (n / 12) % 6, l2 = n % 12;
        int pidx = 828 * z1 + 23 * h1 + l1 + 11 + 1656 * z2 + 138 * h2 - l2;
        float v = bt[(size_t)pidx * 240 + typ * 6 + head];
        int gz1 = iz * 2 + z1, gh1 = ih * 6 + h1;
        int gz2 = iz * 2 + z2, gh2 = ih * 6 + h2;
        int lq = (gz1 < 6 ? 0 : (gz1 < 7 ? 1 : 2)) * 3 + (gh1 < 54 ? 0 : (gh1 < 57 ? 1 : 2));
        int lk = (gz2 < 6 ? 0 : (gz2 < 7 ? 1 : 2)) * 3 + (gh2 < 54 ? 0 : (gh2 < 57 ? 1 : 2));
        if (lq != lk) v -= 100.f;
        dst[idx] = v;
    }
}

// ---------------------------------------------------------------------------
// K1: LN1 + modulate + roll + window gather -> bf16 A
// ---------------------------------------------------------------------------
__global__ __launch_bounds__(256) void k_ln1(const float* __restrict__ x,
                                             const float* __restrict__ cond,
                                             const float* __restrict__ g,
                                             const float* __restrict__ b) {
    int t = blockIdx.x * 8 + (threadIdx.x >> 5);
    int lane = threadIdx.x & 31;
    int w = t / NLOC, n = t - w * NLOC;
    int src = win_to_orig(w, n);
    const float* xr = x + (size_t)src * CDIM;
    float v[6]; float s = 0.f;
#pragma unroll
    for (int i = 0; i < 6; i++) { v[i] = xr[lane + 32 * i]; s += v[i]; }
    s = warpsum(s);
    float mu = s * (1.f / 192.f);
    float vs = 0.f;
#pragma unroll
    for (int i = 0; i < 6; i++) { float d = v[i] - mu; vs += d * d; }
    vs = warpsum(vs);
    float rstd = rsqrtf(vs * (1.f / 192.f) + 1e-5f);
#pragma unroll
    for (int i = 0; i < 6; i++) {
        int c = lane + 32 * i;
        float val = (v[i] - mu) * rstd * g[c] + b[c];
        val = val * (1.f + cond[192 + c]) + cond[c];
        g_A1[(size_t)t * 192 + c] = __float2bfloat16(val);
    }
}

// ---------------------------------------------------------------------------
// Full-K (K=192) single-stage tensor-core GEMM. 120KB smem, 1 barrier.
// Block tile 128x192, 8 warps (2x4), warp tile 64x48.
// MODE 0: qkv -> q/k/v (kind = blockIdx.x)
// MODE 1: proj + gated residual -> g_y AND fused LN2+modulate -> g_A1
// MODE 2: fc1 + GeLU -> g_A2
// ---------------------------------------------------------------------------
#define K192_SMEM (3 * 16384 + 3 * 24576)
template <int MODE>
__global__ __launch_bounds__(256, 1) void k_gemm192(
    const __nv_bfloat16* __restrict__ A, const __nv_bfloat16* __restrict__ Bw,
    const float* __restrict__ bias,
    float* __restrict__ fout, __nv_bfloat16* __restrict__ sout,
    const float* __restrict__ res, const float* __restrict__ cond,
    const float* __restrict__ g2, const float* __restrict__ bt2) {
    extern __shared__ __align__(1024) unsigned char smem_dyn[];

    const int tid = threadIdx.x;
    const int lane = tid & 31;
    const int wid = tid >> 5;
    const int warp_m = (wid & 1) * 64;
    const int warp_n = (wid >> 1) * 48;

    const int rowbase = blockIdx.y * 128;
    const int colbase = blockIdx.x * 192;

    const __nv_bfloat16* Arow = A + (size_t)rowbase * 192;
    const __nv_bfloat16* Brow = Bw + (size_t)colbase * 192;

    const uint32_t smA = cvta_smem(smem_dyn);
    const uint32_t smB = smA + 3 * 16384;

    // ---- load everything (A: 3072 x16B, B: 4608 x16B) ----
#pragma unroll
    for (int i = 0; i < 12; i++) {
        int idx = tid + i * 256;
        int r = idx / 24, s = idx - r * 24;
        int panel = s >> 3, seg = s & 7;
        cp16(smA + panel * 16384 + r * 128 + ((seg ^ (r & 7)) << 4),
             Arow + (size_t)r * 192 + s * 8);
    }
#pragma unroll
    for (int i = 0; i < 18; i++) {
        int idx = tid + i * 256;
        int r = idx / 24, s = idx - r * 24;
        int panel = s >> 3, seg = s & 7;
        cp16(smB + panel * 24576 + r * 128 + ((seg ^ (r & 7)) << 4),
             Brow + (size_t)r * 192 + s * 8);
    }
    asm volatile("cp.async.commit_group;");

    float acc[4][6][4];
#pragma unroll
    for (int mt = 0; mt < 4; mt++)
#pragma unroll
        for (int nt = 0; nt < 6; nt++)
#pragma unroll
            for (int i = 0; i < 4; i++) acc[mt][nt][i] = 0.f;

    asm volatile("cp.async.wait_group 0;");
    __syncthreads();

    // ---- 12 k-steps, no barriers ----
#pragma unroll
    for (int kp = 0; kp < 3; kp++) {
        uint32_t sa = smA + kp * 16384;
        uint32_t sb = smB + kp * 24576;
#pragma unroll
        for (int kk = 0; kk < 4; kk++) {
            uint32_t af[4][4];
#pragma unroll
            for (int mt = 0; mt < 4; mt++) {
                int r = warp_m + mt * 16 + (lane & 15);
                int seg = kk * 2 + (lane >> 4);
                uint32_t addr = sa + r * 128 + (((seg ^ (r & 7)) & 7) << 4);
                asm volatile(
                    "ldmatrix.sync.aligned.m8n8.x4.shared.b16 {%0,%1,%2,%3}, [%4];"
                    : "=r"(af[mt][0]), "=r"(af[mt][1]), "=r"(af[mt][2]), "=r"(af[mt][3])
                    : "r"(addr));
            }
            uint32_t bf[6][2];
#pragma unroll
            for (int nt = 0; nt < 6; nt++) {
                int r = warp_n + nt * 8 + (lane & 7);
                int seg = kk * 2 + ((lane >> 3) & 1);
                uint32_t addr = sb + r * 128 + (((seg ^ (r & 7)) & 7) << 4);
                asm volatile(
                    "ldmatrix.sync.aligned.m8n8.x2.shared.b16 {%0,%1}, [%2];"
                    : "=r"(bf[nt][0]), "=r"(bf[nt][1])
                    : "r"(addr));
            }
#pragma unroll
            for (int mt = 0; mt < 4; mt++)
#pragma unroll
                for (int nt = 0; nt < 6; nt++)
                    mma16816(acc[mt][nt], af[mt], bf[nt]);
        }
    }

    // -------------------- epilogue --------------------
    if (MODE == 0) {
        const int kind = blockIdx.x;
#pragma unroll
        for (int mt = 0; mt < 4; mt++) {
#pragma unroll
            for (int half = 0; half < 2; half++) {
                int row = rowbase + warp_m + mt * 16 + (lane >> 2) + half * 8;
                int wwin = row / NLOC, nn = row - wwin * NLOC;
#pragma unroll
                for (int nt = 0; nt < 6; nt++) {
                    int cc = warp_n + nt * 8 + (lane & 3) * 2;
                    int hd = cc >> 5, d = cc & 31;
                    float a0 = acc[mt][nt][half * 2 + 0] + bias[colbase + cc];
                    float a1 = acc[mt][nt][half * 2 + 1] + bias[colbase + cc + 1];
                    size_t w6h = (size_t)(wwin * 6 + hd);
                    __nv_bfloat16* dst;
                    if (kind == 0) {
                        a0 *= 0.17677669529663687f;
                        a1 *= 0.17677669529663687f;
                        dst = g_q;
                    } else if (kind == 1) dst = g_k;
                    else dst = g_v;
                    *(__nv_bfloat162*)&dst[(w6h * 144 + nn) * 32 + d] =
                        __floats2bfloat162_rn(a0, a1);
                }
            }
        }
    } else if (MODE == 2) {
#pragma unroll
        for (int mt = 0; mt < 4; mt++) {
#pragma unroll
            for (int half = 0; half < 2; half++) {
                int row = rowbase + warp_m + mt * 16 + (lane >> 2) + half * 8;
#pragma unroll
                for (int nt = 0; nt < 6; nt++) {
                    int cc = warp_n + nt * 8 + (lane & 3) * 2;
                    float o[2];
#pragma unroll
                    for (int e = 0; e < 2; e++) {
                        float xg = acc[mt][nt][half * 2 + e] + bias[colbase + cc + e];
                        o[e] = 0.5f * xg * (1.f + erff(xg * 0.70710678118654752f));
                    }
                    *(__nv_bfloat162*)&sout[(size_t)row * 768 + colbase + cc] =
                        __floats2bfloat162_rn(o[0], o[1]);
                }
            }
        }
    } else {
        // MODE 1: y = x + gt_msa*(proj+bias), then LN2+modulate fused.
        __syncthreads();                       // operands no longer needed
        float* red = (float*)smem_dyn;         // [2][4][128] = 4KB
        const int g = wid >> 1;
        // pass 1: compute y, write g_y, accumulate row partials
#pragma unroll
        for (int mt = 0; mt < 4; mt++) {
#pragma unroll
            for (int half = 0; half < 2; half++) {
                int rowl = (wid & 1) * 64 + mt * 16 + half * 8 + (lane >> 2);
                int row = rowbase + rowl;
                int orow = win_to_orig(row / NLOC, row % NLOC);
                float s1 = 0.f, s2 = 0.f;
#pragma unroll
                for (int nt = 0; nt < 6; nt++) {
                    int cc = warp_n + nt * 8 + (lane & 3) * 2;
                    float yv[2];
#pragma unroll
                    for (int e = 0; e < 2; e++) {
                        int c = cc + e;
                        float val = acc[mt][nt][half * 2 + e] + bias[c];
                        yv[e] = res[(size_t)orow * 192 + c] + cond[384 + c] * val;
                        acc[mt][nt][half * 2 + e] = yv[e];
                        s1 += yv[e]; s2 += yv[e] * yv[e];
                    }
                    *(float2*)&fout[(size_t)orow * 192 + cc] =
                        make_float2(yv[0], yv[1]);
                }
                s1 += __shfl_xor_sync(0xffffffffu, s1, 1);
                s1 += __shfl_xor_sync(0xffffffffu, s1, 2);
                s2 += __shfl_xor_sync(0xffffffffu, s2, 1);
                s2 += __shfl_xor_sync(0xffffffffu, s2, 2);
                if ((lane & 3) == 0) {
                    red[g * 128 + rowl] = s1;
                    red[512 + g * 128 + rowl] = s2;
                }
            }
        }
        __syncthreads();
        // pass 2: LN + modulate -> bf16 A1
#pragma unroll
        for (int mt = 0; mt < 4; mt++) {
#pragma unroll
            for (int half = 0; half < 2; half++) {
                int rowl = (wid & 1) * 64 + mt * 16 + half * 8 + (lane >> 2);
                int row = rowbase + rowl;
                int orow = win_to_orig(row / NLOC, row % NLOC);
                float sum = red[rowl] + red[128 + rowl] + red[256 + rowl] + red[384 + rowl];
                float sq  = red[512 + rowl] + red[640 + rowl] + red[768 + rowl] + red[896 + rowl];
                float mu = sum * (1.f / 192.f);
                float var = sq * (1.f / 192.f) - mu * mu;
                float rstd = rsqrtf(var + 1e-5f);
#pragma unroll
                for (int nt = 0; nt < 6; nt++) {
                    int cc = warp_n + nt * 8 + (lane & 3) * 2;
                    float o[2];
#pragma unroll
                    for (int e = 0; e < 2; e++) {
                        int c = cc + e;
                        float nv = (acc[mt][nt][half * 2 + e] - mu) * rstd * g2[c] + bt2[c];
                        o[e] = nv * (1.f + cond[768 + c]) + cond[576 + c];
                    }
                    *(__nv_bfloat162*)&sout[(size_t)orow * 192 + cc] =
                        __floats2bfloat162_rn(o[0], o[1]);
                }
            }
        }
    }
}

// ---------------------------------------------------------------------------
// FC2 GEMM (K=768): 2-stage cp.async pipeline; gated residual epilogue.
// ---------------------------------------------------------------------------
#define STAGE_BYTES 40960
__global__ __launch_bounds__(256, 1) void k_gemm_fc2(
    const __nv_bfloat16* __restrict__ A, const __nv_bfloat16* __restrict__ Bw,
    const float* __restrict__ bias,
    float* __restrict__ fout, const float* __restrict__ res,
    const float* __restrict__ cond) {
    extern __shared__ __align__(1024) unsigned char smem_dyn[];

    const int tid = threadIdx.x;
    const int lane = tid & 31;
    const int wid = tid >> 5;
    const int warp_m = (wid & 1) * 64;
    const int warp_n = (wid >> 1) * 48;
    const int rowbase = blockIdx.y * 128;
    const int Keff = 768;

    const __nv_bfloat16* Arow = A + (size_t)rowbase * Keff;
    const __nv_bfloat16* Brow = Bw;

    float acc[4][6][4];
#pragma unroll
    for (int mt = 0; mt < 4; mt++)
#pragma unroll
        for (int nt = 0; nt < 6; nt++)
#pragma unroll
            for (int i = 0; i < 4; i++) acc[mt][nt][i] = 0.f;

    int ar[4], as_[4], br[6], bs_[6];
#pragma unroll
    for (int i = 0; i < 4; i++) {
        int idx = tid + i * 256;
        ar[i] = idx >> 3; as_[i] = idx & 7;
    }
#pragma unroll
    for (int i = 0; i < 6; i++) {
        int idx = tid + i * 256;
        br[i] = idx >> 3; bs_[i] = idx & 7;
    }

    const uint32_t smem_u = cvta_smem(smem_dyn);

    auto issue = [&](int ch) {
        uint32_t sa = smem_u + (ch & 1) * STAGE_BYTES;
        uint32_t sb = sa + 16384;
        const __nv_bfloat16* Ach = Arow + ch * 64;
        const __nv_bfloat16* Bch = Brow + ch * 64;
#pragma unroll
        for (int i = 0; i < 4; i++)
            cp16(sa + (uint32_t)(ar[i] * 128 + ((as_[i] ^ (ar[i] & 7)) << 4)),
                 Ach + (size_t)ar[i] * Keff + as_[i] * 8);
#pragma unroll
        for (int i = 0; i < 6; i++)
            cp16(sb + (uint32_t)(br[i] * 128 + ((bs_[i] ^ (br[i] & 7)) << 4)),
                 Bch + (size_t)br[i] * Keff + bs_[i] * 8);
        asm volatile("cp.async.commit_group;");
    };

    issue(0);
    for (int ch = 0; ch < 12; ch++) {
        if (ch + 1 < 12) {
            issue(ch + 1);
            asm volatile("cp.async.wait_group 1;");
        } else {
            asm volatile("cp.async.wait_group 0;");
        }
        __syncthreads();
        uint32_t sa = smem_u + (ch & 1) * STAGE_BYTES;
        uint32_t sb = sa + 16384;
#pragma unroll
        for (int kk = 0; kk < 4; kk++) {
            uint32_t af[4][4];
#pragma unroll
            for (int mt = 0; mt < 4; mt++) {
                int r = warp_m + mt * 16 + (lane & 15);
                int seg = kk * 2 + (lane >> 4);
                uint32_t addr = sa + r * 128 + (((seg ^ (r & 7)) & 7) << 4);
                asm volatile(
                    "ldmatrix.sync.aligned.m8n8.x4.shared.b16 {%0,%1,%2,%3}, [%4];"
                    : "=r"(af[mt][0]), "=r"(af[mt][1]), "=r"(af[mt][2]), "=r"(af[mt][3])
                    : "r"(addr));
            }
            uint32_t bf[6][2];
#pragma unroll
            for (int nt = 0; nt < 6; nt++) {
                int r = warp_n + nt * 8 + (lane & 7);
                int seg = kk * 2 + ((lane >> 3) & 1);
                uint32_t addr = sb + r * 128 + (((seg ^ (r & 7)) & 7) << 4);
                asm volatile(
                    "ldmatrix.sync.aligned.m8n8.x2.shared.b16 {%0,%1}, [%2];"
                    : "=r"(bf[nt][0]), "=r"(bf[nt][1])
                    : "r"(addr));
            }
#pragma unroll
            for (int mt = 0; mt < 4; mt++)
#pragma unroll
                for (int nt = 0; nt < 6; nt++)
                    mma16816(acc[mt][nt], af[mt], bf[nt]);
        }
        __syncthreads();
    }

#pragma unroll
    for (int mt = 0; mt < 4; mt++) {
#pragma unroll
        for (int half = 0; half < 2; half++) {
            int row = rowbase + warp_m + mt * 16 + (lane >> 2) + half * 8;
#pragma unroll
            for (int nt = 0; nt < 6; nt++) {
                int cc = warp_n + nt * 8 + (lane & 3) * 2;
#pragma unroll
                for (int e = 0; e < 2; e++) {
                    int c = cc + e;
                    float val = acc[mt][nt][half * 2 + e] + bias[c];
                    fout[(size_t)row * 192 + c] =
                        res[(size_t)row * 192 + c] + cond[960 + c] * val;
                }
            }
        }
    }
}

// ---------------------------------------------------------------------------
// K3: tensor-core flash attention (unchanged from R9).
// ---------------------------------------------------------------------------
__global__ __launch_bounds__(96) void k_attn() {
    __shared__ __align__(16) __nv_bfloat16 sq[144 * 40];
    __shared__ __align__(16) __nv_bfloat16 sk[144 * 40];
    __shared__ __align__(16) __nv_bfloat16 sv[144 * 40];

    int w = blockIdx.x / 6, head = blockIdx.x - w * 6;
    int tid = threadIdx.x, lane = tid & 31, wp = tid >> 5;
    size_t w6h = (size_t)(w * 6 + head);
    const __nv_bfloat16* qgb = g_q + w6h * 4608;
    const __nv_bfloat16* kgb = g_k + w6h * 4608;
    const __nv_bfloat16* vgb = g_v + w6h * 4608;
    uint32_t squ = cvta_smem(sq), sku = cvta_smem(sk), svu = cvta_smem(sv);

    for (int i = tid; i < 576; i += 96) {
        int r = i >> 2, s = i & 3;
        cp16(squ + r * 80 + s * 16, qgb + r * 32 + s * 8);
        cp16(sku + r * 80 + s * 16, kgb + r * 32 + s * 8);
        cp16(svu + r * 80 + s * 16, vgb + r * 32 + s * 8);
    }
    asm volatile("cp.async.commit_group;");
    asm volatile("cp.async.wait_group 0;");
    __syncthreads();

    int iz = w / 100, ih = (w / 10) % 10;
    const float* comb = g_comb + (size_t)(((iz * 10 + ih) * 6 + head)) * 20736;

    uint32_t qf[3][2][4];
#pragma unroll
    for (int mtl = 0; mtl < 3; mtl++)
#pragma unroll
        for (int ks = 0; ks < 2; ks++) {
            int r = wp * 48 + mtl * 16 + (lane & 15);
            int seg = ks * 2 + (lane >> 4);
            uint32_t addr = squ + r * 80 + seg * 16;
            asm volatile(
                "ldmatrix.sync.aligned.m8n8.x4.shared.b16 {%0,%1,%2,%3}, [%4];"
                : "=r"(qf[mtl][ks][0]), "=r"(qf[mtl][ks][1]),
                  "=r"(qf[mtl][ks][2]), "=r"(qf[mtl][ks][3])
                : "r"(addr));
        }

    float O[3][4][4];
#pragma unroll
    for (int a = 0; a < 3; a++)
#pragma unroll
        for (int b = 0; b < 4; b++)
#pragma unroll
            for (int c = 0; c < 4; c++) O[a][b][c] = 0.f;
    float mrun[3][2], lrun[3][2];
#pragma unroll
    for (int a = 0; a < 3; a++) { mrun[a][0] = mrun[a][1] = -1e30f; lrun[a][0] = lrun[a][1] = 0.f; }

#pragma unroll 1
    for (int cn_ = 0; cn_ < 9; cn_++) {
        uint32_t kf[2][2][2];
#pragma unroll
        for (int nt8 = 0; nt8 < 2; nt8++)
#pragma unroll
            for (int ks = 0; ks < 2; ks++) {
                int r = cn_ * 16 + nt8 * 8 + (lane & 7);
                int seg = ks * 2 + ((lane >> 3) & 1);
                uint32_t addr = sku + r * 80 + seg * 16;
                asm volatile(
                    "ldmatrix.sync.aligned.m8n8.x2.shared.b16 {%0,%1}, [%2];"
                    : "=r"(kf[nt8][ks][0]), "=r"(kf[nt8][ks][1]) : "r"(addr));
            }
        uint32_t vf[4][2];
#pragma unroll
        for (int dt = 0; dt < 4; dt++) {
            int r = cn_ * 16 + (lane & 7) + ((lane >> 3) & 1) * 8;
            uint32_t addr = svu + r * 80 + dt * 16;
            asm volatile(
                "ldmatrix.sync.aligned.m8n8.x2.trans.shared.b16 {%0,%1}, [%2];"
                : "=r"(vf[dt][0]), "=r"(vf[dt][1]) : "r"(addr));
        }

#pragma unroll
        for (int mtl = 0; mtl < 3; mtl++) {
            float s_[2][4];
#pragma unroll
            for (int nt8 = 0; nt8 < 2; nt8++) {
#pragma unroll
                for (int i = 0; i < 4; i++) s_[nt8][i] = 0.f;
#pragma unroll
                for (int ks = 0; ks < 2; ks++)
                    mma16816(s_[nt8], qf[mtl][ks], kf[nt8][ks]);
                const float4 b4 = *(const float4*)(comb +
                    (size_t)(((cn_ * 9 + wp * 3 + mtl) * 2 + nt8) * 128 + lane * 4));
                s_[nt8][0] += b4.x; s_[nt8][1] += b4.y;
                s_[nt8][2] += b4.z; s_[nt8][3] += b4.w;
            }
            float rm0 = fmaxf(fmaxf(s_[0][0], s_[0][1]), fmaxf(s_[1][0], s_[1][1]));
            float rm1 = fmaxf(fmaxf(s_[0][2], s_[0][3]), fmaxf(s_[1][2], s_[1][3]));
            rm0 = fmaxf(rm0, __shfl_xor_sync(0xffffffffu, rm0, 1));
            rm0 = fmaxf(rm0, __shfl_xor_sync(0xffffffffu, rm0, 2));
            rm1 = fmaxf(rm1, __shfl_xor_sync(0xffffffffu, rm1, 1));
            rm1 = fmaxf(rm1, __shfl_xor_sync(0xffffffffu, rm1, 2));
            float nm0 = fmaxf(mrun[mtl][0], rm0);
            float nm1 = fmaxf(mrun[mtl][1], rm1);
            float cr0 = __expf(mrun[mtl][0] - nm0);
            float cr1 = __expf(mrun[mtl][1] - nm1);
            mrun[mtl][0] = nm0; mrun[mtl][1] = nm1;
            float p[2][4];
#pragma unroll
            for (int nt8 = 0; nt8 < 2; nt8++) {
                p[nt8][0] = __expf(s_[nt8][0] - nm0);
                p[nt8][1] = __expf(s_[nt8][1] - nm0);
                p[nt8][2] = __expf(s_[nt8][2] - nm1);
                p[nt8][3] = __expf(s_[nt8][3] - nm1);
            }
            float ps0 = p[0][0] + p[0][1] + p[1][0] + p[1][1];
            float ps1 = p[0][2] + p[0][3] + p[1][2] + p[1][3];
            ps0 += __shfl_xor_sync(0xffffffffu, ps0, 1);
            ps0 += __shfl_xor_sync(0xffffffffu, ps0, 2);
            ps1 += __shfl_xor_sync(0xffffffffu, ps1, 1);
            ps1 += __shfl_xor_sync(0xffffffffu, ps1, 2);
            lrun[mtl][0] = lrun[mtl][0] * cr0 + ps0;
            lrun[mtl][1] = lrun[mtl][1] * cr1 + ps1;
#pragma unroll
            for (int dt = 0; dt < 4; dt++) {
                O[mtl][dt][0] *= cr0; O[mtl][dt][1] *= cr0;
                O[mtl][dt][2] *= cr1; O[mtl][dt][3] *= cr1;
            }
            uint32_t pa[4];
            __nv_bfloat162 t0 = __floats2bfloat162_rn(p[0][0], p[0][1]);
            __nv_bfloat162 t1 = __floats2bfloat162_rn(p[0][2], p[0][3]);
            __nv_bfloat162 t2 = __floats2bfloat162_rn(p[1][0], p[1][1]);
            __nv_bfloat162 t3 = __floats2bfloat162_rn(p[1][2], p[1][3]);
            pa[0] = *(uint32_t*)&t0; pa[1] = *(uint32_t*)&t1;
            pa[2] = *(uint32_t*)&t2; pa[3] = *(uint32_t*)&t3;
#pragma unroll
            for (int dt = 0; dt < 4; dt++)
                mma16816(O[mtl][dt], pa, vf[dt]);
        }
    }

#pragma unroll
    for (int mtl = 0; mtl < 3; mtl++) {
        float inv0 = 1.f / lrun[mtl][0];
        float inv1 = 1.f / lrun[mtl][1];
        int t0 = w * 144 + wp * 48 + mtl * 16 + (lane >> 2);
        int c0 = head * 32 + (lane & 3) * 2;
#pragma unroll
        for (int dt = 0; dt < 4; dt++) {
            int c = c0 + dt * 8;
            float v0 = O[mtl][dt][0] * inv0, v1 = O[mtl][dt][1] * inv0;
            float v2 = O[mtl][dt][2] * inv1, v3 = O[mtl][dt][3] * inv1;
            *(__nv_bfloat162*)&g_Aattn[(size_t)t0 * 192 + c] =
                __floats2bfloat162_rn(v0, v1);
            *(__nv_bfloat162*)&g_Aattn[(size_t)(t0 + 8) * 192 + c] =
                __floats2bfloat162_rn(v2, v3);
        }
    }
}

// ---------------------------------------------------------------------------
// Launch
// ---------------------------------------------------------------------------
extern "C" void kernel_launch(void* const* d_in, const int* in_sizes, int n_in,
                              void* d_out, int out_size) {
    const float* x          = (const float*)d_in[0];
    const float* cond       = (const float*)d_in[1];
    const float* g1         = (const float*)d_in[2];
    const float* bt1        = (const float*)d_in[3];
    const float* w_qkv      = (const float*)d_in[4];
    const float* b_qkv      = (const float*)d_in[5];
    const float* bias_table = (const float*)d_in[6];
    const float* w_proj     = (const float*)d_in[7];
    const float* b_proj     = (const float*)d_in[8];
    const float* g2         = (const float*)d_in[9];
    const float* bt2        = (const float*)d_in[10];
    const float* w_fc1      = (const float*)d_in[11];
    const float* b_fc1      = (const float*)d_in[12];
    const float* w_fc2      = (const float*)d_in[13];
    const float* b_fc2      = (const float*)d_in[14];
    float* out = (float*)d_out;

    __nv_bfloat16 *a1, *aat, *a2, *bq, *bp, *bf1, *bf2;
    float *yb;
    cudaGetSymbolAddress((void**)&a1, g_A1);
    cudaGetSymbolAddress((void**)&aat, g_Aattn);
    cudaGetSymbolAddress((void**)&yb, g_y);
    cudaGetSymbolAddress((void**)&a2, g_A2);
    cudaGetSymbolAddress((void**)&bq, g_Bqkv);
    cudaGetSymbolAddress((void**)&bp, g_Bproj);
    cudaGetSymbolAddress((void**)&bf1, g_Bfc1);
    cudaGetSymbolAddress((void**)&bf2, g_Bfc2);

    static bool attr_done = false;
    if (!attr_done) {
        cudaFuncSetAttribute(k_gemm192<0>,
                             cudaFuncAttributeMaxDynamicSharedMemorySize, K192_SMEM);
        cudaFuncSetAttribute(k_gemm192<1>,
                             cudaFuncAttributeMaxDynamicSharedMemorySize, K192_SMEM);
        cudaFuncSetAttribute(k_gemm192<2>,
                             cudaFuncAttributeMaxDynamicSharedMemorySize, K192_SMEM);
        cudaFuncSetAttribute(k_gemm_fc2,
                             cudaFuncAttributeMaxDynamicSharedMemorySize, 2 * STAGE_BYTES);
        attr_done = true;
    }

    // 0. Fused prep: weight transposes + bias/mask precompute
    k_prep<<<1968, 256>>>(w_qkv, w_proj, w_fc1, w_fc2, bias_table);

    // 1. LN1 + modulate + window gather
    k_ln1<<<NTOK / 8, 256>>>(x, cond, g1, bt1);

    // 2. QKV GEMM -> q/k/v bf16
    k_gemm192<0><<<dim3(3, NTOK / 128), 256, K192_SMEM>>>(
        a1, bq, b_qkv, nullptr, nullptr, nullptr, nullptr, nullptr, nullptr);

    // 3. Flash attention (tensor cores)
    k_attn<<<NWIN * NHEADS, 96>>>();

    // 4. Proj GEMM + gated residual -> y, fused LN2+modulate -> a1
    k_gemm192<1><<<dim3(1, NTOK / 128), 256, K192_SMEM>>>(
        aat, bp, b_proj, yb, a1, x, cond, g2, bt2);

    // 5. FC1 GEMM + GeLU -> a2
    k_gemm192<2><<<dim3(4, NTOK / 128), 256, K192_SMEM>>>(
        a1, bf1, b_fc1, nullptr, a2, nullptr, nullptr, nullptr, nullptr);

    // 6. FC2 GEMM + gated residual -> out
    k_gemm_fc2<<<dim3(1, NTOK / 128), 256, 2 * STAGE_BYTES>>>(
        a2, bf2, b_fc2, out, yb, cond);
}

// round 12
// speedup vs baseline: 3.3588x; 1.0369x over previous
#include <cuda_runtime.h>
#include <cuda_bf16.h>
#include <math.h>
#include <stdint.h>

// ---------------------------------------------------------------------------
// Problem constants (B=1)
// ---------------------------------------------------------------------------
#define ZD 8
#define HD_ 60
#define WD 120
#define CDIM 192
#define NHEADS 6
#define WS0 2
#define WS1 6
#define WS2 12
#define NTOK 57600
#define NWIN 400
#define NLOC 144
#define NZ 4
#define NH 10
#define NL 10

// ---------------------------------------------------------------------------
// Scratch — plain bf16 GEMM operands. B' rows = N, K-major.
// ---------------------------------------------------------------------------
__device__ __nv_bfloat16 g_A1[NTOK * 192];      // ln1 out / ln2 out (K=192)
__device__ __nv_bfloat16 g_Aattn[NTOK * 192];   // attn out (K=192)
__device__ float         g_y[NTOK * 192];       // post-MSA residual
__device__ __nv_bfloat16 g_A2[NTOK * 768];      // fc1 out (K=768)
__device__ __nv_bfloat16 g_Bqkv[576 * 192];
__device__ __nv_bfloat16 g_Bproj[192 * 192];
__device__ __nv_bfloat16 g_Bfc1[768 * 192];
__device__ __nv_bfloat16 g_Bfc2[192 * 768];
// attention operands, per (window,head) contiguous — all [w][h][n][d]
__device__ __nv_bfloat16 g_q[NTOK * 192];       // q pre-scaled
__device__ __nv_bfloat16 g_k[NTOK * 192];
__device__ __nv_bfloat16 g_v[NTOK * 192];
// combined bias+mask in mma-fragment order
__device__ float g_comb[240 * 20736];

// ---------------------------------------------------------------------------
// Helpers
// ---------------------------------------------------------------------------
__device__ __forceinline__ float warpsum(float v) {
#pragma unroll
    for (int o = 16; o > 0; o >>= 1) v += __shfl_xor_sync(0xffffffffu, v, o);
    return v;
}

__device__ __forceinline__ int win_to_orig(int w, int n) {
    int ih = (w / NL) % NH, iz = w / (NL * NH);
    int il = w % NL;
    int z = n / (WS1 * WS2), hh = (n / WS2) % WS1, l = n % WS2;
    int gz = iz * WS0 + z, gh = ih * WS1 + hh, gl = il * WS2 + l;
    int oz = (gz + 1) & 7;
    int oh = gh + 3; if (oh >= HD_) oh -= HD_;
    int ol = gl + 6; if (ol >= WD) ol -= WD;
    return (oz * HD_ + oh) * WD + ol;
}

__device__ __forceinline__ uint32_t cvta_smem(const void* p) {
    return (uint32_t)__cvta_generic_to_shared(p);
}

__device__ __forceinline__ void cp16(uint32_t saddr, const void* g) {
    asm volatile("cp.async.cg.shared.global [%0], [%1], 16;"
                 :: "r"(saddr), "l"(g));
}

__device__ __forceinline__ void mma16816(float* c, const uint32_t* a, const uint32_t* b) {
    asm volatile(
        "mma.sync.aligned.m16n8k16.row.col.f32.bf16.bf16.f32 "
        "{%0,%1,%2,%3}, {%4,%5,%6,%7}, {%8,%9}, {%0,%1,%2,%3};"
        : "+f"(c[0]), "+f"(c[1]), "+f"(c[2]), "+f"(c[3])
        : "r"(a[0]), "r"(a[1]), "r"(a[2]), "r"(a[3]), "r"(b[0]), "r"(b[1]));
}

// ---------------------------------------------------------------------------
// K0: fused prep (4 weight transposes + bias/mask) AND LN1+modulate+gather.
// Blocks [0,432): qkv  [432,576): proj  [576,1152): fc1  [1152,1728): fc2
// [1728,1968): bias+mask   [1968, 1968+7200): LN1
// ---------------------------------------------------------------------------
__device__ __forceinline__ void wprep_body(const float* __restrict__ W,
                                           __nv_bfloat16* __restrict__ Bp,
                                           int K, int N, int blk) {
    int i = blk * 256 + threadIdx.x;
    if (i >= K * N) return;
    int k = i / N, n = i - k * N;
    Bp[(size_t)n * K + k] = __float2bfloat16(W[i]);
}

__global__ __launch_bounds__(256) void k_preln(
    const float* __restrict__ wq, const float* __restrict__ wp,
    const float* __restrict__ w1, const float* __restrict__ w2,
    const float* __restrict__ bt,
    const float* __restrict__ x, const float* __restrict__ cond,
    const float* __restrict__ g1, const float* __restrict__ bt1) {
    int b = blockIdx.x;
    if (b < 432)       { wprep_body(wq, g_Bqkv, 192, 576, b); return; }
    if (b < 576)       { wprep_body(wp, g_Bproj, 192, 192, b - 432); return; }
    if (b < 1152)      { wprep_body(w1, g_Bfc1, 192, 768, b - 576); return; }
    if (b < 1728)      { wprep_body(w2, g_Bfc2, 768, 192, b - 1152); return; }
    if (b < 1968) {
        int th = b - 1728;                 // 0..239
        int typ = th / 6, head = th - typ * 6;
        int iz = typ / 10, ih = typ - iz * 10;
        float* dst = g_comb + (size_t)th * 20736;
        for (int idx = threadIdx.x; idx < 20736; idx += 256) {
            int cn_ = idx / 2304, r1 = idx - cn_ * 2304;
            int mt = r1 / 256, r2 = r1 - mt * 256;
            int nt8 = r2 >> 7, r3 = r2 & 127;
            int lane = r3 >> 2, he = r3 & 3;
            int h = he >> 1, e = he & 1;
            int m = mt * 16 + (lane >> 2) + h * 8;
            int n = cn_ * 16 + nt8 * 8 + (lane & 3) * 2 + e;
            int z1 = m / 72, h1 = (m / 12) % 6, l1 = m % 12;
            int z2 = n / 72, h2 = (n / 12) % 6, l2 = n % 12;
            int pidx = 828 * z1 + 23 * h1 + l1 + 11 + 1656 * z2 + 138 * h2 - l2;
            float v = bt[(size_t)pidx * 240 + typ * 6 + head];
            int gz1 = iz * 2 + z1, gh1 = ih * 6 + h1;
            int gz2 = iz * 2 + z2, gh2 = ih * 6 + h2;
            int lq = (gz1 < 6 ? 0 : (gz1 < 7 ? 1 : 2)) * 3 + (gh1 < 54 ? 0 : (gh1 < 57 ? 1 : 2));
            int lk = (gz2 < 6 ? 0 : (gz2 < 7 ? 1 : 2)) * 3 + (gh2 < 54 ? 0 : (gh2 < 57 ? 1 : 2));
            if (lq != lk) v -= 100.f;
            dst[idx] = v;
        }
        return;
    }
    // ---- LN1 + modulate + window gather ----
    int t = (b - 1968) * 8 + (threadIdx.x >> 5);
    int lane = threadIdx.x & 31;
    int w = t / NLOC, n = t - w * NLOC;
    int src = win_to_orig(w, n);
    const float* xr = x + (size_t)src * CDIM;
    float v[6]; float s = 0.f;
#pragma unroll
    for (int i = 0; i < 6; i++) { v[i] = xr[lane + 32 * i]; s += v[i]; }
    s = warpsum(s);
    float mu = s * (1.f / 192.f);
    float vs = 0.f;
#pragma unroll
    for (int i = 0; i < 6; i++) { float d = v[i] - mu; vs += d * d; }
    vs = warpsum(vs);
    float rstd = rsqrtf(vs * (1.f / 192.f) + 1e-5f);
#pragma unroll
    for (int i = 0; i < 6; i++) {
        int c = lane + 32 * i;
        float val = (v[i] - mu) * rstd * g1[c] + bt1[c];
        val = val * (1.f + cond[192 + c]) + cond[c];
        g_A1[(size_t)t * 192 + c] = __float2bfloat16(val);
    }
}

// ---------------------------------------------------------------------------
// Full-K (K=192) single-stage tensor-core GEMM. 120KB smem, 1 barrier.
// MODE 0: qkv -> q/k/v (kind = blockIdx.x)
// MODE 1: proj + gated residual -> g_y AND fused LN2+modulate -> g_A1
// MODE 2: fc1 + GeLU -> g_A2
// ---------------------------------------------------------------------------
#define K192_SMEM (3 * 16384 + 3 * 24576)
template <int MODE>
__global__ __launch_bounds__(256, 1) void k_gemm192(
    const __nv_bfloat16* __restrict__ A, const __nv_bfloat16* __restrict__ Bw,
    const float* __restrict__ bias,
    float* __restrict__ fout, __nv_bfloat16* __restrict__ sout,
    const float* __restrict__ res, const float* __restrict__ cond,
    const float* __restrict__ g2, const float* __restrict__ bt2) {
    extern __shared__ __align__(1024) unsigned char smem_dyn[];

    const int tid = threadIdx.x;
    const int lane = tid & 31;
    const int wid = tid >> 5;
    const int warp_m = (wid & 1) * 64;
    const int warp_n = (wid >> 1) * 48;

    const int rowbase = blockIdx.y * 128;
    const int colbase = blockIdx.x * 192;

    const __nv_bfloat16* Arow = A + (size_t)rowbase * 192;
    const __nv_bfloat16* Brow = Bw + (size_t)colbase * 192;

    const uint32_t smA = cvta_smem(smem_dyn);
    const uint32_t smB = smA + 3 * 16384;

#pragma unroll
    for (int i = 0; i < 12; i++) {
        int idx = tid + i * 256;
        int r = idx / 24, s = idx - r * 24;
        int panel = s >> 3, seg = s & 7;
        cp16(smA + panel * 16384 + r * 128 + ((seg ^ (r & 7)) << 4),
             Arow + (size_t)r * 192 + s * 8);
    }
#pragma unroll
    for (int i = 0; i < 18; i++) {
        int idx = tid + i * 256;
        int r = idx / 24, s = idx - r * 24;
        int panel = s >> 3, seg = s & 7;
        cp16(smB + panel * 24576 + r * 128 + ((seg ^ (r & 7)) << 4),
             Brow + (size_t)r * 192 + s * 8);
    }
    asm volatile("cp.async.commit_group;");

    float acc[4][6][4];
#pragma unroll
    for (int mt = 0; mt < 4; mt++)
#pragma unroll
        for (int nt = 0; nt < 6; nt++)
#pragma unroll
            for (int i = 0; i < 4; i++) acc[mt][nt][i] = 0.f;

    asm volatile("cp.async.wait_group 0;");
    __syncthreads();

#pragma unroll
    for (int kp = 0; kp < 3; kp++) {
        uint32_t sa = smA + kp * 16384;
        uint32_t sb = smB + kp * 24576;
#pragma unroll
        for (int kk = 0; kk < 4; kk++) {
            uint32_t af[4][4];
#pragma unroll
            for (int mt = 0; mt < 4; mt++) {
                int r = warp_m + mt * 16 + (lane & 15);
                int seg = kk * 2 + (lane >> 4);
                uint32_t addr = sa + r * 128 + (((seg ^ (r & 7)) & 7) << 4);
                asm volatile(
                    "ldmatrix.sync.aligned.m8n8.x4.shared.b16 {%0,%1,%2,%3}, [%4];"
                    : "=r"(af[mt][0]), "=r"(af[mt][1]), "=r"(af[mt][2]), "=r"(af[mt][3])
                    : "r"(addr));
            }
            uint32_t bf[6][2];
#pragma unroll
            for (int nt = 0; nt < 6; nt++) {
                int r = warp_n + nt * 8 + (lane & 7);
                int seg = kk * 2 + ((lane >> 3) & 1);
                uint32_t addr = sb + r * 128 + (((seg ^ (r & 7)) & 7) << 4);
                asm volatile(
                    "ldmatrix.sync.aligned.m8n8.x2.shared.b16 {%0,%1}, [%2];"
                    : "=r"(bf[nt][0]), "=r"(bf[nt][1])
                    : "r"(addr));
            }
#pragma unroll
            for (int mt = 0; mt < 4; mt++)
#pragma unroll
                for (int nt = 0; nt < 6; nt++)
                    mma16816(acc[mt][nt], af[mt], bf[nt]);
        }
    }

    // -------------------- epilogue --------------------
    if (MODE == 0) {
        const int kind = blockIdx.x;
#pragma unroll
        for (int mt = 0; mt < 4; mt++) {
#pragma unroll
            for (int half = 0; half < 2; half++) {
                int row = rowbase + warp_m + mt * 16 + (lane >> 2) + half * 8;
                int wwin = row / NLOC, nn = row - wwin * NLOC;
#pragma unroll
                for (int nt = 0; nt < 6; nt++) {
                    int cc = warp_n + nt * 8 + (lane & 3) * 2;
                    int hd = cc >> 5, d = cc & 31;
                    float a0 = acc[mt][nt][half * 2 + 0] + bias[colbase + cc];
                    float a1 = acc[mt][nt][half * 2 + 1] + bias[colbase + cc + 1];
                    size_t w6h = (size_t)(wwin * 6 + hd);
                    __nv_bfloat16* dst;
                    if (kind == 0) {
                        a0 *= 0.17677669529663687f;
                        a1 *= 0.17677669529663687f;
                        dst = g_q;
                    } else if (kind == 1) dst = g_k;
                    else dst = g_v;
                    *(__nv_bfloat162*)&dst[(w6h * 144 + nn) * 32 + d] =
                        __floats2bfloat162_rn(a0, a1);
                }
            }
        }
    } else if (MODE == 2) {
#pragma unroll
        for (int mt = 0; mt < 4; mt++) {
#pragma unroll
            for (int half = 0; half < 2; half++) {
                int row = rowbase + warp_m + mt * 16 + (lane >> 2) + half * 8;
#pragma unroll
                for (int nt = 0; nt < 6; nt++) {
                    int cc = warp_n + nt * 8 + (lane & 3) * 2;
                    float o[2];
#pragma unroll
                    for (int e = 0; e < 2; e++) {
                        float xg = acc[mt][nt][half * 2 + e] + bias[colbase + cc + e];
                        o[e] = 0.5f * xg * (1.f + erff(xg * 0.70710678118654752f));
                    }
                    *(__nv_bfloat162*)&sout[(size_t)row * 768 + colbase + cc] =
                        __floats2bfloat162_rn(o[0], o[1]);
                }
            }
        }
    } else {
        __syncthreads();
        float* red = (float*)smem_dyn;
        const int g = wid >> 1;
#pragma unroll
        for (int mt = 0; mt < 4; mt++) {
#pragma unroll
            for (int half = 0; half < 2; half++) {
                int rowl = (wid & 1) * 64 + mt * 16 + half * 8 + (lane >> 2);
                int row = rowbase + rowl;
                int orow = win_to_orig(row / NLOC, row % NLOC);
                float s1 = 0.f, s2 = 0.f;
#pragma unroll
                for (int nt = 0; nt < 6; nt++) {
                    int cc = warp_n + nt * 8 + (lane & 3) * 2;
                    float yv[2];
#pragma unroll
                    for (int e = 0; e < 2; e++) {
                        int c = cc + e;
                        float val = acc[mt][nt][half * 2 + e] + bias[c];
                        yv[e] = res[(size_t)orow * 192 + c] + cond[384 + c] * val;
                        acc[mt][nt][half * 2 + e] = yv[e];
                        s1 += yv[e]; s2 += yv[e] * yv[e];
                    }
                    *(float2*)&fout[(size_t)orow * 192 + cc] =
                        make_float2(yv[0], yv[1]);
                }
                s1 += __shfl_xor_sync(0xffffffffu, s1, 1);
                s1 += __shfl_xor_sync(0xffffffffu, s1, 2);
                s2 += __shfl_xor_sync(0xffffffffu, s2, 1);
                s2 += __shfl_xor_sync(0xffffffffu, s2, 2);
                if ((lane & 3) == 0) {
                    red[g * 128 + rowl] = s1;
                    red[512 + g * 128 + rowl] = s2;
                }
            }
        }
        __syncthreads();
#pragma unroll
        for (int mt = 0; mt < 4; mt++) {
#pragma unroll
            for (int half = 0; half < 2; half++) {
                int rowl = (wid & 1) * 64 + mt * 16 + half * 8 + (lane >> 2);
                int row = rowbase + rowl;
                int orow = win_to_orig(row / NLOC, row % NLOC);
                float sum = red[rowl] + red[128 + rowl] + red[256 + rowl] + red[384 + rowl];
                float sq  = red[512 + rowl] + red[640 + rowl] + red[768 + rowl] + red[896 + rowl];
                float mu = sum * (1.f / 192.f);
                float var = sq * (1.f / 192.f) - mu * mu;
                float rstd = rsqrtf(var + 1e-5f);
#pragma unroll
                for (int nt = 0; nt < 6; nt++) {
                    int cc = warp_n + nt * 8 + (lane & 3) * 2;
                    float o[2];
#pragma unroll
                    for (int e = 0; e < 2; e++) {
                        int c = cc + e;
                        float nv = (acc[mt][nt][half * 2 + e] - mu) * rstd * g2[c] + bt2[c];
                        o[e] = nv * (1.f + cond[768 + c]) + cond[576 + c];
                    }
                    *(__nv_bfloat162*)&sout[(size_t)orow * 192 + cc] =
                        __floats2bfloat162_rn(o[0], o[1]);
                }
            }
        }
    }
}

// ---------------------------------------------------------------------------
// FC2 GEMM (K=768): 3-stage cp.async ring, ONE barrier per chunk.
// ---------------------------------------------------------------------------
#define STAGE_BYTES 40960
__global__ __launch_bounds__(256, 1) void k_gemm_fc2(
    const __nv_bfloat16* __restrict__ A, const __nv_bfloat16* __restrict__ Bw,
    const float* __restrict__ bias,
    float* __restrict__ fout, const float* __restrict__ res,
    const float* __restrict__ cond) {
    extern __shared__ __align__(1024) unsigned char smem_dyn[];

    const int tid = threadIdx.x;
    const int lane = tid & 31;
    const int wid = tid >> 5;
    const int warp_m = (wid & 1) * 64;
    const int warp_n = (wid >> 1) * 48;
    const int rowbase = blockIdx.y * 128;
    const int Keff = 768;

    const __nv_bfloat16* Arow = A + (size_t)rowbase * Keff;
    const __nv_bfloat16* Brow = Bw;

    float acc[4][6][4];
#pragma unroll
    for (int mt = 0; mt < 4; mt++)
#pragma unroll
        for (int nt = 0; nt < 6; nt++)
#pragma unroll
            for (int i = 0; i < 4; i++) acc[mt][nt][i] = 0.f;

    int ar[4], as_[4], br[6], bs_[6];
#pragma unroll
    for (int i = 0; i < 4; i++) {
        int idx = tid + i * 256;
        ar[i] = idx >> 3; as_[i] = idx & 7;
    }
#pragma unroll
    for (int i = 0; i < 6; i++) {
        int idx = tid + i * 256;
        br[i] = idx >> 3; bs_[i] = idx & 7;
    }

    const uint32_t smem_u = cvta_smem(smem_dyn);

    auto issue = [&](int ch) {
        uint32_t sa = smem_u + (ch % 3) * STAGE_BYTES;
        uint32_t sb = sa + 16384;
        const __nv_bfloat16* Ach = Arow + ch * 64;
        const __nv_bfloat16* Bch = Brow + ch * 64;
#pragma unroll
        for (int i = 0; i < 4; i++)
            cp16(sa + (uint32_t)(ar[i] * 128 + ((as_[i] ^ (ar[i] & 7)) << 4)),
                 Ach + (size_t)ar[i] * Keff + as_[i] * 8);
#pragma unroll
        for (int i = 0; i < 6; i++)
            cp16(sb + (uint32_t)(br[i] * 128 + ((bs_[i] ^ (br[i] & 7)) << 4)),
                 Bch + (size_t)br[i] * Keff + bs_[i] * 8);
        asm volatile("cp.async.commit_group;");
    };

    issue(0);
    issue(1);
    for (int ch = 0; ch < 12; ch++) {
        if (ch + 1 < 12) {
            asm volatile("cp.async.wait_group 1;");
        } else {
            asm volatile("cp.async.wait_group 0;");
        }
        __syncthreads();
        if (ch + 2 < 12) issue(ch + 2);

        uint32_t sa = smem_u + (ch % 3) * STAGE_BYTES;
        uint32_t sb = sa + 16384;
#pragma unroll
        for (int kk = 0; kk < 4; kk++) {
            uint32_t af[4][4];
#pragma unroll
            for (int mt = 0; mt < 4; mt++) {
                int r = warp_m + mt * 16 + (lane & 15);
                int seg = kk * 2 + (lane >> 4);
                uint32_t addr = sa + r * 128 + (((seg ^ (r & 7)) & 7) << 4);
                asm volatile(
                    "ldmatrix.sync.aligned.m8n8.x4.shared.b16 {%0,%1,%2,%3}, [%4];"
                    : "=r"(af[mt][0]), "=r"(af[mt][1]), "=r"(af[mt][2]), "=r"(af[mt][3])
                    : "r"(addr));
            }
            uint32_t bf[6][2];
#pragma unroll
            for (int nt = 0; nt < 6; nt++) {
                int r = warp_n + nt * 8 + (lane & 7);
                int seg = kk * 2 + ((lane >> 3) & 1);
                uint32_t addr = sb + r * 128 + (((seg ^ (r & 7)) & 7) << 4);
                asm volatile(
                    "ldmatrix.sync.aligned.m8n8.x2.shared.b16 {%0,%1}, [%2];"
                    : "=r"(bf[nt][0]), "=r"(bf[nt][1])
                    : "r"(addr));
            }
#pragma unroll
            for (int mt = 0; mt < 4; mt++)
#pragma unroll
                for (int nt = 0; nt < 6; nt++)
                    mma16816(acc[mt][nt], af[mt], bf[nt]);
        }
    }

#pragma unroll
    for (int mt = 0; mt < 4; mt++) {
#pragma unroll
        for (int half = 0; half < 2; half++) {
            int row = rowbase + warp_m + mt * 16 + (lane >> 2) + half * 8;
#pragma unroll
            for (int nt = 0; nt < 6; nt++) {
                int cc = warp_n + nt * 8 + (lane & 3) * 2;
#pragma unroll
                for (int e = 0; e < 2; e++) {
                    int c = cc + e;
                    float val = acc[mt][nt][half * 2 + e] + bias[c];
                    fout[(size_t)row * 192 + c] =
                        res[(size_t)row * 192 + c] + cond[960 + c] * val;
                }
            }
        }
    }
}

// ---------------------------------------------------------------------------
// K3: tensor-core flash attention, no-max softmax (logits bounded),
// lane-local l accumulation with single end reduction.
// ---------------------------------------------------------------------------
__global__ __launch_bounds__(96) void k_attn() {
    __shared__ __align__(16) __nv_bfloat16 sq[144 * 40];
    __shared__ __align__(16) __nv_bfloat16 sk[144 * 40];
    __shared__ __align__(16) __nv_bfloat16 sv[144 * 40];

    int w = blockIdx.x / 6, head = blockIdx.x - w * 6;
    int tid = threadIdx.x, lane = tid & 31, wp = tid >> 5;
    size_t w6h = (size_t)(w * 6 + head);
    const __nv_bfloat16* qgb = g_q + w6h * 4608;
    const __nv_bfloat16* kgb = g_k + w6h * 4608;
    const __nv_bfloat16* vgb = g_v + w6h * 4608;
    uint32_t squ = cvta_smem(sq), sku = cvta_smem(sk), svu = cvta_smem(sv);

    for (int i = tid; i < 576; i += 96) {
        int r = i >> 2, s = i & 3;
        cp16(squ + r * 80 + s * 16, qgb + r * 32 + s * 8);
        cp16(sku + r * 80 + s * 16, kgb + r * 32 + s * 8);
        cp16(svu + r * 80 + s * 16, vgb + r * 32 + s * 8);
    }
    asm volatile("cp.async.commit_group;");
    asm volatile("cp.async.wait_group 0;");
    __syncthreads();

    int iz = w / 100, ih = (w / 10) % 10;
    const float* comb = g_comb + (size_t)(((iz * 10 + ih) * 6 + head)) * 20736;

    uint32_t qf[3][2][4];
#pragma unroll
    for (int mtl = 0; mtl < 3; mtl++)
#pragma unroll
        for (int ks = 0; ks < 2; ks++) {
            int r = wp * 48 + mtl * 16 + (lane & 15);
            int seg = ks * 2 + (lane >> 4);
            uint32_t addr = squ + r * 80 + seg * 16;
            asm volatile(
                "ldmatrix.sync.aligned.m8n8.x4.shared.b16 {%0,%1,%2,%3}, [%4];"
                : "=r"(qf[mtl][ks][0]), "=r"(qf[mtl][ks][1]),
                  "=r"(qf[mtl][ks][2]), "=r"(qf[mtl][ks][3])
                : "r"(addr));
        }

    float O[3][4][4];
#pragma unroll
    for (int a = 0; a < 3; a++)
#pragma unroll
        for (int b = 0; b < 4; b++)
#pragma unroll
            for (int c = 0; c < 4; c++) O[a][b][c] = 0.f;
    float lsum[3][2];
#pragma unroll
    for (int a = 0; a < 3; a++) { lsum[a][0] = 0.f; lsum[a][1] = 0.f; }

#pragma unroll 1
    for (int cn_ = 0; cn_ < 9; cn_++) {
        uint32_t kf[2][2][2];
#pragma unroll
        for (int nt8 = 0; nt8 < 2; nt8++)
#pragma unroll
            for (int ks = 0; ks < 2; ks++) {
                int r = cn_ * 16 + nt8 * 8 + (lane & 7);
                int seg = ks * 2 + ((lane >> 3) & 1);
                uint32_t addr = sku + r * 80 + seg * 16;
                asm volatile(
                    "ldmatrix.sync.aligned.m8n8.x2.shared.b16 {%0,%1}, [%2];"
                    : "=r"(kf[nt8][ks][0]), "=r"(kf[nt8][ks][1]) : "r"(addr));
            }
        uint32_t vf[4][2];
#pragma unroll
        for (int dt = 0; dt < 4; dt++) {
            int r = cn_ * 16 + (lane & 7) + ((lane >> 3) & 1) * 8;
            uint32_t addr = svu + r * 80 + dt * 16;
            asm volatile(
                "ldmatrix.sync.aligned.m8n8.x2.trans.shared.b16 {%0,%1}, [%2];"
                : "=r"(vf[dt][0]), "=r"(vf[dt][1]) : "r"(addr));
        }

#pragma unroll
        for (int mtl = 0; mtl < 3; mtl++) {
            float s_[2][4];
#pragma unroll
            for (int nt8 = 0; nt8 < 2; nt8++) {
#pragma unroll
                for (int i = 0; i < 4; i++) s_[nt8][i] = 0.f;
#pragma unroll
                for (int ks = 0; ks < 2; ks++)
                    mma16816(s_[nt8], qf[mtl][ks], kf[nt8][ks]);
                const float4 b4 = *(const float4*)(comb +
                    (size_t)(((cn_ * 9 + wp * 3 + mtl) * 2 + nt8) * 128 + lane * 4));
                s_[nt8][0] += b4.x; s_[nt8][1] += b4.y;
                s_[nt8][2] += b4.z; s_[nt8][3] += b4.w;
            }
            float p[2][4];
#pragma unroll
            for (int nt8 = 0; nt8 < 2; nt8++) {
                p[nt8][0] = __expf(s_[nt8][0]);
                p[nt8][1] = __expf(s_[nt8][1]);
                p[nt8][2] = __expf(s_[nt8][2]);
                p[nt8][3] = __expf(s_[nt8][3]);
            }
            lsum[mtl][0] += p[0][0] + p[0][1] + p[1][0] + p[1][1];
            lsum[mtl][1] += p[0][2] + p[0][3] + p[1][2] + p[1][3];
            uint32_t pa[4];
            __nv_bfloat162 t0 = __floats2bfloat162_rn(p[0][0], p[0][1]);
            __nv_bfloat162 t1 = __floats2bfloat162_rn(p[0][2], p[0][3]);
            __nv_bfloat162 t2 = __floats2bfloat162_rn(p[1][0], p[1][1]);
            __nv_bfloat162 t3 = __floats2bfloat162_rn(p[1][2], p[1][3]);
            pa[0] = *(uint32_t*)&t0; pa[1] = *(uint32_t*)&t1;
            pa[2] = *(uint32_t*)&t2; pa[3] = *(uint32_t*)&t3;
#pragma unroll
            for (int dt = 0; dt < 4; dt++)
                mma16816(O[mtl][dt], pa, vf[dt]);
        }
    }

#pragma unroll
    for (int mtl = 0; mtl < 3; mtl++) {
        float l0 = lsum[mtl][0], l1 = lsum[mtl][1];
        l0 += __shfl_xor_sync(0xffffffffu, l0, 1);
        l0 += __shfl_xor_sync(0xffffffffu, l0, 2);
        l1 += __shfl_xor_sync(0xffffffffu, l1, 1);
        l1 += __shfl_xor_sync(0xffffffffu, l1, 2);
        float inv0 = 1.f / l0;
        float inv1 = 1.f / l1;
        int t0 = w * 144 + wp * 48 + mtl * 16 + (lane >> 2);
        int c0 = head * 32 + (lane & 3) * 2;
#pragma unroll
        for (int dt = 0; dt < 4; dt++) {
            int c = c0 + dt * 8;
            float v0 = O[mtl][dt][0] * inv0, v1 = O[mtl][dt][1] * inv0;
            float v2 = O[mtl][dt][2] * inv1, v3 = O[mtl][dt][3] * inv1;
            *(__nv_bfloat162*)&g_Aattn[(size_t)t0 * 192 + c] =
                __floats2bfloat162_rn(v0, v1);
            *(__nv_bfloat162*)&g_Aattn[(size_t)(t0 + 8) * 192 + c] =
                __floats2bfloat162_rn(v2, v3);
        }
    }
}

// ---------------------------------------------------------------------------
// Launch
// ---------------------------------------------------------------------------
extern "C" void kernel_launch(void* const* d_in, const int* in_sizes, int n_in,
                              void* d_out, int out_size) {
    const float* x          = (const float*)d_in[0];
    const float* cond       = (const float*)d_in[1];
    const float* g1         = (const float*)d_in[2];
    const float* bt1        = (const float*)d_in[3];
    const float* w_qkv      = (const float*)d_in[4];
    const float* b_qkv      = (const float*)d_in[5];
    const float* bias_table = (const float*)d_in[6];
    const float* w_proj     = (const float*)d_in[7];
    const float* b_proj     = (const float*)d_in[8];
    const float* g2         = (const float*)d_in[9];
    const float* bt2        = (const float*)d_in[10];
    const float* w_fc1      = (const float*)d_in[11];
    const float* b_fc1      = (const float*)d_in[12];
    const float* w_fc2      = (const float*)d_in[13];
    const float* b_fc2      = (const float*)d_in[14];
    float* out = (float*)d_out;

    __nv_bfloat16 *a1, *aat, *a2, *bq, *bp, *bf1, *bf2;
    float *yb;
    cudaGetSymbolAddress((void**)&a1, g_A1);
    cudaGetSymbolAddress((void**)&aat, g_Aattn);
    cudaGetSymbolAddress((void**)&yb, g_y);
    cudaGetSymbolAddress((void**)&a2, g_A2);
    cudaGetSymbolAddress((void**)&bq, g_Bqkv);
    cudaGetSymbolAddress((void**)&bp, g_Bproj);
    cudaGetSymbolAddress((void**)&bf1, g_Bfc1);
    cudaGetSymbolAddress((void**)&bf2, g_Bfc2);

    static bool attr_done = false;
    if (!attr_done) {
        cudaFuncSetAttribute(k_gemm192<0>,
                             cudaFuncAttributeMaxDynamicSharedMemorySize, K192_SMEM);
        cudaFuncSetAttribute(k_gemm192<1>,
                             cudaFuncAttributeMaxDynamicSharedMemorySize, K192_SMEM);
        cudaFuncSetAttribute(k_gemm192<2>,
                             cudaFuncAttributeMaxDynamicSharedMemorySize, K192_SMEM);
        cudaFuncSetAttribute(k_gemm_fc2,
                             cudaFuncAttributeMaxDynamicSharedMemorySize, 3 * STAGE_BYTES);
        attr_done = true;
    }

    // 0. Fused prep + LN1 (independent work, one launch)
    k_preln<<<1968 + NTOK / 8, 256>>>(w_qkv, w_proj, w_fc1, w_fc2, bias_table,
                                      x, cond, g1, bt1);

    // 1. QKV GEMM -> q/k/v bf16
    k_gemm192<0><<<dim3(3, NTOK / 128), 256, K192_SMEM>>>(
        a1, bq, b_qkv, nullptr, nullptr, nullptr, nullptr, nullptr, nullptr);

    // 2. Flash attention (tensor cores)
    k_attn<<<NWIN * NHEADS, 96>>>();

    // 3. Proj GEMM + gated residual -> y, fused LN2+modulate -> a1
    k_gemm192<1><<<dim3(1, NTOK / 128), 256, K192_SMEM>>>(
        aat, bp, b_proj, yb, a1, x, cond, g2, bt2);

    // 4. FC1 GEMM + GeLU -> a2
    k_gemm192<2><<<dim3(4, NTOK / 128), 256, K192_SMEM>>>(
        a1, bf1, b_fc1, nullptr, a2, nullptr, nullptr, nullptr, nullptr);

    // 5. FC2 GEMM + gated residual -> out
    k_gemm_fc2<<<dim3(1, NTOK / 128), 256, 3 * STAGE_BYTES>>>(
        a2, bf2, b_fc2, out, yb, cond);
}

// round 13
// speedup vs baseline: 3.5457x; 1.0556x over previous
#include <cuda_runtime.h>
#include <cuda_bf16.h>
#include <math.h>
#include <stdint.h>

// ---------------------------------------------------------------------------
// Problem constants (B=1)
// ---------------------------------------------------------------------------
#define ZD 8
#define HD_ 60
#define WD 120
#define CDIM 192
#define NHEADS 6
#define WS0 2
#define WS1 6
#define WS2 12
#define NTOK 57600
#define NWIN 400
#define NLOC 144
#define NZ 4
#define NH 10
#define NL 10

// ---------------------------------------------------------------------------
// Scratch — plain bf16 GEMM operands. B' rows = N, K-major.
// ---------------------------------------------------------------------------
__device__ __nv_bfloat16 g_A1[NTOK * 192];      // ln1 out / ln2 out (K=192)
__device__ __nv_bfloat16 g_Aattn[NTOK * 192];   // attn out (K=192)
__device__ float         g_y[NTOK * 192];       // post-MSA residual
__device__ __nv_bfloat16 g_A2[NTOK * 768];      // fc1 out (K=768)
__device__ __nv_bfloat16 g_Bqkv[576 * 192];
__device__ __nv_bfloat16 g_Bproj[192 * 192];
__device__ __nv_bfloat16 g_Bfc1[768 * 192];
__device__ __nv_bfloat16 g_Bfc2[192 * 768];
// attention operands, per (window,head) contiguous — all [w][h][n][d]
__device__ __nv_bfloat16 g_q[NTOK * 192];       // q pre-scaled
__device__ __nv_bfloat16 g_k[NTOK * 192];
__device__ __nv_bfloat16 g_v[NTOK * 192];
// combined bias+mask in mma-fragment order
__device__ float g_comb[240 * 20736];

// ---------------------------------------------------------------------------
// Helpers
// ---------------------------------------------------------------------------
__device__ __forceinline__ float warpsum(float v) {
#pragma unroll
    for (int o = 16; o > 0; o >>= 1) v += __shfl_xor_sync(0xffffffffu, v, o);
    return v;
}

__device__ __forceinline__ int win_to_orig(int w, int n) {
    int ih = (w / NL) % NH, iz = w / (NL * NH);
    int il = w % NL;
    int z = n / (WS1 * WS2), hh = (n / WS2) % WS1, l = n % WS2;
    int gz = iz * WS0 + z, gh = ih * WS1 + hh, gl = il * WS2 + l;
    int oz = (gz + 1) & 7;
    int oh = gh + 3; if (oh >= HD_) oh -= HD_;
    int ol = gl + 6; if (ol >= WD) ol -= WD;
    return (oz * HD_ + oh) * WD + ol;
}

__device__ __forceinline__ uint32_t cvta_smem(const void* p) {
    return (uint32_t)__cvta_generic_to_shared(p);
}

__device__ __forceinline__ void cp16(uint32_t saddr, const void* g) {
    asm volatile("cp.async.cg.shared.global [%0], [%1], 16;"
                 :: "r"(saddr), "l"(g));
}

__device__ __forceinline__ void mma16816(float* c, const uint32_t* a, const uint32_t* b) {
    asm volatile(
        "mma.sync.aligned.m16n8k16.row.col.f32.bf16.bf16.f32 "
        "{%0,%1,%2,%3}, {%4,%5,%6,%7}, {%8,%9}, {%0,%1,%2,%3};"
        : "+f"(c[0]), "+f"(c[1]), "+f"(c[2]), "+f"(c[3])
        : "r"(a[0]), "r"(a[1]), "r"(a[2]), "r"(a[3]), "r"(b[0]), "r"(b[1]));
}

// ---------------------------------------------------------------------------
// K0: fused prep (4 weight transposes + bias/mask) AND LN1+modulate+gather.
// ---------------------------------------------------------------------------
__device__ __forceinline__ void wprep_body(const float* __restrict__ W,
                                           __nv_bfloat16* __restrict__ Bp,
                                           int K, int N, int blk) {
    int i = blk * 256 + threadIdx.x;
    if (i >= K * N) return;
    int k = i / N, n = i - k * N;
    Bp[(size_t)n * K + k] = __float2bfloat16(W[i]);
}

__global__ __launch_bounds__(256) void k_preln(
    const float* __restrict__ wq, const float* __restrict__ wp,
    const float* __restrict__ w1, const float* __restrict__ w2,
    const float* __restrict__ bt,
    const float* __restrict__ x, const float* __restrict__ cond,
    const float* __restrict__ g1, const float* __restrict__ bt1) {
    int b = blockIdx.x;
    if (b < 432)       { wprep_body(wq, g_Bqkv, 192, 576, b); return; }
    if (b < 576)       { wprep_body(wp, g_Bproj, 192, 192, b - 432); return; }
    if (b < 1152)      { wprep_body(w1, g_Bfc1, 192, 768, b - 576); return; }
    if (b < 1728)      { wprep_body(w2, g_Bfc2, 768, 192, b - 1152); return; }
    if (b < 1968) {
        int th = b - 1728;                 // 0..239
        int typ = th / 6, head = th - typ * 6;
        int iz = typ / 10, ih = typ - iz * 10;
        float* dst = g_comb + (size_t)th * 20736;
        for (int idx = threadIdx.x; idx < 20736; idx += 256) {
            int cn_ = idx / 2304, r1 = idx - cn_ * 2304;
            int mt = r1 / 256, r2 = r1 - mt * 256;
            int nt8 = r2 >> 7, r3 = r2 & 127;
            int lane = r3 >> 2, he = r3 & 3;
            int h = he >> 1, e = he & 1;
            int m = mt * 16 + (lane >> 2) + h * 8;
            int n = cn_ * 16 + nt8 * 8 + (lane & 3) * 2 + e;
            int z1 = m / 72, h1 = (m / 12) % 6, l1 = m % 12;
            int z2 = n / 72, h2 = (n / 12) % 6, l2 = n % 12;
            int pidx = 828 * z1 + 23 * h1 + l1 + 11 + 1656 * z2 + 138 * h2 - l2;
            float v = bt[(size_t)pidx * 240 + typ * 6 + head];
            int gz1 = iz * 2 + z1, gh1 = ih * 6 + h1;
            int gz2 = iz * 2 + z2, gh2 = ih * 6 + h2;
            int lq = (gz1 < 6 ? 0 : (gz1 < 7 ? 1 : 2)) * 3 + (gh1 < 54 ? 0 : (gh1 < 57 ? 1 : 2));
            int lk = (gz2 < 6 ? 0 : (gz2 < 7 ? 1 : 2)) * 3 + (gh2 < 54 ? 0 : (gh2 < 57 ? 1 : 2));
            if (lq != lk) v -= 100.f;
            dst[idx] = v;
        }
        return;
    }
    // ---- LN1 + modulate + window gather ----
    int t = (b - 1968) * 8 + (threadIdx.x >> 5);
    int lane = threadIdx.x & 31;
    int w = t / NLOC, n = t - w * NLOC;
    int src = win_to_orig(w, n);
    const float* xr = x + (size_t)src * CDIM;
    float v[6]; float s = 0.f;
#pragma unroll
    for (int i = 0; i < 6; i++) { v[i] = xr[lane + 32 * i]; s += v[i]; }
    s = warpsum(s);
    float mu = s * (1.f / 192.f);
    float vs = 0.f;
#pragma unroll
    for (int i = 0; i < 6; i++) { float d = v[i] - mu; vs += d * d; }
    vs = warpsum(vs);
    float rstd = rsqrtf(vs * (1.f / 192.f) + 1e-5f);
#pragma unroll
    for (int i = 0; i < 6; i++) {
        int c = lane + 32 * i;
        float val = (v[i] - mu) * rstd * g1[c] + bt1[c];
        val = val * (1.f + cond[192 + c]) + cond[c];
        g_A1[(size_t)t * 192 + c] = __float2bfloat16(val);
    }
}

// ---------------------------------------------------------------------------
// Full-K (K=192) GEMM: 3 per-panel commit groups with PROGRESSIVE waits —
// panels 1,2 load under panel 0,1 compute. 120KB smem.
// MODE 0: qkv -> q/k/v (kind = blockIdx.x)
// MODE 1: proj + gated residual -> g_y AND fused LN2+modulate -> g_A1
// MODE 2: fc1 + GeLU -> g_A2
// ---------------------------------------------------------------------------
#define K192_SMEM (3 * 16384 + 3 * 24576)
template <int MODE>
__global__ __launch_bounds__(256, 1) void k_gemm192(
    const __nv_bfloat16* __restrict__ A, const __nv_bfloat16* __restrict__ Bw,
    const float* __restrict__ bias,
    float* __restrict__ fout, __nv_bfloat16* __restrict__ sout,
    const float* __restrict__ res, const float* __restrict__ cond,
    const float* __restrict__ g2, const float* __restrict__ bt2) {
    extern __shared__ __align__(1024) unsigned char smem_dyn[];

    const int tid = threadIdx.x;
    const int lane = tid & 31;
    const int wid = tid >> 5;
    const int warp_m = (wid & 1) * 64;
    const int warp_n = (wid >> 1) * 48;

    const int rowbase = blockIdx.y * 128;
    const int colbase = blockIdx.x * 192;

    const __nv_bfloat16* Arow = A + (size_t)rowbase * 192;
    const __nv_bfloat16* Brow = Bw + (size_t)colbase * 192;

    const uint32_t smA = cvta_smem(smem_dyn);
    const uint32_t smB = smA + 3 * 16384;

    // ---- issue 3 per-panel groups (A 16KB + B 24KB each) ----
#pragma unroll
    for (int p = 0; p < 3; p++) {
#pragma unroll
        for (int i = 0; i < 4; i++) {
            int idx = tid + i * 256;
            int r = idx >> 3, seg = idx & 7;
            cp16(smA + p * 16384 + r * 128 + ((seg ^ (r & 7)) << 4),
                 Arow + (size_t)r * 192 + p * 64 + seg * 8);
        }
#pragma unroll
        for (int i = 0; i < 6; i++) {
            int idx = tid + i * 256;
            int r = idx >> 3, seg = idx & 7;
            cp16(smB + p * 24576 + r * 128 + ((seg ^ (r & 7)) << 4),
                 Brow + (size_t)r * 192 + p * 64 + seg * 8);
        }
        asm volatile("cp.async.commit_group;");
    }

    float acc[4][6][4];
#pragma unroll
    for (int mt = 0; mt < 4; mt++)
#pragma unroll
        for (int nt = 0; nt < 6; nt++)
#pragma unroll
            for (int i = 0; i < 4; i++) acc[mt][nt][i] = 0.f;

    // ---- compute with progressive waits ----
#pragma unroll
    for (int kp = 0; kp < 3; kp++) {
        if (kp == 0)      asm volatile("cp.async.wait_group 2;");
        else if (kp == 1) asm volatile("cp.async.wait_group 1;");
        else              asm volatile("cp.async.wait_group 0;");
        __syncthreads();

        uint32_t sa = smA + kp * 16384;
        uint32_t sb = smB + kp * 24576;
#pragma unroll
        for (int kk = 0; kk < 4; kk++) {
            uint32_t af[4][4];
#pragma unroll
            for (int mt = 0; mt < 4; mt++) {
                int r = warp_m + mt * 16 + (lane & 15);
                int seg = kk * 2 + (lane >> 4);
                uint32_t addr = sa + r * 128 + (((seg ^ (r & 7)) & 7) << 4);
                asm volatile(
                    "ldmatrix.sync.aligned.m8n8.x4.shared.b16 {%0,%1,%2,%3}, [%4];"
                    : "=r"(af[mt][0]), "=r"(af[mt][1]), "=r"(af[mt][2]), "=r"(af[mt][3])
                    : "r"(addr));
            }
            uint32_t bf[6][2];
#pragma unroll
            for (int nt = 0; nt < 6; nt++) {
                int r = warp_n + nt * 8 + (lane & 7);
                int seg = kk * 2 + ((lane >> 3) & 1);
                uint32_t addr = sb + r * 128 + (((seg ^ (r & 7)) & 7) << 4);
                asm volatile(
                    "ldmatrix.sync.aligned.m8n8.x2.shared.b16 {%0,%1}, [%2];"
                    : "=r"(bf[nt][0]), "=r"(bf[nt][1])
                    : "r"(addr));
            }
#pragma unroll
            for (int mt = 0; mt < 4; mt++)
#pragma unroll
                for (int nt = 0; nt < 6; nt++)
                    mma16816(acc[mt][nt], af[mt], bf[nt]);
        }
    }

    // -------------------- epilogue --------------------
    if (MODE == 0) {
        const int kind = blockIdx.x;
#pragma unroll
        for (int mt = 0; mt < 4; mt++) {
#pragma unroll
            for (int half = 0; half < 2; half++) {
                int row = rowbase + warp_m + mt * 16 + (lane >> 2) + half * 8;
                int wwin = row / NLOC, nn = row - wwin * NLOC;
#pragma unroll
                for (int nt = 0; nt < 6; nt++) {
                    int cc = warp_n + nt * 8 + (lane & 3) * 2;
                    int hd = cc >> 5, d = cc & 31;
                    float a0 = acc[mt][nt][half * 2 + 0] + bias[colbase + cc];
                    float a1 = acc[mt][nt][half * 2 + 1] + bias[colbase + cc + 1];
                    size_t w6h = (size_t)(wwin * 6 + hd);
                    __nv_bfloat16* dst;
                    if (kind == 0) {
                        a0 *= 0.17677669529663687f;
                        a1 *= 0.17677669529663687f;
                        dst = g_q;
                    } else if (kind == 1) dst = g_k;
                    else dst = g_v;
                    *(__nv_bfloat162*)&dst[(w6h * 144 + nn) * 32 + d] =
                        __floats2bfloat162_rn(a0, a1);
                }
            }
        }
    } else if (MODE == 2) {
#pragma unroll
        for (int mt = 0; mt < 4; mt++) {
#pragma unroll
            for (int half = 0; half < 2; half++) {
                int row = rowbase + warp_m + mt * 16 + (lane >> 2) + half * 8;
#pragma unroll
                for (int nt = 0; nt < 6; nt++) {
                    int cc = warp_n + nt * 8 + (lane & 3) * 2;
                    float o[2];
#pragma unroll
                    for (int e = 0; e < 2; e++) {
                        float xg = acc[mt][nt][half * 2 + e] + bias[colbase + cc + e];
                        o[e] = 0.5f * xg * (1.f + erff(xg * 0.70710678118654752f));
                    }
                    *(__nv_bfloat162*)&sout[(size_t)row * 768 + colbase + cc] =
                        __floats2bfloat162_rn(o[0], o[1]);
                }
            }
        }
    } else {
        __syncthreads();
        float* red = (float*)smem_dyn;
        const int g = wid >> 1;
#pragma unroll
        for (int mt = 0; mt < 4; mt++) {
#pragma unroll
            for (int half = 0; half < 2; half++) {
                int rowl = (wid & 1) * 64 + mt * 16 + half * 8 + (lane >> 2);
                int row = rowbase + rowl;
                int orow = win_to_orig(row / NLOC, row % NLOC);
                float s1 = 0.f, s2 = 0.f;
#pragma unroll
                for (int nt = 0; nt < 6; nt++) {
                    int cc = warp_n + nt * 8 + (lane & 3) * 2;
                    float yv[2];
#pragma unroll
                    for (int e = 0; e < 2; e++) {
                        int c = cc + e;
                        float val = acc[mt][nt][half * 2 + e] + bias[c];
                        yv[e] = res[(size_t)orow * 192 + c] + cond[384 + c] * val;
                        acc[mt][nt][half * 2 + e] = yv[e];
                        s1 += yv[e]; s2 += yv[e] * yv[e];
                    }
                    *(float2*)&fout[(size_t)orow * 192 + cc] =
                        make_float2(yv[0], yv[1]);
                }
                s1 += __shfl_xor_sync(0xffffffffu, s1, 1);
                s1 += __shfl_xor_sync(0xffffffffu, s1, 2);
                s2 += __shfl_xor_sync(0xffffffffu, s2, 1);
                s2 += __shfl_xor_sync(0xffffffffu, s2, 2);
                if ((lane & 3) == 0) {
                    red[g * 128 + rowl] = s1;
                    red[512 + g * 128 + rowl] = s2;
                }
            }
        }
        __syncthreads();
#pragma unroll
        for (int mt = 0; mt < 4; mt++) {
#pragma unroll
            for (int half = 0; half < 2; half++) {
                int rowl = (wid & 1) * 64 + mt * 16 + half * 8 + (lane >> 2);
                int row = rowbase + rowl;
                int orow = win_to_orig(row / NLOC, row % NLOC);
                float sum = red[rowl] + red[128 + rowl] + red[256 + rowl] + red[384 + rowl];
                float sq  = red[512 + rowl] + red[640 + rowl] + red[768 + rowl] + red[896 + rowl];
                float mu = sum * (1.f / 192.f);
                float var = sq * (1.f / 192.f) - mu * mu;
                float rstd = rsqrtf(var + 1e-5f);
#pragma unroll
                for (int nt = 0; nt < 6; nt++) {
                    int cc = warp_n + nt * 8 + (lane & 3) * 2;
                    float o[2];
#pragma unroll
                    for (int e = 0; e < 2; e++) {
                        int c = cc + e;
                        float nv = (acc[mt][nt][half * 2 + e] - mu) * rstd * g2[c] + bt2[c];
                        o[e] = nv * (1.f + cond[768 + c]) + cond[576 + c];
                    }
                    *(__nv_bfloat162*)&sout[(size_t)orow * 192 + cc] =
                        __floats2bfloat162_rn(o[0], o[1]);
                }
            }
        }
    }
}

// ---------------------------------------------------------------------------
// FC2 GEMM (K=768): 3-stage cp.async ring, ONE barrier per chunk.
// ---------------------------------------------------------------------------
#define STAGE_BYTES 40960
__global__ __launch_bounds__(256, 1) void k_gemm_fc2(
    const __nv_bfloat16* __restrict__ A, const __nv_bfloat16* __restrict__ Bw,
    const float* __restrict__ bias,
    float* __restrict__ fout, const float* __restrict__ res,
    const float* __restrict__ cond) {
    extern __shared__ __align__(1024) unsigned char smem_dyn[];

    const int tid = threadIdx.x;
    const int lane = tid & 31;
    const int wid = tid >> 5;
    const int warp_m = (wid & 1) * 64;
    const int warp_n = (wid >> 1) * 48;
    const int rowbase = blockIdx.y * 128;
    const int Keff = 768;

    const __nv_bfloat16* Arow = A + (size_t)rowbase * Keff;
    const __nv_bfloat16* Brow = Bw;

    float acc[4][6][4];
#pragma unroll
    for (int mt = 0; mt < 4; mt++)
#pragma unroll
        for (int nt = 0; nt < 6; nt++)
#pragma unroll
            for (int i = 0; i < 4; i++) acc[mt][nt][i] = 0.f;

    int ar[4], as_[4], br[6], bs_[6];
#pragma unroll
    for (int i = 0; i < 4; i++) {
        int idx = tid + i * 256;
        ar[i] = idx >> 3; as_[i] = idx & 7;
    }
#pragma unroll
    for (int i = 0; i < 6; i++) {
        int idx = tid + i * 256;
        br[i] = idx >> 3; bs_[i] = idx & 7;
    }

    const uint32_t smem_u = cvta_smem(smem_dyn);

    auto issue = [&](int ch) {
        uint32_t sa = smem_u + (ch % 3) * STAGE_BYTES;
        uint32_t sb = sa + 16384;
        const __nv_bfloat16* Ach = Arow + ch * 64;
        const __nv_bfloat16* Bch = Brow + ch * 64;
#pragma unroll
        for (int i = 0; i < 4; i++)
            cp16(sa + (uint32_t)(ar[i] * 128 + ((as_[i] ^ (ar[i] & 7)) << 4)),
                 Ach + (size_t)ar[i] * Keff + as_[i] * 8);
#pragma unroll
        for (int i = 0; i < 6; i++)
            cp16(sb + (uint32_t)(br[i] * 128 + ((bs_[i] ^ (br[i] & 7)) << 4)),
                 Bch + (size_t)br[i] * Keff + bs_[i] * 8);
        asm volatile("cp.async.commit_group;");
    };

    issue(0);
    issue(1);
    for (int ch = 0; ch < 12; ch++) {
        if (ch + 1 < 12) {
            asm volatile("cp.async.wait_group 1;");
        } else {
            asm volatile("cp.async.wait_group 0;");
        }
        __syncthreads();
        if (ch + 2 < 12) issue(ch + 2);

        uint32_t sa = smem_u + (ch % 3) * STAGE_BYTES;
        uint32_t sb = sa + 16384;
#pragma unroll
        for (int kk = 0; kk < 4; kk++) {
            uint32_t af[4][4];
#pragma unroll
            for (int mt = 0; mt < 4; mt++) {
                int r = warp_m + mt * 16 + (lane & 15);
                int seg = kk * 2 + (lane >> 4);
                uint32_t addr = sa + r * 128 + (((seg ^ (r & 7)) & 7) << 4);
                asm volatile(
                    "ldmatrix.sync.aligned.m8n8.x4.shared.b16 {%0,%1,%2,%3}, [%4];"
                    : "=r"(af[mt][0]), "=r"(af[mt][1]), "=r"(af[mt][2]), "=r"(af[mt][3])
                    : "r"(addr));
            }
            uint32_t bf[6][2];
#pragma unroll
            for (int nt = 0; nt < 6; nt++) {
                int r = warp_n + nt * 8 + (lane & 7);
                int seg = kk * 2 + ((lane >> 3) & 1);
                uint32_t addr = sb + r * 128 + (((seg ^ (r & 7)) & 7) << 4);
                asm volatile(
                    "ldmatrix.sync.aligned.m8n8.x2.shared.b16 {%0,%1}, [%2];"
                    : "=r"(bf[nt][0]), "=r"(bf[nt][1])
                    : "r"(addr));
            }
#pragma unroll
            for (int mt = 0; mt < 4; mt++)
#pragma unroll
                for (int nt = 0; nt < 6; nt++)
                    mma16816(acc[mt][nt], af[mt], bf[nt]);
        }
    }

#pragma unroll
    for (int mt = 0; mt < 4; mt++) {
#pragma unroll
        for (int half = 0; half < 2; half++) {
            int row = rowbase + warp_m + mt * 16 + (lane >> 2) + half * 8;
#pragma unroll
            for (int nt = 0; nt < 6; nt++) {
                int cc = warp_n + nt * 8 + (lane & 3) * 2;
#pragma unroll
                for (int e = 0; e < 2; e++) {
                    int c = cc + e;
                    float val = acc[mt][nt][half * 2 + e] + bias[c];
                    fout[(size_t)row * 192 + c] =
                        res[(size_t)row * 192 + c] + cond[960 + c] * val;
                }
            }
        }
    }
}

// ---------------------------------------------------------------------------
// K3: tensor-core flash attention, no-max softmax, lane-local l accumulation.
// ---------------------------------------------------------------------------
__global__ __launch_bounds__(96) void k_attn() {
    __shared__ __align__(16) __nv_bfloat16 sq[144 * 40];
    __shared__ __align__(16) __nv_bfloat16 sk[144 * 40];
    __shared__ __align__(16) __nv_bfloat16 sv[144 * 40];

    int w = blockIdx.x / 6, head = blockIdx.x - w * 6;
    int tid = threadIdx.x, lane = tid & 31, wp = tid >> 5;
    size_t w6h = (size_t)(w * 6 + head);
    const __nv_bfloat16* qgb = g_q + w6h * 4608;
    const __nv_bfloat16* kgb = g_k + w6h * 4608;
    const __nv_bfloat16* vgb = g_v + w6h * 4608;
    uint32_t squ = cvta_smem(sq), sku = cvta_smem(sk), svu = cvta_smem(sv);

    for (int i = tid; i < 576; i += 96) {
        int r = i >> 2, s = i & 3;
        cp16(squ + r * 80 + s * 16, qgb + r * 32 + s * 8);
        cp16(sku + r * 80 + s * 16, kgb + r * 32 + s * 8);
        cp16(svu + r * 80 + s * 16, vgb + r * 32 + s * 8);
    }
    asm volatile("cp.async.commit_group;");
    asm volatile("cp.async.wait_group 0;");
    __syncthreads();

    int iz = w / 100, ih = (w / 10) % 10;
    const float* comb = g_comb + (size_t)(((iz * 10 + ih) * 6 + head)) * 20736;

    uint32_t qf[3][2][4];
#pragma unroll
    for (int mtl = 0; mtl < 3; mtl++)
#pragma unroll
        for (int ks = 0; ks < 2; ks++) {
            int r = wp * 48 + mtl * 16 + (lane & 15);
            int seg = ks * 2 + (lane >> 4);
            uint32_t addr = squ + r * 80 + seg * 16;
            asm volatile(
                "ldmatrix.sync.aligned.m8n8.x4.shared.b16 {%0,%1,%2,%3}, [%4];"
                : "=r"(qf[mtl][ks][0]), "=r"(qf[mtl][ks][1]),
                  "=r"(qf[mtl][ks][2]), "=r"(qf[mtl][ks][3])
                : "r"(addr));
        }

    float O[3][4][4];
#pragma unroll
    for (int a = 0; a < 3; a++)
#pragma unroll
        for (int b = 0; b < 4; b++)
#pragma unroll
            for (int c = 0; c < 4; c++) O[a][b][c] = 0.f;
    float lsum[3][2];
#pragma unroll
    for (int a = 0; a < 3; a++) { lsum[a][0] = 0.f; lsum[a][1] = 0.f; }

#pragma unroll 1
    for (int cn_ = 0; cn_ < 9; cn_++) {
        uint32_t kf[2][2][2];
#pragma unroll
        for (int nt8 = 0; nt8 < 2; nt8++)
#pragma unroll
            for (int ks = 0; ks < 2; ks++) {
                int r = cn_ * 16 + nt8 * 8 + (lane & 7);
                int seg = ks * 2 + ((lane >> 3) & 1);
                uint32_t addr = sku + r * 80 + seg * 16;
                asm volatile(
                    "ldmatrix.sync.aligned.m8n8.x2.shared.b16 {%0,%1}, [%2];"
                    : "=r"(kf[nt8][ks][0]), "=r"(kf[nt8][ks][1]) : "r"(addr));
            }
        uint32_t vf[4][2];
#pragma unroll
        for (int dt = 0; dt < 4; dt++) {
            int r = cn_ * 16 + (lane & 7) + ((lane >> 3) & 1) * 8;
            uint32_t addr = svu + r * 80 + dt * 16;
            asm volatile(
                "ldmatrix.sync.aligned.m8n8.x2.trans.shared.b16 {%0,%1}, [%2];"
                : "=r"(vf[dt][0]), "=r"(vf[dt][1]) : "r"(addr));
        }

#pragma unroll
        for (int mtl = 0; mtl < 3; mtl++) {
            float s_[2][4];
#pragma unroll
            for (int nt8 = 0; nt8 < 2; nt8++) {
#pragma unroll
                for (int i = 0; i < 4; i++) s_[nt8][i] = 0.f;
#pragma unroll
                for (int ks = 0; ks < 2; ks++)
                    mma16816(s_[nt8], qf[mtl][ks], kf[nt8][ks]);
                const float4 b4 = *(const float4*)(comb +
                    (size_t)(((cn_ * 9 + wp * 3 + mtl) * 2 + nt8) * 128 + lane * 4));
                s_[nt8][0] += b4.x; s_[nt8][1] += b4.y;
                s_[nt8][2] += b4.z; s_[nt8][3] += b4.w;
            }
            float p[2][4];
#pragma unroll
            for (int nt8 = 0; nt8 < 2; nt8++) {
                p[nt8][0] = __expf(s_[nt8][0]);
                p[nt8][1] = __expf(s_[nt8][1]);
                p[nt8][2] = __expf(s_[nt8][2]);
                p[nt8][3] = __expf(s_[nt8][3]);
            }
            lsum[mtl][0] += p[0][0] + p[0][1] + p[1][0] + p[1][1];
            lsum[mtl][1] += p[0][2] + p[0][3] + p[1][2] + p[1][3];
            uint32_t pa[4];
            __nv_bfloat162 t0 = __floats2bfloat162_rn(p[0][0], p[0][1]);
            __nv_bfloat162 t1 = __floats2bfloat162_rn(p[0][2], p[0][3]);
            __nv_bfloat162 t2 = __floats2bfloat162_rn(p[1][0], p[1][1]);
            __nv_bfloat162 t3 = __floats2bfloat162_rn(p[1][2], p[1][3]);
            pa[0] = *(uint32_t*)&t0; pa[1] = *(uint32_t*)&t1;
            pa[2] = *(uint32_t*)&t2; pa[3] = *(uint32_t*)&t3;
#pragma unroll
            for (int dt = 0; dt < 4; dt++)
                mma16816(O[mtl][dt], pa, vf[dt]);
        }
    }

#pragma unroll
    for (int mtl = 0; mtl < 3; mtl++) {
        float l0 = lsum[mtl][0], l1 = lsum[mtl][1];
        l0 += __shfl_xor_sync(0xffffffffu, l0, 1);
        l0 += __shfl_xor_sync(0xffffffffu, l0, 2);
        l1 += __shfl_xor_sync(0xffffffffu, l1, 1);
        l1 += __shfl_xor_sync(0xffffffffu, l1, 2);
        float inv0 = 1.f / l0;
        float inv1 = 1.f / l1;
        int t0 = w * 144 + wp * 48 + mtl * 16 + (lane >> 2);
        int c0 = head * 32 + (lane & 3) * 2;
#pragma unroll
        for (int dt = 0; dt < 4; dt++) {
            int c = c0 + dt * 8;
            float v0 = O[mtl][dt][0] * inv0, v1 = O[mtl][dt][1] * inv0;
            float v2 = O[mtl][dt][2] * inv1, v3 = O[mtl][dt][3] * inv1;
            *(__nv_bfloat162*)&g_Aattn[(size_t)t0 * 192 + c] =
                __floats2bfloat162_rn(v0, v1);
            *(__nv_bfloat162*)&g_Aattn[(size_t)(t0 + 8) * 192 + c] =
                __floats2bfloat162_rn(v2, v3);
        }
    }
}

// ---------------------------------------------------------------------------
// Launch
// ---------------------------------------------------------------------------
extern "C" void kernel_launch(void* const* d_in, const int* in_sizes, int n_in,
                              void* d_out, int out_size) {
    const float* x          = (const float*)d_in[0];
    const float* cond       = (const float*)d_in[1];
    const float* g1         = (const float*)d_in[2];
    const float* bt1        = (const float*)d_in[3];
    const float* w_qkv      = (const float*)d_in[4];
    const float* b_qkv      = (const float*)d_in[5];
    const float* bias_table = (const float*)d_in[6];
    const float* w_proj     = (const float*)d_in[7];
    const float* b_proj     = (const float*)d_in[8];
    const float* g2         = (const float*)d_in[9];
    const float* bt2        = (const float*)d_in[10];
    const float* w_fc1      = (const float*)d_in[11];
    const float* b_fc1      = (const float*)d_in[12];
    const float* w_fc2      = (const float*)d_in[13];
    const float* b_fc2      = (const float*)d_in[14];
    float* out = (float*)d_out;

    __nv_bfloat16 *a1, *aat, *a2, *bq, *bp, *bf1, *bf2;
    float *yb;
    cudaGetSymbolAddress((void**)&a1, g_A1);
    cudaGetSymbolAddress((void**)&aat, g_Aattn);
    cudaGetSymbolAddress((void**)&yb, g_y);
    cudaGetSymbolAddress((void**)&a2, g_A2);
    cudaGetSymbolAddress((void**)&bq, g_Bqkv);
    cudaGetSymbolAddress((void**)&bp, g_Bproj);
    cudaGetSymbolAddress((void**)&bf1, g_Bfc1);
    cudaGetSymbolAddress((void**)&bf2, g_Bfc2);

    static bool attr_done = false;
    if (!attr_done) {
        cudaFuncSetAttribute(k_gemm192<0>,
                             cudaFuncAttributeMaxDynamicSharedMemorySize, K192_SMEM);
        cudaFuncSetAttribute(k_gemm192<1>,
                             cudaFuncAttributeMaxDynamicSharedMemorySize, K192_SMEM);
        cudaFuncSetAttribute(k_gemm192<2>,
                             cudaFuncAttributeMaxDynamicSharedMemorySize, K192_SMEM);
        cudaFuncSetAttribute(k_gemm_fc2,
                             cudaFuncAttributeMaxDynamicSharedMemorySize, 3 * STAGE_BYTES);
        attr_done = true;
    }

    // 0. Fused prep + LN1 (independent work, one launch)
    k_preln<<<1968 + NTOK / 8, 256>>>(w_qkv, w_proj, w_fc1, w_fc2, bias_table,
                                      x, cond, g1, bt1);

    // 1. QKV GEMM -> q/k/v bf16
    k_gemm192<0><<<dim3(3, NTOK / 128), 256, K192_SMEM>>>(
        a1, bq, b_qkv, nullptr, nullptr, nullptr, nullptr, nullptr, nullptr);

    // 2. Flash attention (tensor cores)
    k_attn<<<NWIN * NHEADS, 96>>>();

    // 3. Proj GEMM + gated residual -> y, fused LN2+modulate -> a1
    k_gemm192<1><<<dim3(1, NTOK / 128), 256, K192_SMEM>>>(
        aat, bp, b_proj, yb, a1, x, cond, g2, bt2);

    // 4. FC1 GEMM + GeLU -> a2
    k_gemm192<2><<<dim3(4, NTOK / 128), 256, K192_SMEM>>>(
        a1, bf1, b_fc1, nullptr, a2, nullptr, nullptr, nullptr, nullptr);

    // 5. FC2 GEMM + gated residual -> out
    k_gemm_fc2<<<dim3(1, NTOK / 128), 256, 3 * STAGE_BYTES>>>(
        a2, bf2, b_fc2, out, yb, cond);
}

// round 14
// speedup vs baseline: 3.7666x; 1.0623x over previous
#include <cuda_runtime.h>
#include <cuda_bf16.h>
#include <math.h>
#include <stdint.h>

// ---------------------------------------------------------------------------
// Problem constants (B=1)
// ---------------------------------------------------------------------------
#define ZD 8
#define HD_ 60
#define WD 120
#define CDIM 192
#define NHEADS 6
#define WS0 2
#define WS1 6
#define WS2 12
#define NTOK 57600
#define NWIN 400
#define NLOC 144
#define NZ 4
#define NH 10
#define NL 10

// ---------------------------------------------------------------------------
// Scratch — plain bf16 GEMM operands. B' rows = N, K-major.
// ---------------------------------------------------------------------------
__device__ __nv_bfloat16 g_A1[NTOK * 192];      // ln1 out / ln2 out (K=192)
__device__ __nv_bfloat16 g_Aattn[NTOK * 192];   // attn out (K=192)
__device__ float         g_y[NTOK * 192];       // post-MSA residual
__device__ __nv_bfloat16 g_A2[NTOK * 768];      // fc1 out (K=768)
__device__ __nv_bfloat16 g_Bqkv[576 * 192];
__device__ __nv_bfloat16 g_Bproj[192 * 192];
__device__ __nv_bfloat16 g_Bfc1[768 * 192];
__device__ __nv_bfloat16 g_Bfc2[192 * 768];
// attention operands, per (window,head) contiguous — all [w][h][n][d]
__device__ __nv_bfloat16 g_q[NTOK * 192];       // q pre-scaled
__device__ __nv_bfloat16 g_k[NTOK * 192];
__device__ __nv_bfloat16 g_v[NTOK * 192];
// combined bias+mask in mma-fragment order
__device__ float g_comb[240 * 20736];

// ---------------------------------------------------------------------------
// Helpers
// ---------------------------------------------------------------------------
__device__ __forceinline__ float warpsum(float v) {
#pragma unroll
    for (int o = 16; o > 0; o >>= 1) v += __shfl_xor_sync(0xffffffffu, v, o);
    return v;
}

__device__ __forceinline__ int win_to_orig(int w, int n) {
    int ih = (w / NL) % NH, iz = w / (NL * NH);
    int il = w % NL;
    int z = n / (WS1 * WS2), hh = (n / WS2) % WS1, l = n % WS2;
    int gz = iz * WS0 + z, gh = ih * WS1 + hh, gl = il * WS2 + l;
    int oz = (gz + 1) & 7;
    int oh = gh + 3; if (oh >= HD_) oh -= HD_;
    int ol = gl + 6; if (ol >= WD) ol -= WD;
    return (oz * HD_ + oh) * WD + ol;
}

__device__ __forceinline__ uint32_t cvta_smem(const void* p) {
    return (uint32_t)__cvta_generic_to_shared(p);
}

__device__ __forceinline__ void cp16(uint32_t saddr, const void* g) {
    asm volatile("cp.async.cg.shared.global [%0], [%1], 16;"
                 :: "r"(saddr), "l"(g));
}

__device__ __forceinline__ void mma16816(float* c, const uint32_t* a, const uint32_t* b) {
    asm volatile(
        "mma.sync.aligned.m16n8k16.row.col.f32.bf16.bf16.f32 "
        "{%0,%1,%2,%3}, {%4,%5,%6,%7}, {%8,%9}, {%0,%1,%2,%3};"
        : "+f"(c[0]), "+f"(c[1]), "+f"(c[2]), "+f"(c[3])
        : "r"(a[0]), "r"(a[1]), "r"(a[2]), "r"(a[3]), "r"(b[0]), "r"(b[1]));
}

// ---------------------------------------------------------------------------
// K0: fused prep (4 weight transposes + bias/mask) AND LN1+modulate+gather.
// ---------------------------------------------------------------------------
__device__ __forceinline__ void wprep_body(const float* __restrict__ W,
                                           __nv_bfloat16* __restrict__ Bp,
                                           int K, int N, int blk) {
    int i = blk * 256 + threadIdx.x;
    if (i >= K * N) return;
    int k = i / N, n = i - k * N;
    Bp[(size_t)n * K + k] = __float2bfloat16(W[i]);
}

__global__ __launch_bounds__(256) void k_preln(
    const float* __restrict__ wq, const float* __restrict__ wp,
    const float* __restrict__ w1, const float* __restrict__ w2,
    const float* __restrict__ bt,
    const float* __restrict__ x, const float* __restrict__ cond,
    const float* __restrict__ g1, const float* __restrict__ bt1) {
    int b = blockIdx.x;
    if (b < 432)       { wprep_body(wq, g_Bqkv, 192, 576, b); return; }
    if (b < 576)       { wprep_body(wp, g_Bproj, 192, 192, b - 432); return; }
    if (b < 1152)      { wprep_body(w1, g_Bfc1, 192, 768, b - 576); return; }
    if (b < 1728)      { wprep_body(w2, g_Bfc2, 768, 192, b - 1152); return; }
    if (b < 1968) {
        int th = b - 1728;                 // 0..239
        int typ = th / 6, head = th - typ * 6;
        int iz = typ / 10, ih = typ - iz * 10;
        float* dst = g_comb + (size_t)th * 20736;
        for (int idx = threadIdx.x; idx < 20736; idx += 256) {
            int cn_ = idx / 2304, r1 = idx - cn_ * 2304;
            int mt = r1 / 256, r2 = r1 - mt * 256;
            int nt8 = r2 >> 7, r3 = r2 & 127;
            int lane = r3 >> 2, he = r3 & 3;
            int h = he >> 1, e = he & 1;
            int m = mt * 16 + (lane >> 2) + h * 8;
            int n = cn_ * 16 + nt8 * 8 + (lane & 3) * 2 + e;
            int z1 = m / 72, h1 = (m / 12) % 6, l1 = m % 12;
            int z2 = n / 72, h2 = (n / 12) % 6, l2 = n % 12;
            int pidx = 828 * z1 + 23 * h1 + l1 + 11 + 1656 * z2 + 138 * h2 - l2;
            float v = bt[(size_t)pidx * 240 + typ * 6 + head];
            int gz1 = iz * 2 + z1, gh1 = ih * 6 + h1;
            int gz2 = iz * 2 + z2, gh2 = ih * 6 + h2;
            int lq = (gz1 < 6 ? 0 : (gz1 < 7 ? 1 : 2)) * 3 + (gh1 < 54 ? 0 : (gh1 < 57 ? 1 : 2));
            int lk = (gz2 < 6 ? 0 : (gz2 < 7 ? 1 : 2)) * 3 + (gh2 < 54 ? 0 : (gh2 < 57 ? 1 : 2));
            if (lq != lk) v -= 100.f;
            dst[idx] = v;
        }
        return;
    }
    // ---- LN1 + modulate + window gather ----
    int t = (b - 1968) * 8 + (threadIdx.x >> 5);
    int lane = threadIdx.x & 31;
    int w = t / NLOC, n = t - w * NLOC;
    int src = win_to_orig(w, n);
    const float* xr = x + (size_t)src * CDIM;
    float v[6]; float s = 0.f;
#pragma unroll
    for (int i = 0; i < 6; i++) { v[i] = xr[lane + 32 * i]; s += v[i]; }
    s = warpsum(s);
    float mu = s * (1.f / 192.f);
    float vs = 0.f;
#pragma unroll
    for (int i = 0; i < 6; i++) { float d = v[i] - mu; vs += d * d; }
    vs = warpsum(vs);
    float rstd = rsqrtf(vs * (1.f / 192.f) + 1e-5f);
#pragma unroll
    for (int i = 0; i < 6; i++) {
        int c = lane + 32 * i;
        float val = (v[i] - mu) * rstd * g1[c] + bt1[c];
        val = val * (1.f + cond[192 + c]) + cond[c];
        g_A1[(size_t)t * 192 + c] = __float2bfloat16(val);
    }
}

// ---------------------------------------------------------------------------
// Full-K (K=192) GEMM: 64x192 block tile, 8 warps (2Mx4N), warp tile 32x48.
// 96KB smem -> 2 CTAs/SM. 3 per-panel commit groups, progressive waits.
// MODE 0: qkv -> q/k/v (kind = blockIdx.x)
// MODE 1: proj + gated residual -> g_y AND fused LN2+modulate -> g_A1
// MODE 2: fc1 + GeLU -> g_A2
// ---------------------------------------------------------------------------
#define K192_SMEM (3 * 8192 + 3 * 24576)
template <int MODE>
__global__ __launch_bounds__(256, 2) void k_gemm192(
    const __nv_bfloat16* __restrict__ A, const __nv_bfloat16* __restrict__ Bw,
    const float* __restrict__ bias,
    float* __restrict__ fout, __nv_bfloat16* __restrict__ sout,
    const float* __restrict__ res, const float* __restrict__ cond,
    const float* __restrict__ g2, const float* __restrict__ bt2) {
    extern __shared__ __align__(1024) unsigned char smem_dyn[];

    const int tid = threadIdx.x;
    const int lane = tid & 31;
    const int wid = tid >> 5;
    const int warp_m = (wid & 1) * 32;
    const int warp_n = (wid >> 1) * 48;

    const int rowbase = blockIdx.y * 64;
    const int colbase = blockIdx.x * 192;

    const __nv_bfloat16* Arow = A + (size_t)rowbase * 192;
    const __nv_bfloat16* Brow = Bw + (size_t)colbase * 192;

    const uint32_t smA = cvta_smem(smem_dyn);
    const uint32_t smB = smA + 3 * 8192;

    // ---- issue 3 per-panel groups (A 8KB + B 24KB each) ----
#pragma unroll
    for (int p = 0; p < 3; p++) {
#pragma unroll
        for (int i = 0; i < 2; i++) {
            int idx = tid + i * 256;
            int r = idx >> 3, seg = idx & 7;
            cp16(smA + p * 8192 + r * 128 + ((seg ^ (r & 7)) << 4),
                 Arow + (size_t)r * 192 + p * 64 + seg * 8);
        }
#pragma unroll
        for (int i = 0; i < 6; i++) {
            int idx = tid + i * 256;
            int r = idx >> 3, seg = idx & 7;
            cp16(smB + p * 24576 + r * 128 + ((seg ^ (r & 7)) << 4),
                 Brow + (size_t)r * 192 + p * 64 + seg * 8);
        }
        asm volatile("cp.async.commit_group;");
    }

    float acc[2][6][4];
#pragma unroll
    for (int mt = 0; mt < 2; mt++)
#pragma unroll
        for (int nt = 0; nt < 6; nt++)
#pragma unroll
            for (int i = 0; i < 4; i++) acc[mt][nt][i] = 0.f;

    // ---- compute with progressive waits ----
#pragma unroll
    for (int kp = 0; kp < 3; kp++) {
        if (kp == 0)      asm volatile("cp.async.wait_group 2;");
        else if (kp == 1) asm volatile("cp.async.wait_group 1;");
        else              asm volatile("cp.async.wait_group 0;");
        __syncthreads();

        uint32_t sa = smA + kp * 8192;
        uint32_t sb = smB + kp * 24576;
#pragma unroll
        for (int kk = 0; kk < 4; kk++) {
            uint32_t af[2][4];
#pragma unroll
            for (int mt = 0; mt < 2; mt++) {
                int r = warp_m + mt * 16 + (lane & 15);
                int seg = kk * 2 + (lane >> 4);
                uint32_t addr = sa + r * 128 + (((seg ^ (r & 7)) & 7) << 4);
                asm volatile(
                    "ldmatrix.sync.aligned.m8n8.x4.shared.b16 {%0,%1,%2,%3}, [%4];"
                    : "=r"(af[mt][0]), "=r"(af[mt][1]), "=r"(af[mt][2]), "=r"(af[mt][3])
                    : "r"(addr));
            }
            uint32_t bf[6][2];
#pragma unroll
            for (int nt = 0; nt < 6; nt++) {
                int r = warp_n + nt * 8 + (lane & 7);
                int seg = kk * 2 + ((lane >> 3) & 1);
                uint32_t addr = sb + r * 128 + (((seg ^ (r & 7)) & 7) << 4);
                asm volatile(
                    "ldmatrix.sync.aligned.m8n8.x2.shared.b16 {%0,%1}, [%2];"
                    : "=r"(bf[nt][0]), "=r"(bf[nt][1])
                    : "r"(addr));
            }
#pragma unroll
            for (int mt = 0; mt < 2; mt++)
#pragma unroll
                for (int nt = 0; nt < 6; nt++)
                    mma16816(acc[mt][nt], af[mt], bf[nt]);
        }
    }

    // -------------------- epilogue --------------------
    if (MODE == 0) {
        const int kind = blockIdx.x;
#pragma unroll
        for (int mt = 0; mt < 2; mt++) {
#pragma unroll
            for (int half = 0; half < 2; half++) {
                int row = rowbase + warp_m + mt * 16 + (lane >> 2) + half * 8;
                int wwin = row / NLOC, nn = row - wwin * NLOC;
#pragma unroll
                for (int nt = 0; nt < 6; nt++) {
                    int cc = warp_n + nt * 8 + (lane & 3) * 2;
                    int hd = cc >> 5, d = cc & 31;
                    float a0 = acc[mt][nt][half * 2 + 0] + bias[colbase + cc];
                    float a1 = acc[mt][nt][half * 2 + 1] + bias[colbase + cc + 1];
                    size_t w6h = (size_t)(wwin * 6 + hd);
                    __nv_bfloat16* dst;
                    if (kind == 0) {
                        a0 *= 0.17677669529663687f;
                        a1 *= 0.17677669529663687f;
                        dst = g_q;
                    } else if (kind == 1) dst = g_k;
                    else dst = g_v;
                    *(__nv_bfloat162*)&dst[(w6h * 144 + nn) * 32 + d] =
                        __floats2bfloat162_rn(a0, a1);
                }
            }
        }
    } else if (MODE == 2) {
#pragma unroll
        for (int mt = 0; mt < 2; mt++) {
#pragma unroll
            for (int half = 0; half < 2; half++) {
                int row = rowbase + warp_m + mt * 16 + (lane >> 2) + half * 8;
#pragma unroll
                for (int nt = 0; nt < 6; nt++) {
                    int cc = warp_n + nt * 8 + (lane & 3) * 2;
                    float o[2];
#pragma unroll
                    for (int e = 0; e < 2; e++) {
                        float xg = acc[mt][nt][half * 2 + e] + bias[colbase + cc + e];
                        o[e] = 0.5f * xg * (1.f + erff(xg * 0.70710678118654752f));
                    }
                    *(__nv_bfloat162*)&sout[(size_t)row * 768 + colbase + cc] =
                        __floats2bfloat162_rn(o[0], o[1]);
                }
            }
        }
    } else {
        // MODE 1: y = x + gt_msa*(proj+bias), then LN2+modulate fused.
        __syncthreads();
        float* red = (float*)smem_dyn;          // [2][4][64] floats = 2KB
        const int g = wid >> 1;
#pragma unroll
        for (int mt = 0; mt < 2; mt++) {
#pragma unroll
            for (int half = 0; half < 2; half++) {
                int rowl = (wid & 1) * 32 + mt * 16 + half * 8 + (lane >> 2);
                int row = rowbase + rowl;
                int orow = win_to_orig(row / NLOC, row % NLOC);
                float s1 = 0.f, s2 = 0.f;
#pragma unroll
                for (int nt = 0; nt < 6; nt++) {
                    int cc = warp_n + nt * 8 + (lane & 3) * 2;
                    float yv[2];
#pragma unroll
                    for (int e = 0; e < 2; e++) {
                        int c = cc + e;
                        float val = acc[mt][nt][half * 2 + e] + bias[c];
                        yv[e] = res[(size_t)orow * 192 + c] + cond[384 + c] * val;
                        acc[mt][nt][half * 2 + e] = yv[e];
                        s1 += yv[e]; s2 += yv[e] * yv[e];
                    }
                    *(float2*)&fout[(size_t)orow * 192 + cc] =
                        make_float2(yv[0], yv[1]);
                }
                s1 += __shfl_xor_sync(0xffffffffu, s1, 1);
                s1 += __shfl_xor_sync(0xffffffffu, s1, 2);
                s2 += __shfl_xor_sync(0xffffffffu, s2, 1);
                s2 += __shfl_xor_sync(0xffffffffu, s2, 2);
                if ((lane & 3) == 0) {
                    red[g * 64 + rowl] = s1;
                    red[256 + g * 64 + rowl] = s2;
                }
            }
        }
        __syncthreads();
#pragma unroll
        for (int mt = 0; mt < 2; mt++) {
#pragma unroll
            for (int half = 0; half < 2; half++) {
                int rowl = (wid & 1) * 32 + mt * 16 + half * 8 + (lane >> 2);
                int row = rowbase + rowl;
                int orow = win_to_orig(row / NLOC, row % NLOC);
                float sum = red[rowl] + red[64 + rowl] + red[128 + rowl] + red[192 + rowl];
                float sq  = red[256 + rowl] + red[320 + rowl] + red[384 + rowl] + red[448 + rowl];
                float mu = sum * (1.f / 192.f);
                float var = sq * (1.f / 192.f) - mu * mu;
                float rstd = rsqrtf(var + 1e-5f);
#pragma unroll
                for (int nt = 0; nt < 6; nt++) {
                    int cc = warp_n + nt * 8 + (lane & 3) * 2;
                    float o[2];
#pragma unroll
                    for (int e = 0; e < 2; e++) {
                        int c = cc + e;
                        float nv = (acc[mt][nt][half * 2 + e] - mu) * rstd * g2[c] + bt2[c];
                        o[e] = nv * (1.f + cond[768 + c]) + cond[576 + c];
                    }
                    *(__nv_bfloat162*)&sout[(size_t)orow * 192 + cc] =
                        __floats2bfloat162_rn(o[0], o[1]);
                }
            }
        }
    }
}

// ---------------------------------------------------------------------------
// FC2 GEMM (K=768): 3-stage cp.async ring, ONE barrier per chunk.
// ---------------------------------------------------------------------------
#define STAGE_BYTES 40960
__global__ __launch_bounds__(256, 1) void k_gemm_fc2(
    const __nv_bfloat16* __restrict__ A, const __nv_bfloat16* __restrict__ Bw,
    const float* __restrict__ bias,
    float* __restrict__ fout, const float* __restrict__ res,
    const float* __restrict__ cond) {
    extern __shared__ __align__(1024) unsigned char smem_dyn[];

    const int tid = threadIdx.x;
    const int lane = tid & 31;
    const int wid = tid >> 5;
    const int warp_m = (wid & 1) * 64;
    const int warp_n = (wid >> 1) * 48;
    const int rowbase = blockIdx.y * 128;
    const int Keff = 768;

    const __nv_bfloat16* Arow = A + (size_t)rowbase * Keff;
    const __nv_bfloat16* Brow = Bw;

    float acc[4][6][4];
#pragma unroll
    for (int mt = 0; mt < 4; mt++)
#pragma unroll
        for (int nt = 0; nt < 6; nt++)
#pragma unroll
            for (int i = 0; i < 4; i++) acc[mt][nt][i] = 0.f;

    int ar[4], as_[4], br[6], bs_[6];
#pragma unroll
    for (int i = 0; i < 4; i++) {
        int idx = tid + i * 256;
        ar[i] = idx >> 3; as_[i] = idx & 7;
    }
#pragma unroll
    for (int i = 0; i < 6; i++) {
        int idx = tid + i * 256;
        br[i] = idx >> 3; bs_[i] = idx & 7;
    }

    const uint32_t smem_u = cvta_smem(smem_dyn);

    auto issue = [&](int ch) {
        uint32_t sa = smem_u + (ch % 3) * STAGE_BYTES;
        uint32_t sb = sa + 16384;
        const __nv_bfloat16* Ach = Arow + ch * 64;
        const __nv_bfloat16* Bch = Brow + ch * 64;
#pragma unroll
        for (int i = 0; i < 4; i++)
            cp16(sa + (uint32_t)(ar[i] * 128 + ((as_[i] ^ (ar[i] & 7)) << 4)),
                 Ach + (size_t)ar[i] * Keff + as_[i] * 8);
#pragma unroll
        for (int i = 0; i < 6; i++)
            cp16(sb + (uint32_t)(br[i] * 128 + ((bs_[i] ^ (br[i] & 7)) << 4)),
                 Bch + (size_t)br[i] * Keff + bs_[i] * 8);
        asm volatile("cp.async.commit_group;");
    };

    issue(0);
    issue(1);
    for (int ch = 0; ch < 12; ch++) {
        if (ch + 1 < 12) {
            asm volatile("cp.async.wait_group 1;");
        } else {
            asm volatile("cp.async.wait_group 0;");
        }
        __syncthreads();
        if (ch + 2 < 12) issue(ch + 2);

        uint32_t sa = smem_u + (ch % 3) * STAGE_BYTES;
        uint32_t sb = sa + 16384;
#pragma unroll
        for (int kk = 0; kk < 4; kk++) {
            uint32_t af[4][4];
#pragma unroll
            for (int mt = 0; mt < 4; mt++) {
                int r = warp_m + mt * 16 + (lane & 15);
                int seg = kk * 2 + (lane >> 4);
                uint32_t addr = sa + r * 128 + (((seg ^ (r & 7)) & 7) << 4);
                asm volatile(
                    "ldmatrix.sync.aligned.m8n8.x4.shared.b16 {%0,%1,%2,%3}, [%4];"
                    : "=r"(af[mt][0]), "=r"(af[mt][1]), "=r"(af[mt][2]), "=r"(af[mt][3])
                    : "r"(addr));
            }
            uint32_t bf[6][2];
#pragma unroll
            for (int nt = 0; nt < 6; nt++) {
                int r = warp_n + nt * 8 + (lane & 7);
                int seg = kk * 2 + ((lane >> 3) & 1);
                uint32_t addr = sb + r * 128 + (((seg ^ (r & 7)) & 7) << 4);
                asm volatile(
                    "ldmatrix.sync.aligned.m8n8.x2.shared.b16 {%0,%1}, [%2];"
                    : "=r"(bf[nt][0]), "=r"(bf[nt][1])
                    : "r"(addr));
            }
#pragma unroll
            for (int mt = 0; mt < 4; mt++)
#pragma unroll
                for (int nt = 0; nt < 6; nt++)
                    mma16816(acc[mt][nt], af[mt], bf[nt]);
        }
    }

#pragma unroll
    for (int mt = 0; mt < 4; mt++) {
#pragma unroll
        for (int half = 0; half < 2; half++) {
            int row = rowbase + warp_m + mt * 16 + (lane >> 2) + half * 8;
#pragma unroll
            for (int nt = 0; nt < 6; nt++) {
                int cc = warp_n + nt * 8 + (lane & 3) * 2;
#pragma unroll
                for (int e = 0; e < 2; e++) {
                    int c = cc + e;
                    float val = acc[mt][nt][half * 2 + e] + bias[c];
                    fout[(size_t)row * 192 + c] =
                        res[(size_t)row * 192 + c] + cond[960 + c] * val;
                }
            }
        }
    }
}

// ---------------------------------------------------------------------------
// K3: tensor-core flash attention, no-max softmax, lane-local l accumulation.
// ---------------------------------------------------------------------------
__global__ __launch_bounds__(96) void k_attn() {
    __shared__ __align__(16) __nv_bfloat16 sq[144 * 40];
    __shared__ __align__(16) __nv_bfloat16 sk[144 * 40];
    __shared__ __align__(16) __nv_bfloat16 sv[144 * 40];

    int w = blockIdx.x / 6, head = blockIdx.x - w * 6;
    int tid = threadIdx.x, lane = tid & 31, wp = tid >> 5;
    size_t w6h = (size_t)(w * 6 + head);
    const __nv_bfloat16* qgb = g_q + w6h * 4608;
    const __nv_bfloat16* kgb = g_k + w6h * 4608;
    const __nv_bfloat16* vgb = g_v + w6h * 4608;
    uint32_t squ = cvta_smem(sq), sku = cvta_smem(sk), svu = cvta_smem(sv);

    for (int i = tid; i < 576; i += 96) {
        int r = i >> 2, s = i & 3;
        cp16(squ + r * 80 + s * 16, qgb + r * 32 + s * 8);
        cp16(sku + r * 80 + s * 16, kgb + r * 32 + s * 8);
        cp16(svu + r * 80 + s * 16, vgb + r * 32 + s * 8);
    }
    asm volatile("cp.async.commit_group;");
    asm volatile("cp.async.wait_group 0;");
    __syncthreads();

    int iz = w / 100, ih = (w / 10) % 10;
    const float* comb = g_comb + (size_t)(((iz * 10 + ih) * 6 + head)) * 20736;

    uint32_t qf[3][2][4];
#pragma unroll
    for (int mtl = 0; mtl < 3; mtl++)
#pragma unroll
        for (int ks = 0; ks < 2; ks++) {
            int r = wp * 48 + mtl * 16 + (lane & 15);
            int seg = ks * 2 + (lane >> 4);
            uint32_t addr = squ + r * 80 + seg * 16;
            asm volatile(
                "ldmatrix.sync.aligned.m8n8.x4.shared.b16 {%0,%1,%2,%3}, [%4];"
                : "=r"(qf[mtl][ks][0]), "=r"(qf[mtl][ks][1]),
                  "=r"(qf[mtl][ks][2]), "=r"(qf[mtl][ks][3])
                : "r"(addr));
        }

    float O[3][4][4];
#pragma unroll
    for (int a = 0; a < 3; a++)
#pragma unroll
        for (int b = 0; b < 4; b++)
#pragma unroll
            for (int c = 0; c < 4; c++) O[a][b][c] = 0.f;
    float lsum[3][2];
#pragma unroll
    for (int a = 0; a < 3; a++) { lsum[a][0] = 0.f; lsum[a][1] = 0.f; }

#pragma unroll 1
    for (int cn_ = 0; cn_ < 9; cn_++) {
        uint32_t kf[2][2][2];
#pragma unroll
        for (int nt8 = 0; nt8 < 2; nt8++)
#pragma unroll
            for (int ks = 0; ks < 2; ks++) {
                int r = cn_ * 16 + nt8 * 8 + (lane & 7);
                int seg = ks * 2 + ((lane >> 3) & 1);
                uint32_t addr = sku + r * 80 + seg * 16;
                asm volatile(
                    "ldmatrix.sync.aligned.m8n8.x2.shared.b16 {%0,%1}, [%2];"
                    : "=r"(kf[nt8][ks][0]), "=r"(kf[nt8][ks][1]) : "r"(addr));
            }
        uint32_t vf[4][2];
#pragma unroll
        for (int dt = 0; dt < 4; dt++) {
            int r = cn_ * 16 + (lane & 7) + ((lane >> 3) & 1) * 8;
            uint32_t addr = svu + r * 80 + dt * 16;
            asm volatile(
                "ldmatrix.sync.aligned.m8n8.x2.trans.shared.b16 {%0,%1}, [%2];"
                : "=r"(vf[dt][0]), "=r"(vf[dt][1]) : "r"(addr));
        }

#pragma unroll
        for (int mtl = 0; mtl < 3; mtl++) {
            float s_[2][4];
#pragma unroll
            for (int nt8 = 0; nt8 < 2; nt8++) {
#pragma unroll
                for (int i = 0; i < 4; i++) s_[nt8][i] = 0.f;
#pragma unroll
                for (int ks = 0; ks < 2; ks++)
                    mma16816(s_[nt8], qf[mtl][ks], kf[nt8][ks]);
                const float4 b4 = *(const float4*)(comb +
                    (size_t)(((cn_ * 9 + wp * 3 + mtl) * 2 + nt8) * 128 + lane * 4));
                s_[nt8][0] += b4.x; s_[nt8][1] += b4.y;
                s_[nt8][2] += b4.z; s_[nt8][3] += b4.w;
            }
            float p[2][4];
#pragma unroll
            for (int nt8 = 0; nt8 < 2; nt8++) {
                p[nt8][0] = __expf(s_[nt8][0]);
                p[nt8][1] = __expf(s_[nt8][1]);
                p[nt8][2] = __expf(s_[nt8][2]);
                p[nt8][3] = __expf(s_[nt8][3]);
            }
            lsum[mtl][0] += p[0][0] + p[0][1] + p[1][0] + p[1][1];
            lsum[mtl][1] += p[0][2] + p[0][3] + p[1][2] + p[1][3];
            uint32_t pa[4];
            __nv_bfloat162 t0 = __floats2bfloat162_rn(p[0][0], p[0][1]);
            __nv_bfloat162 t1 = __floats2bfloat162_rn(p[0][2], p[0][3]);
            __nv_bfloat162 t2 = __floats2bfloat162_rn(p[1][0], p[1][1]);
            __nv_bfloat162 t3 = __floats2bfloat162_rn(p[1][2], p[1][3]);
            pa[0] = *(uint32_t*)&t0; pa[1] = *(uint32_t*)&t1;
            pa[2] = *(uint32_t*)&t2; pa[3] = *(uint32_t*)&t3;
#pragma unroll
            for (int dt = 0; dt < 4; dt++)
                mma16816(O[mtl][dt], pa, vf[dt]);
        }
    }

#pragma unroll
    for (int mtl = 0; mtl < 3; mtl++) {
        float l0 = lsum[mtl][0], l1 = lsum[mtl][1];
        l0 += __shfl_xor_sync(0xffffffffu, l0, 1);
        l0 += __shfl_xor_sync(0xffffffffu, l0, 2);
        l1 += __shfl_xor_sync(0xffffffffu, l1, 1);
        l1 += __shfl_xor_sync(0xffffffffu, l1, 2);
        float inv0 = 1.f / l0;
        float inv1 = 1.f / l1;
        int t0 = w * 144 + wp * 48 + mtl * 16 + (lane >> 2);
        int c0 = head * 32 + (lane & 3) * 2;
#pragma unroll
        for (int dt = 0; dt < 4; dt++) {
            int c = c0 + dt * 8;
            float v0 = O[mtl][dt][0] * inv0, v1 = O[mtl][dt][1] * inv0;
            float v2 = O[mtl][dt][2] * inv1, v3 = O[mtl][dt][3] * inv1;
            *(__nv_bfloat162*)&g_Aattn[(size_t)t0 * 192 + c] =
                __floats2bfloat162_rn(v0, v1);
            *(__nv_bfloat162*)&g_Aattn[(size_t)(t0 + 8) * 192 + c] =
                __floats2bfloat162_rn(v2, v3);
        }
    }
}

// ---------------------------------------------------------------------------
// Launch
// ---------------------------------------------------------------------------
extern "C" void kernel_launch(void* const* d_in, const int* in_sizes, int n_in,
                              void* d_out, int out_size) {
    const float* x          = (const float*)d_in[0];
    const float* cond       = (const float*)d_in[1];
    const float* g1         = (const float*)d_in[2];
    const float* bt1        = (const float*)d_in[3];
    const float* w_qkv      = (const float*)d_in[4];
    const float* b_qkv      = (const float*)d_in[5];
    const float* bias_table = (const float*)d_in[6];
    const float* w_proj     = (const float*)d_in[7];
    const float* b_proj     = (const float*)d_in[8];
    const float* g2         = (const float*)d_in[9];
    const float* bt2        = (const float*)d_in[10];
    const float* w_fc1      = (const float*)d_in[11];
    const float* b_fc1      = (const float*)d_in[12];
    const float* w_fc2      = (const float*)d_in[13];
    const float* b_fc2      = (const float*)d_in[14];
    float* out = (float*)d_out;

    __nv_bfloat16 *a1, *aat, *a2, *bq, *bp, *bf1, *bf2;
    float *yb;
    cudaGetSymbolAddress((void**)&a1, g_A1);
    cudaGetSymbolAddress((void**)&aat, g_Aattn);
    cudaGetSymbolAddress((void**)&yb, g_y);
    cudaGetSymbolAddress((void**)&a2, g_A2);
    cudaGetSymbolAddress((void**)&bq, g_Bqkv);
    cudaGetSymbolAddress((void**)&bp, g_Bproj);
    cudaGetSymbolAddress((void**)&bf1, g_Bfc1);
    cudaGetSymbolAddress((void**)&bf2, g_Bfc2);

    static bool attr_done = false;
    if (!attr_done) {
        cudaFuncSetAttribute(k_gemm192<0>,
                             cudaFuncAttributeMaxDynamicSharedMemorySize, K192_SMEM);
        cudaFuncSetAttribute(k_gemm192<1>,
                             cudaFuncAttributeMaxDynamicSharedMemorySize, K192_SMEM);
        cudaFuncSetAttribute(k_gemm192<2>,
                             cudaFuncAttributeMaxDynamicSharedMemorySize, K192_SMEM);
        cudaFuncSetAttribute(k_gemm_fc2,
                             cudaFuncAttributeMaxDynamicSharedMemorySize, 3 * STAGE_BYTES);
        attr_done = true;
    }

    // 0. Fused prep + LN1 (independent work, one launch)
    k_preln<<<1968 + NTOK / 8, 256>>>(w_qkv, w_proj, w_fc1, w_fc2, bias_table,
                                      x, cond, g1, bt1);

    // 1. QKV GEMM -> q/k/v bf16
    k_gemm192<0><<<dim3(3, NTOK / 64), 256, K192_SMEM>>>(
        a1, bq, b_qkv, nullptr, nullptr, nullptr, nullptr, nullptr, nullptr);

    // 2. Flash attention (tensor cores)
    k_attn<<<NWIN * NHEADS, 96>>>();

    // 3. Proj GEMM + gated residual -> y, fused LN2+modulate -> a1
    k_gemm192<1><<<dim3(1, NTOK / 64), 256, K192_SMEM>>>(
        aat, bp, b_proj, yb, a1, x, cond, g2, bt2);

    // 4. FC1 GEMM + GeLU -> a2
    k_gemm192<2><<<dim3(4, NTOK / 64), 256, K192_SMEM>>>(
        a1, bf1, b_fc1, nullptr, a2, nullptr, nullptr, nullptr, nullptr);

    // 5. FC2 GEMM + gated residual -> out
    k_gemm_fc2<<<dim3(1, NTOK / 128), 256, 3 * STAGE_BYTES>>>(
        a2, bf2, b_fc2, out, yb, cond);
}

// round 16
// speedup vs baseline: 3.8089x; 1.0112x over previous
#include <cuda_runtime.h>
#include <cuda_bf16.h>
#include <math.h>
#include <stdint.h>

// ---------------------------------------------------------------------------
// Problem constants (B=1)
// ---------------------------------------------------------------------------
#define ZD 8
#define HD_ 60
#define WD 120
#define CDIM 192
#define NHEADS 6
#define WS0 2
#define WS1 6
#define WS2 12
#define NTOK 57600
#define NWIN 400
#define NLOC 144
#define NZ 4
#define NH 10
#define NL 10

// ---------------------------------------------------------------------------
// Scratch — plain bf16 GEMM operands. B' rows = N, K-major.
// ---------------------------------------------------------------------------
__device__ __nv_bfloat16 g_A1[NTOK * 192];      // ln1 out / ln2 out (K=192)
__device__ __nv_bfloat16 g_Aattn[NTOK * 192];   // attn out (K=192)
__device__ float         g_y[NTOK * 192];       // post-MSA residual
__device__ __nv_bfloat16 g_A2[NTOK * 768];      // fc1 out (K=768)
__device__ __nv_bfloat16 g_Bqkv[576 * 192];
__device__ __nv_bfloat16 g_Bproj[192 * 192];
__device__ __nv_bfloat16 g_Bfc1[768 * 192];
__device__ __nv_bfloat16 g_Bfc2[192 * 768];
// attention operands, per (window,head) contiguous — all [w][h][n][d]
__device__ __nv_bfloat16 g_q[NTOK * 192];       // q pre-scaled
__device__ __nv_bfloat16 g_k[NTOK * 192];
__device__ __nv_bfloat16 g_v[NTOK * 192];
// combined bias+mask in mma-fragment order
__device__ float g_comb[240 * 20736];

// ---------------------------------------------------------------------------
// Helpers
// ---------------------------------------------------------------------------
__device__ __forceinline__ float warpsum(float v) {
#pragma unroll
    for (int o = 16; o > 0; o >>= 1) v += __shfl_xor_sync(0xffffffffu, v, o);
    return v;
}

__device__ __forceinline__ int win_to_orig(int w, int n) {
    int ih = (w / NL) % NH, iz = w / (NL * NH);
    int il = w % NL;
    int z = n / (WS1 * WS2), hh = (n / WS2) % WS1, l = n % WS2;
    int gz = iz * WS0 + z, gh = ih * WS1 + hh, gl = il * WS2 + l;
    int oz = (gz + 1) & 7;
    int oh = gh + 3; if (oh >= HD_) oh -= HD_;
    int ol = gl + 6; if (ol >= WD) ol -= WD;
    return (oz * HD_ + oh) * WD + ol;
}

__device__ __forceinline__ uint32_t cvta_smem(const void* p) {
    return (uint32_t)__cvta_generic_to_shared(p);
}

__device__ __forceinline__ void cp16(uint32_t saddr, const void* g) {
    asm volatile("cp.async.cg.shared.global [%0], [%1], 16;"
                 :: "r"(saddr), "l"(g));
}

__device__ __forceinline__ void mma16816(float* c, const uint32_t* a, const uint32_t* b) {
    asm volatile(
        "mma.sync.aligned.m16n8k16.row.col.f32.bf16.bf16.f32 "
        "{%0,%1,%2,%3}, {%4,%5,%6,%7}, {%8,%9}, {%0,%1,%2,%3};"
        : "+f"(c[0]), "+f"(c[1]), "+f"(c[2]), "+f"(c[3])
        : "r"(a[0]), "r"(a[1]), "r"(a[2]), "r"(a[3]), "r"(b[0]), "r"(b[1]));
}

// ---------------------------------------------------------------------------
// K0: fused prep (4 weight transposes + bias/mask) AND LN1+modulate+gather.
// ---------------------------------------------------------------------------
__device__ __forceinline__ void wprep_body(const float* __restrict__ W,
                                           __nv_bfloat16* __restrict__ Bp,
                                           int K, int N, int blk) {
    int i = blk * 256 + threadIdx.x;
    if (i >= K * N) return;
    int k = i / N, n = i - k * N;
    Bp[(size_t)n * K + k] = __float2bfloat16(W[i]);
}

__global__ __launch_bounds__(256) void k_preln(
    const float* __restrict__ wq, const float* __restrict__ wp,
    const float* __restrict__ w1, const float* __restrict__ w2,
    const float* __restrict__ bt,
    const float* __restrict__ x, const float* __restrict__ cond,
    const float* __restrict__ g1, const float* __restrict__ bt1) {
    int b = blockIdx.x;
    if (b < 432)       { wprep_body(wq, g_Bqkv, 192, 576, b); return; }
    if (b < 576)       { wprep_body(wp, g_Bproj, 192, 192, b - 432); return; }
    if (b < 1152)      { wprep_body(w1, g_Bfc1, 192, 768, b - 576); return; }
    if (b < 1728)      { wprep_body(w2, g_Bfc2, 768, 192, b - 1152); return; }
    if (b < 1968) {
        int th = b - 1728;                 // 0..239
        int typ = th / 6, head = th - typ * 6;
        int iz = typ / 10, ih = typ - iz * 10;
        float* dst = g_comb + (size_t)th * 20736;
        for (int idx = threadIdx.x; idx < 20736; idx += 256) {
            int cn_ = idx / 2304, r1 = idx - cn_ * 2304;
            int mt = r1 / 256, r2 = r1 - mt * 256;
            int nt8 = r2 >> 7, r3 = r2 & 127;
            int lane = r3 >> 2, he = r3 & 3;
            int h = he >> 1, e = he & 1;
            int m = mt * 16 + (lane >> 2) + h * 8;
            int n = cn_ * 16 + nt8 * 8 + (lane & 3) * 2 + e;
            int z1 = m / 72, h1 = (m / 12) % 6, l1 = m % 12;
            int z2 = n / 72, h2 = (n / 12) % 6, l2 = n % 12;
            int pidx = 828 * z1 + 23 * h1 + l1 + 11 + 1656 * z2 + 138 * h2 - l2;
            float v = bt[(size_t)pidx * 240 + typ * 6 + head];
            int gz1 = iz * 2 + z1, gh1 = ih * 6 + h1;
            int gz2 = iz * 2 + z2, gh2 = ih * 6 + h2;
            int lq = (gz1 < 6 ? 0 : (gz1 < 7 ? 1 : 2)) * 3 + (gh1 < 54 ? 0 : (gh1 < 57 ? 1 : 2));
            int lk = (gz2 < 6 ? 0 : (gz2 < 7 ? 1 : 2)) * 3 + (gh2 < 54 ? 0 : (gh2 < 57 ? 1 : 2));
            if (lq != lk) v -= 100.f;
            dst[idx] = v;
        }
        return;
    }
    // ---- LN1 + modulate + window gather ----
    int t = (b - 1968) * 8 + (threadIdx.x >> 5);
    int lane = threadIdx.x & 31;
    int w = t / NLOC, n = t - w * NLOC;
    int src = win_to_orig(w, n);
    const float* xr = x + (size_t)src * CDIM;
    float v[6]; float s = 0.f;
#pragma unroll
    for (int i = 0; i < 6; i++) { v[i] = xr[lane + 32 * i]; s += v[i]; }
    s = warpsum(s);
    float mu = s * (1.f / 192.f);
    float vs = 0.f;
#pragma unroll
    for (int i = 0; i < 6; i++) { float d = v[i] - mu; vs += d * d; }
    vs = warpsum(vs);
    float rstd = rsqrtf(vs * (1.f / 192.f) + 1e-5f);
#pragma unroll
    for (int i = 0; i < 6; i++) {
        int c = lane + 32 * i;
        float val = (v[i] - mu) * rstd * g1[c] + bt1[c];
        val = val * (1.f + cond[192 + c]) + cond[c];
        g_A1[(size_t)t * 192 + c] = __float2bfloat16(val);
    }
}

// ---------------------------------------------------------------------------
// Full-K (K=192) GEMM: 64x192 tile, 8 warps (2Mx4N), warp tile 32x48.
// Each block processes NITER row-tiles, loading B ONCE into smem.
// smem: A 3x8KB + B 3x24KB + red 2KB = 98KB -> 2 CTAs/SM.
// MODE 0: qkv -> q/k/v (kind = blockIdx.x)
// MODE 1: proj + gated residual -> g_y AND fused LN2+modulate -> g_A1
// MODE 2: fc1 + GeLU -> g_A2
// ---------------------------------------------------------------------------
#define K192_SMEM (3 * 8192 + 3 * 24576 + 2048)
template <int MODE>
__global__ __launch_bounds__(256, 2) void k_gemm192(
    const __nv_bfloat16* __restrict__ A, const __nv_bfloat16* __restrict__ Bw,
    const float* __restrict__ bias, int NITER,
    float* __restrict__ fout, __nv_bfloat16* __restrict__ sout,
    const float* __restrict__ res, const float* __restrict__ cond,
    const float* __restrict__ g2, const float* __restrict__ bt2) {
    extern __shared__ __align__(1024) unsigned char smem_dyn[];

    const int tid = threadIdx.x;
    const int lane = tid & 31;
    const int wid = tid >> 5;
    const int warp_m = (wid & 1) * 32;
    const int warp_n = (wid >> 1) * 48;

    const int colbase = blockIdx.x * 192;
    const int base0 = blockIdx.y * 64 * NITER;

    const __nv_bfloat16* Brow = Bw + (size_t)colbase * 192;

    const uint32_t smA = cvta_smem(smem_dyn);
    const uint32_t smB = smA + 3 * 8192;
    float* red = (float*)(smem_dyn + 3 * 8192 + 3 * 24576);

    // issue the 3 A panels for one row-tile (2 cp16/thread/panel)
    auto issueA = [&](int rowbase, bool withB) {
        const __nv_bfloat16* Arow = A + (size_t)rowbase * 192;
#pragma unroll
        for (int p = 0; p < 3; p++) {
#pragma unroll
            for (int i = 0; i < 2; i++) {
                int idx = tid + i * 256;
                int r = idx >> 3, seg = idx & 7;
                cp16(smA + p * 8192 + r * 128 + ((seg ^ (r & 7)) << 4),
                     Arow + (size_t)r * 192 + p * 64 + seg * 8);
            }
            if (withB) {
#pragma unroll
                for (int i = 0; i < 6; i++) {
                    int idx = tid + i * 256;
                    int r = idx >> 3, seg = idx & 7;
                    cp16(smB + p * 24576 + r * 128 + ((seg ^ (r & 7)) << 4),
                         Brow + (size_t)r * 192 + p * 64 + seg * 8);
                }
            }
            asm volatile("cp.async.commit_group;");
        }
    };

    issueA(base0, true);

#pragma unroll 1
    for (int t = 0; t < NITER; t++) {
        const int rowbase = base0 + t * 64;

        float acc[2][6][4];
#pragma unroll
        for (int mt = 0; mt < 2; mt++)
#pragma unroll
            for (int nt = 0; nt < 6; nt++)
#pragma unroll
                for (int i = 0; i < 4; i++) acc[mt][nt][i] = 0.f;

#pragma unroll
        for (int kp = 0; kp < 3; kp++) {
            if (kp == 0)      asm volatile("cp.async.wait_group 2;");
            else if (kp == 1) asm volatile("cp.async.wait_group 1;");
            else              asm volatile("cp.async.wait_group 0;");
            __syncthreads();

            uint32_t sa = smA + kp * 8192;
            uint32_t sb = smB + kp * 24576;
#pragma unroll
            for (int kk = 0; kk < 4; kk++) {
                uint32_t af[2][4];
#pragma unroll
                for (int mt = 0; mt < 2; mt++) {
                    int r = warp_m + mt * 16 + (lane & 15);
                    int seg = kk * 2 + (lane >> 4);
                    uint32_t addr = sa + r * 128 + (((seg ^ (r & 7)) & 7) << 4);
                    asm volatile(
                        "ldmatrix.sync.aligned.m8n8.x4.shared.b16 {%0,%1,%2,%3}, [%4];"
                        : "=r"(af[mt][0]), "=r"(af[mt][1]), "=r"(af[mt][2]), "=r"(af[mt][3])
                        : "r"(addr));
                }
                uint32_t bf[6][2];
#pragma unroll
                for (int nt = 0; nt < 6; nt++) {
                    int r = warp_n + nt * 8 + (lane & 7);
                    int seg = kk * 2 + ((lane >> 3) & 1);
                    uint32_t addr = sb + r * 128 + (((seg ^ (r & 7)) & 7) << 4);
                    asm volatile(
                        "ldmatrix.sync.aligned.m8n8.x2.shared.b16 {%0,%1}, [%2];"
                        : "=r"(bf[nt][0]), "=r"(bf[nt][1])
                        : "r"(addr));
                }
#pragma unroll
                for (int mt = 0; mt < 2; mt++)
#pragma unroll
                    for (int nt = 0; nt < 6; nt++)
                        mma16816(acc[mt][nt], af[mt], bf[nt]);
            }
        }

        // prefetch next tile's A under the epilogue
        __syncthreads();
        if (t + 1 < NITER) issueA(rowbase + 64, false);

        // ---------------- epilogue for this tile ----------------
        if (MODE == 0) {
            const int kind = blockIdx.x;
#pragma unroll
            for (int mt = 0; mt < 2; mt++) {
#pragma unroll
                for (int half = 0; half < 2; half++) {
                    int row = rowbase + warp_m + mt * 16 + (lane >> 2) + half * 8;
                    int wwin = row / NLOC, nn = row - wwin * NLOC;
#pragma unroll
                    for (int nt = 0; nt < 6; nt++) {
                        int cc = warp_n + nt * 8 + (lane & 3) * 2;
                        int hd = cc >> 5, d = cc & 31;
                        float a0 = acc[mt][nt][half * 2 + 0] + bias[colbase + cc];
                        float a1 = acc[mt][nt][half * 2 + 1] + bias[colbase + cc + 1];
                        size_t w6h = (size_t)(wwin * 6 + hd);
                        __nv_bfloat16* dst;
                        if (kind == 0) {
                            a0 *= 0.17677669529663687f;
                            a1 *= 0.17677669529663687f;
                            dst = g_q;
                        } else if (kind == 1) dst = g_k;
                        else dst = g_v;
                        *(__nv_bfloat162*)&dst[(w6h * 144 + nn) * 32 + d] =
                            __floats2bfloat162_rn(a0, a1);
                    }
                }
            }
        } else if (MODE == 2) {
#pragma unroll
            for (int mt = 0; mt < 2; mt++) {
#pragma unroll
                for (int half = 0; half < 2; half++) {
                    int row = rowbase + warp_m + mt * 16 + (lane >> 2) + half * 8;
#pragma unroll
                    for (int nt = 0; nt < 6; nt++) {
                        int cc = warp_n + nt * 8 + (lane & 3) * 2;
                        float o[2];
#pragma unroll
                        for (int e = 0; e < 2; e++) {
                            float xg = acc[mt][nt][half * 2 + e] + bias[colbase + cc + e];
                            o[e] = 0.5f * xg * (1.f + erff(xg * 0.70710678118654752f));
                        }
                        *(__nv_bfloat162*)&sout[(size_t)row * 768 + colbase + cc] =
                            __floats2bfloat162_rn(o[0], o[1]);
                    }
                }
            }
        } else {
            // MODE 1: y = x + gt_msa*(proj+bias), then LN2+modulate fused.
            const int g = wid >> 1;
#pragma unroll
            for (int mt = 0; mt < 2; mt++) {
#pragma unroll
                for (int half = 0; half < 2; half++) {
                    int rowl = (wid & 1) * 32 + mt * 16 + half * 8 + (lane >> 2);
                    int row = rowbase + rowl;
                    int orow = win_to_orig(row / NLOC, row % NLOC);
                    float s1 = 0.f, s2 = 0.f;
#pragma unroll
                    for (int nt = 0; nt < 6; nt++) {
                        int cc = warp_n + nt * 8 + (lane & 3) * 2;
                        float yv[2];
#pragma unroll
                        for (int e = 0; e < 2; e++) {
                            int c = cc + e;
                            float val = acc[mt][nt][half * 2 + e] + bias[c];
                            yv[e] = res[(size_t)orow * 192 + c] + cond[384 + c] * val;
                            acc[mt][nt][half * 2 + e] = yv[e];
                            s1 += yv[e]; s2 += yv[e] * yv[e];
                        }
                        *(float2*)&fout[(size_t)orow * 192 + cc] =
                            make_float2(yv[0], yv[1]);
                    }
                    s1 += __shfl_xor_sync(0xffffffffu, s1, 1);
                    s1 += __shfl_xor_sync(0xffffffffu, s1, 2);
                    s2 += __shfl_xor_sync(0xffffffffu, s2, 1);
                    s2 += __shfl_xor_sync(0xffffffffu, s2, 2);
                    if ((lane & 3) == 0) {
                        red[g * 64 + rowl] = s1;
                        red[256 + g * 64 + rowl] = s2;
                    }
                }
            }
            __syncthreads();
#pragma unroll
            for (int mt = 0; mt < 2; mt++) {
#pragma unroll
                for (int half = 0; half < 2; half++) {
                    int rowl = (wid & 1) * 32 + mt * 16 + half * 8 + (lane >> 2);
                    int row = rowbase + rowl;
                    int orow = win_to_orig(row / NLOC, row % NLOC);
                    float sum = red[rowl] + red[64 + rowl] + red[128 + rowl] + red[192 + rowl];
                    float sq  = red[256 + rowl] + red[320 + rowl] + red[384 + rowl] + red[448 + rowl];
                    float mu = sum * (1.f / 192.f);
                    float var = sq * (1.f / 192.f) - mu * mu;
                    float rstd = rsqrtf(var + 1e-5f);
#pragma unroll
                    for (int nt = 0; nt < 6; nt++) {
                        int cc = warp_n + nt * 8 + (lane & 3) * 2;
                        float o[2];
#pragma unroll
                        for (int e = 0; e < 2; e++) {
                            int c = cc + e;
                            float nv = (acc[mt][nt][half * 2 + e] - mu) * rstd * g2[c] + bt2[c];
                            o[e] = nv * (1.f + cond[768 + c]) + cond[576 + c];
                        }
                        *(__nv_bfloat162*)&sout[(size_t)orow * 192 + cc] =
                            __floats2bfloat162_rn(o[0], o[1]);
                    }
                }
            }
            if (t + 1 < NITER) __syncthreads();   // red reused next tile
        }
    }
}

// ---------------------------------------------------------------------------
// FC2 GEMM (K=768): 3-stage cp.async ring, ONE barrier per chunk.
// ---------------------------------------------------------------------------
#define STAGE_BYTES 40960
__global__ __launch_bounds__(256, 1) void k_gemm_fc2(
    const __nv_bfloat16* __restrict__ A, const __nv_bfloat16* __restrict__ Bw,
    const float* __restrict__ bias,
    float* __restrict__ fout, const float* __restrict__ res,
    const float* __restrict__ cond) {
    extern __shared__ __align__(1024) unsigned char smem_dyn[];

    const int tid = threadIdx.x;
    const int lane = tid & 31;
    const int wid = tid >> 5;
    const int warp_m = (wid & 1) * 64;
    const int warp_n = (wid >> 1) * 48;
    const int rowbase = blockIdx.y * 128;
    const int Keff = 768;

    const __nv_bfloat16* Arow = A + (size_t)rowbase * Keff;
    const __nv_bfloat16* Brow = Bw;

    float acc[4][6][4];
#pragma unroll
    for (int mt = 0; mt < 4; mt++)
#pragma unroll
        for (int nt = 0; nt < 6; nt++)
#pragma unroll
            for (int i = 0; i < 4; i++) acc[mt][nt][i] = 0.f;

    int ar[4], as_[4], br[6], bs_[6];
#pragma unroll
    for (int i = 0; i < 4; i++) {
        int idx = tid + i * 256;
        ar[i] = idx >> 3; as_[i] = idx & 7;
    }
#pragma unroll
    for (int i = 0; i < 6; i++) {
        int idx = tid + i * 256;
        br[i] = idx >> 3; bs_[i] = idx & 7;
    }

    const uint32_t smem_u = cvta_smem(smem_dyn);

    auto issue = [&](int ch) {
        uint32_t sa = smem_u + (ch % 3) * STAGE_BYTES;
        uint32_t sb = sa + 16384;
        const __nv_bfloat16* Ach = Arow + ch * 64;
        const __nv_bfloat16* Bch = Brow + ch * 64;
#pragma unroll
        for (int i = 0; i < 4; i++)
            cp16(sa + (uint32_t)(ar[i] * 128 + ((as_[i] ^ (ar[i] & 7)) << 4)),
                 Ach + (size_t)ar[i] * Keff + as_[i] * 8);
#pragma unroll
        for (int i = 0; i < 6; i++)
            cp16(sb + (uint32_t)(br[i] * 128 + ((bs_[i] ^ (br[i] & 7)) << 4)),
                 Bch + (size_t)br[i] * Keff + bs_[i] * 8);
        asm volatile("cp.async.commit_group;");
    };

    issue(0);
    issue(1);
    for (int ch = 0; ch < 12; ch++) {
        if (ch + 1 < 12) {
            asm volatile("cp.async.wait_group 1;");
        } else {
            asm volatile("cp.async.wait_group 0;");
        }
        __syncthreads();
        if (ch + 2 < 12) issue(ch + 2);

        uint32_t sa = smem_u + (ch % 3) * STAGE_BYTES;
        uint32_t sb = sa + 16384;
#pragma unroll
        for (int kk = 0; kk < 4; kk++) {
            uint32_t af[4][4];
#pragma unroll
            for (int mt = 0; mt < 4; mt++) {
                int r = warp_m + mt * 16 + (lane & 15);
                int seg = kk * 2 + (lane >> 4);
                uint32_t addr = sa + r * 128 + (((seg ^ (r & 7)) & 7) << 4);
                asm volatile(
                    "ldmatrix.sync.aligned.m8n8.x4.shared.b16 {%0,%1,%2,%3}, [%4];"
                    : "=r"(af[mt][0]), "=r"(af[mt][1]), "=r"(af[mt][2]), "=r"(af[mt][3])
                    : "r"(addr));
            }
            uint32_t bf[6][2];
#pragma unroll
            for (int nt = 0; nt < 6; nt++) {
                int r = warp_n + nt * 8 + (lane & 7);
                int seg = kk * 2 + ((lane >> 3) & 1);
                uint32_t addr = sb + r * 128 + (((seg ^ (r & 7)) & 7) << 4);
                asm volatile(
                    "ldmatrix.sync.aligned.m8n8.x2.shared.b16 {%0,%1}, [%2];"
                    : "=r"(bf[nt][0]), "=r"(bf[nt][1])
                    : "r"(addr));
            }
#pragma unroll
            for (int mt = 0; mt < 4; mt++)
#pragma unroll
                for (int nt = 0; nt < 6; nt++)
                    mma16816(acc[mt][nt], af[mt], bf[nt]);
        }
    }

#pragma unroll
    for (int mt = 0; mt < 4; mt++) {
#pragma unroll
        for (int half = 0; half < 2; half++) {
            int row = rowbase + warp_m + mt * 16 + (lane >> 2) + half * 8;
#pragma unroll
            for (int nt = 0; nt < 6; nt++) {
                int cc = warp_n + nt * 8 + (lane & 3) * 2;
#pragma unroll
                for (int e = 0; e < 2; e++) {
                    int c = cc + e;
                    float val = acc[mt][nt][half * 2 + e] + bias[c];
                    fout[(size_t)row * 192 + c] =
                        res[(size_t)row * 192 + c] + cond[960 + c] * val;
                }
            }
        }
    }
}

// ---------------------------------------------------------------------------
// K3: tensor-core flash attention, no-max softmax, lane-local l accumulation.
// ---------------------------------------------------------------------------
__global__ __launch_bounds__(96) void k_attn() {
    __shared__ __align__(16) __nv_bfloat16 sq[144 * 40];
    __shared__ __align__(16) __nv_bfloat16 sk[144 * 40];
    __shared__ __align__(16) __nv_bfloat16 sv[144 * 40];

    int w = blockIdx.x / 6, head = blockIdx.x - w * 6;
    int tid = threadIdx.x, lane = tid & 31, wp = tid >> 5;
    size_t w6h = (size_t)(w * 6 + head);
    const __nv_bfloat16* qgb = g_q + w6h * 4608;
    const __nv_bfloat16* kgb = g_k + w6h * 4608;
    const __nv_bfloat16* vgb = g_v + w6h * 4608;
    uint32_t squ = cvta_smem(sq), sku = cvta_smem(sk), svu = cvta_smem(sv);

    for (int i = tid; i < 576; i += 96) {
        int r = i >> 2, s = i & 3;
        cp16(squ + r * 80 + s * 16, qgb + r * 32 + s * 8);
        cp16(sku + r * 80 + s * 16, kgb + r * 32 + s * 8);
        cp16(svu + r * 80 + s * 16, vgb + r * 32 + s * 8);
    }
    asm volatile("cp.async.commit_group;");
    asm volatile("cp.async.wait_group 0;");
    __syncthreads();

    int iz = w / 100, ih = (w / 10) % 10;
    const float* comb = g_comb + (size_t)(((iz * 10 + ih) * 6 + head)) * 20736;

    uint32_t qf[3][2][4];
#pragma unroll
    for (int mtl = 0; mtl < 3; mtl++)
#pragma unroll
        for (int ks = 0; ks < 2; ks++) {
            int r = wp * 48 + mtl * 16 + (lane & 15);
            int seg = ks * 2 + (lane >> 4);
            uint32_t addr = squ + r * 80 + seg * 16;
            asm volatile(
                "ldmatrix.sync.aligned.m8n8.x4.shared.b16 {%0,%1,%2,%3}, [%4];"
                : "=r"(qf[mtl][ks][0]), "=r"(qf[mtl][ks][1]),
                  "=r"(qf[mtl][ks][2]), "=r"(qf[mtl][ks][3])
                : "r"(addr));
        }

    float O[3][4][4];
#pragma unroll
    for (int a = 0; a < 3; a++)
#pragma unroll
        for (int b = 0; b < 4; b++)
#pragma unroll
            for (int c = 0; c < 4; c++) O[a][b][c] = 0.f;
    float lsum[3][2];
#pragma unroll
    for (int a = 0; a < 3; a++) { lsum[a][0] = 0.f; lsum[a][1] = 0.f; }

#pragma unroll 1
    for (int cn_ = 0; cn_ < 9; cn_++) {
        uint32_t kf[2][2][2];
#pragma unroll
        for (int nt8 = 0; nt8 < 2; nt8++)
#pragma unroll
            for (int ks = 0; ks < 2; ks++) {
                int r = cn_ * 16 + nt8 * 8 + (lane & 7);
                int seg = ks * 2 + ((lane >> 3) & 1);
                uint32_t addr = sku + r * 80 + seg * 16;
                asm volatile(
                    "ldmatrix.sync.aligned.m8n8.x2.shared.b16 {%0,%1}, [%2];"
                    : "=r"(kf[nt8][ks][0]), "=r"(kf[nt8][ks][1]) : "r"(addr));
            }
        uint32_t vf[4][2];
#pragma unroll
        for (int dt = 0; dt < 4; dt++) {
            int r = cn_ * 16 + (lane & 7) + ((lane >> 3) & 1) * 8;
            uint32_t addr = svu + r * 80 + dt * 16;
            asm volatile(
                "ldmatrix.sync.aligned.m8n8.x2.trans.shared.b16 {%0,%1}, [%2];"
                : "=r"(vf[dt][0]), "=r"(vf[dt][1]) : "r"(addr));
        }

#pragma unroll
        for (int mtl = 0; mtl < 3; mtl++) {
            float s_[2][4];
#pragma unroll
            for (int nt8 = 0; nt8 < 2; nt8++) {
#pragma unroll
                for (int i = 0; i < 4; i++) s_[nt8][i] = 0.f;
#pragma unroll
                for (int ks = 0; ks < 2; ks++)
                    mma16816(s_[nt8], qf[mtl][ks], kf[nt8][ks]);
                const float4 b4 = *(const float4*)(comb +
                    (size_t)(((cn_ * 9 + wp * 3 + mtl) * 2 + nt8) * 128 + lane * 4));
                s_[nt8][0] += b4.x; s_[nt8][1] += b4.y;
                s_[nt8][2] += b4.z; s_[nt8][3] += b4.w;
            }
            float p[2][4];
#pragma unroll
            for (int nt8 = 0; nt8 < 2; nt8++) {
                p[nt8][0] = __expf(s_[nt8][0]);
                p[nt8][1] = __expf(s_[nt8][1]);
                p[nt8][2] = __expf(s_[nt8][2]);
                p[nt8][3] = __expf(s_[nt8][3]);
            }
            lsum[mtl][0] += p[0][0] + p[0][1] + p[1][0] + p[1][1];
            lsum[mtl][1] += p[0][2] + p[0][3] + p[1][2] + p[1][3];
            uint32_t pa[4];
            __nv_bfloat162 t0 = __floats2bfloat162_rn(p[0][0], p[0][1]);
            __nv_bfloat162 t1 = __floats2bfloat162_rn(p[0][2], p[0][3]);
            __nv_bfloat162 t2 = __floats2bfloat162_rn(p[1][0], p[1][1]);
            __nv_bfloat162 t3 = __floats2bfloat162_rn(p[1][2], p[1][3]);
            pa[0] = *(uint32_t*)&t0; pa[1] = *(uint32_t*)&t1;
            pa[2] = *(uint32_t*)&t2; pa[3] = *(uint32_t*)&t3;
#pragma unroll
            for (int dt = 0; dt < 4; dt++)
                mma16816(O[mtl][dt], pa, vf[dt]);
        }
    }

#pragma unroll
    for (int mtl = 0; mtl < 3; mtl++) {
        float l0 = lsum[mtl][0], l1 = lsum[mtl][1];
        l0 += __shfl_xor_sync(0xffffffffu, l0, 1);
        l0 += __shfl_xor_sync(0xffffffffu, l0, 2);
        l1 += __shfl_xor_sync(0xffffffffu, l1, 1);
        l1 += __shfl_xor_sync(0xffffffffu, l1, 2);
        float inv0 = 1.f / l0;
        float inv1 = 1.f / l1;
        int t0 = w * 144 + wp * 48 + mtl * 16 + (lane >> 2);
        int c0 = head * 32 + (lane & 3) * 2;
#pragma unroll
        for (int dt = 0; dt < 4; dt++) {
            int c = c0 + dt * 8;
            float v0 = O[mtl][dt][0] * inv0, v1 = O[mtl][dt][1] * inv0;
            float v2 = O[mtl][dt][2] * inv1, v3 = O[mtl][dt][3] * inv1;
            *(__nv_bfloat162*)&g_Aattn[(size_t)t0 * 192 + c] =
                __floats2bfloat162_rn(v0, v1);
            *(__nv_bfloat162*)&g_Aattn[(size_t)(t0 + 8) * 192 + c] =
                __floats2bfloat162_rn(v2, v3);
        }
    }
}

// ---------------------------------------------------------------------------
// Launch
// ---------------------------------------------------------------------------
extern "C" void kernel_launch(void* const* d_in, const int* in_sizes, int n_in,
                              void* d_out, int out_size) {
    const float* x          = (const float*)d_in[0];
    const float* cond       = (const float*)d_in[1];
    const float* g1         = (const float*)d_in[2];
    const float* bt1        = (const float*)d_in[3];
    const float* w_qkv      = (const float*)d_in[4];
    const float* b_qkv      = (const float*)d_in[5];
    const float* bias_table = (const float*)d_in[6];
    const float* w_proj     = (const float*)d_in[7];
    const float* b_proj     = (const float*)d_in[8];
    const float* g2         = (const float*)d_in[9];
    const float* bt2        = (const float*)d_in[10];
    const float* w_fc1      = (const float*)d_in[11];
    const float* b_fc1      = (const float*)d_in[12];
    const float* w_fc2      = (const float*)d_in[13];
    const float* b_fc2      = (const float*)d_in[14];
    float* out = (float*)d_out;

    __nv_bfloat16 *a1, *aat, *a2, *bq, *bp, *bf1, *bf2;
    float *yb;
    cudaGetSymbolAddress((void**)&a1, g_A1);
    cudaGetSymbolAddress((void**)&aat, g_Aattn);
    cudaGetSymbolAddress((void**)&yb, g_y);
    cudaGetSymbolAddress((void**)&a2, g_A2);
    cudaGetSymbolAddress((void**)&bq, g_Bqkv);
    cudaGetSymbolAddress((void**)&bp, g_Bproj);
    cudaGetSymbolAddress((void**)&bf1, g_Bfc1);
    cudaGetSymbolAddress((void**)&bf2, g_Bfc2);

    static bool attr_done = false;
    if (!attr_done) {
        cudaFuncSetAttribute(k_gemm192<0>,
                             cudaFuncAttributeMaxDynamicSharedMemorySize, K192_SMEM);
        cudaFuncSetAttribute(k_gemm192<1>,
                             cudaFuncAttributeMaxDynamicSharedMemorySize, K192_SMEM);
        cudaFuncSetAttribute(k_gemm192<2>,
                             cudaFuncAttributeMaxDynamicSharedMemorySize, K192_SMEM);
        cudaFuncSetAttribute(k_gemm_fc2,
                             cudaFuncAttributeMaxDynamicSharedMemorySize, 3 * STAGE_BYTES);
        attr_done = true;
    }

    // 0. Fused prep + LN1 (independent work, one launch)
    k_preln<<<1968 + NTOK / 8, 256>>>(w_qkv, w_proj, w_fc1, w_fc2, bias_table,
                                      x, cond, g1, bt1);

    // 1. QKV GEMM -> q/k/v bf16 (NITER=4: 3x225=675 blocks)
    k_gemm192<0><<<dim3(3, 225), 256, K192_SMEM>>>(
        a1, bq, b_qkv, 4, nullptr, nullptr, nullptr, nullptr, nullptr, nullptr);

    // 2. Flash attention (tensor cores)
    k_attn<<<NWIN * NHEADS, 96>>>();

    // 3. Proj GEMM + gated residual -> y, fused LN2+modulate -> a1 (NITER=3: 300 blocks)
    k_gemm192<1><<<dim3(1, 300), 256, K192_SMEM>>>(
        aat, bp, b_proj, 3, yb, a1, x, cond, g2, bt2);

    // 4. FC1 GEMM + GeLU -> a2 (NITER=4: 4x225=900 blocks)
    k_gemm192<2><<<dim3(4, 225), 256, K192_SMEM>>>(
        a1, bf1, b_fc1, 4, nullptr, a2, nullptr, nullptr, nullptr, nullptr);

    // 5. FC2 GEMM + gated residual -> out
    k_gemm_fc2<<<dim3(1, NTOK / 128), 256, 3 * STAGE_BYTES>>>(
        a2, bf2, b_fc2, out, yb, cond);
}